// round 1
// baseline (speedup 1.0000x reference)
#include <cuda_runtime.h>
#include <math.h>

#define Bb  2
#define Cc  128
#define Hh  256
#define Ww  510
#define WFD 256
#define HWD 130560   /* 256*510 */
#define BCD 256      /* Bb*Cc */

// ---------------- scratch (static device globals; no allocation) ----------------
__device__ float  d_yg [(size_t)BCD * HWD];        // conv(g)
__device__ float  d_yx [(size_t)BCD * HWD];        // conv(x)
__device__ float2 d_Fg [(size_t)BCD * Hh * WFD];   // rfft_W(conv g)
__device__ float2 d_Fx [(size_t)BCD * Hh * WFD];
__device__ float2 d_Gg [(size_t)BCD * Hh * WFD];   // fft_H * filt  (g1_feq)
__device__ float2 d_Gx [(size_t)BCD * Hh * WFD];   // (x1_feq)
__device__ float2 d_Sb [(size_t)BCD * WFD * WFD];  // sigmoid(scores)
__device__ float2 d_Tb [(size_t)BCD * Hh * WFD];   // ifft_H(atten)
__device__ float  d_rb [(size_t)BCD * HWD];        // irfft_W + x
__device__ float  d_rsq[BCD * Hh];                 // 1/sqrt(2*pi*var)
__device__ float2 d_Dw [Ww * WFD];                 // forward DFT along W (real->complex)
__device__ float2 d_EhM[Hh * Hh];                  // forward DFT along H
__device__ float2 d_PhM[Hh * Hh];                  // inverse DFT along H
__device__ float2 d_Cw [WFD * Ww];                 // folded Hermitian inverse along W

// ---------------- DFT table builder (runs every launch; deterministic) ----------------
__global__ void build_tables_kernel() {
    int idx = blockIdx.x * blockDim.x + threadIdx.x;
    int stride = gridDim.x * blockDim.x;
    double rsW = 1.0 / sqrt(510.0);
    const double rsH = 1.0 / 16.0;   // 1/sqrt(256)

    for (int i = idx; i < Ww * WFD; i += stride) {
        int w = i / WFD, v = i - w * WFD;
        int m = (int)(((long long)w * v) % Ww);
        double s, c; sincospi(2.0 * (double)m / (double)Ww, &s, &c);
        d_Dw[i] = make_float2((float)(c * rsW), (float)(-s * rsW));
    }
    for (int i = idx; i < Hh * Hh; i += stride) {
        int u = i >> 8, h = i & 255;
        int m = (u * h) & 255;
        double s, c; sincospi(2.0 * (double)m / 256.0, &s, &c);
        d_EhM[i] = make_float2((float)(c * rsH), (float)(-s * rsH));
        d_PhM[i] = make_float2((float)(c * rsH), (float)( s * rsH));  // symmetric in (u,h)
    }
    for (int i = idx; i < WFD * Ww; i += stride) {
        int v = i / Ww, w = i - v * Ww;
        int m = (int)(((long long)v * w) % Ww);
        double s, c; sincospi(2.0 * (double)m / (double)Ww, &s, &c);
        double sv = (v == 0 || v == WFD - 1) ? 1.0 : 2.0;   // DC & Nyquist unfolded
        d_Cw[i] = make_float2((float)(sv * c * rsW), (float)(-sv * s * rsW));
    }
}

__device__ __forceinline__ float sigm(float v) { return 1.f / (1.f + expf(-v)); }

// ---------------- 1x1 conv: Y[b] = Wm[128x128] * X[b][128 x HWD] + bias ----------------
__global__ void conv_kernel(const float* __restrict__ X, const float* __restrict__ Wm,
                            const float* __restrict__ bias, float* __restrict__ Y)
{
    int b = blockIdx.z;
    const float* Xb = X + (size_t)b * Cc * HWD;
    float* Yb = Y + (size_t)b * Cc * HWD;
    int n0 = blockIdx.x * 64, m0 = blockIdx.y * 64;
    __shared__ float As[16][65];
    __shared__ float Bs[16][65];
    int tx = threadIdx.x, ty = threadIdx.y, t = ty * 16 + tx;
    float acc[4][4] = {};
    for (int k0 = 0; k0 < Cc; k0 += 16) {
        int ka = t & 15, mb = t >> 4;
#pragma unroll
        for (int i = 0; i < 4; i++)
            As[ka][mb + i * 16] = Wm[(m0 + mb + i * 16) * Cc + k0 + ka];
        int nb = t & 63, kb = t >> 6;
#pragma unroll
        for (int i = 0; i < 4; i++)
            Bs[kb + i * 4][nb] = Xb[(size_t)(k0 + kb + i * 4) * HWD + n0 + nb];
        __syncthreads();
#pragma unroll
        for (int kk = 0; kk < 16; kk++) {
            float a[4], bv[4];
#pragma unroll
            for (int i = 0; i < 4; i++) a[i] = As[kk][i * 16 + ty];
#pragma unroll
            for (int j = 0; j < 4; j++) bv[j] = Bs[kk][j * 16 + tx];
#pragma unroll
            for (int i = 0; i < 4; i++)
#pragma unroll
                for (int j = 0; j < 4; j++) acc[i][j] += a[i] * bv[j];
        }
        __syncthreads();
    }
#pragma unroll
    for (int i = 0; i < 4; i++) {
        int m = m0 + i * 16 + ty;
        float bvv = bias[m];
#pragma unroll
        for (int j = 0; j < 4; j++)
            Yb[(size_t)m * HWD + n0 + j * 16 + tx] = acc[i][j] + bvv;
    }
}

// ---------------- rfft along W: F[bc][h,v] = sum_w Y[bc][h,w] * Dw[w,v] ----------------
__global__ void rfftw_kernel(const float* __restrict__ Y, float2* __restrict__ F)
{
    int bc = blockIdx.z;
    const float* A = Y + (size_t)bc * HWD;
    float2* Cp = F + (size_t)bc * Hh * WFD;
    int n0 = blockIdx.x * 64, m0 = blockIdx.y * 64;
    __shared__ float  As[16][65];
    __shared__ float2 Bs[16][66];
    int tx = threadIdx.x, ty = threadIdx.y, t = ty * 16 + tx;
    float2 acc[4][4];
#pragma unroll
    for (int i = 0; i < 4; i++)
#pragma unroll
        for (int j = 0; j < 4; j++) acc[i][j] = make_float2(0.f, 0.f);

    for (int k0 = 0; k0 < Ww; k0 += 16) {
        int ka = t & 15, mb = t >> 4;
        bool oka = (k0 + ka) < Ww;
#pragma unroll
        for (int i = 0; i < 4; i++)
            As[ka][mb + i * 16] = oka ? A[(size_t)(m0 + mb + i * 16) * Ww + k0 + ka] : 0.f;
        int nb = t & 63, kb = t >> 6;
#pragma unroll
        for (int i = 0; i < 4; i++) {
            int k = kb + i * 4;
            Bs[k][nb] = (k0 + k) < Ww ? d_Dw[(size_t)(k0 + k) * WFD + n0 + nb]
                                      : make_float2(0.f, 0.f);
        }
        __syncthreads();
#pragma unroll
        for (int kk = 0; kk < 16; kk++) {
            float a[4]; float2 bv[4];
#pragma unroll
            for (int i = 0; i < 4; i++) a[i] = As[kk][i * 16 + ty];
#pragma unroll
            for (int j = 0; j < 4; j++) bv[j] = Bs[kk][j * 16 + tx];
#pragma unroll
            for (int i = 0; i < 4; i++)
#pragma unroll
                for (int j = 0; j < 4; j++) {
                    acc[i][j].x += a[i] * bv[j].x;
                    acc[i][j].y += a[i] * bv[j].y;
                }
        }
        __syncthreads();
    }
#pragma unroll
    for (int i = 0; i < 4; i++)
#pragma unroll
        for (int j = 0; j < 4; j++)
            Cp[(size_t)(m0 + i * 16 + ty) * WFD + n0 + j * 16 + tx] = acc[i][j];
}

// ------- complex GEMM, A shared matrix (row-major MxK), B batched; EPI=1: * filt -------
template<int EPI>
__global__ void cgemm_ann_kernel(const float2* __restrict__ Amat,
                                 const float2* __restrict__ Bbat,
                                 float2* __restrict__ Cbat,
                                 const float2* __restrict__ filt)
{
    int bc = blockIdx.z;
    const float2* Bp = Bbat + (size_t)bc * 65536;
    float2* Cp = Cbat + (size_t)bc * 65536;
    int n0 = blockIdx.x * 64, m0 = blockIdx.y * 64;
    __shared__ float2 As[16][66];
    __shared__ float2 Bs[16][66];
    int tx = threadIdx.x, ty = threadIdx.y, t = ty * 16 + tx;
    float2 acc[4][4];
#pragma unroll
    for (int i = 0; i < 4; i++)
#pragma unroll
        for (int j = 0; j < 4; j++) acc[i][j] = make_float2(0.f, 0.f);

    for (int k0 = 0; k0 < 256; k0 += 16) {
        int ka = t & 15, mb = t >> 4;
#pragma unroll
        for (int i = 0; i < 4; i++)
            As[ka][mb + i * 16] = Amat[(m0 + mb + i * 16) * 256 + k0 + ka];
        int nb = t & 63, kb = t >> 6;
#pragma unroll
        for (int i = 0; i < 4; i++)
            Bs[kb + i * 4][nb] = Bp[(size_t)(k0 + kb + i * 4) * 256 + n0 + nb];
        __syncthreads();
#pragma unroll
        for (int kk = 0; kk < 16; kk++) {
            float2 a[4], bv[4];
#pragma unroll
            for (int i = 0; i < 4; i++) a[i] = As[kk][i * 16 + ty];
#pragma unroll
            for (int j = 0; j < 4; j++) bv[j] = Bs[kk][j * 16 + tx];
#pragma unroll
            for (int i = 0; i < 4; i++)
#pragma unroll
                for (int j = 0; j < 4; j++) {
                    acc[i][j].x += a[i].x * bv[j].x;
                    acc[i][j].x -= a[i].y * bv[j].y;
                    acc[i][j].y += a[i].x * bv[j].y;
                    acc[i][j].y += a[i].y * bv[j].x;
                }
        }
        __syncthreads();
    }
    int c = bc & (Cc - 1);
#pragma unroll
    for (int i = 0; i < 4; i++) {
        int m = m0 + i * 16 + ty;
#pragma unroll
        for (int j = 0; j < 4; j++) {
            int n = n0 + j * 16 + tx;
            float2 v = acc[i][j];
            if (EPI == 1) {
                float2 wc = filt[((size_t)c * Hh + m) * WFD + n];
                float2 r2;
                r2.x = v.x * wc.x - v.y * wc.y;
                r2.y = v.x * wc.y + v.y * wc.x;
                v = r2;
            }
            Cp[(size_t)m * 256 + n] = v;
        }
    }
}

// ------- variance over v per (bc,u) row; output 1/sqrt(2*pi*var) -------
__global__ void var_kernel(const float2* __restrict__ G, float* __restrict__ rsq)
{
    __shared__ float s0[256], s1[256], s2[256];
    int row = blockIdx.x;
    int tid = threadIdx.x;
    float2 z = G[(size_t)row * WFD + tid];
    s0[tid] = z.x; s1[tid] = z.y; s2[tid] = z.x * z.x + z.y * z.y;
    __syncthreads();
    for (int s = 128; s > 0; s >>= 1) {
        if (tid < s) { s0[tid] += s0[tid + s]; s1[tid] += s1[tid + s]; s2[tid] += s2[tid + s]; }
        __syncthreads();
    }
    if (tid == 0) {
        float mr = s0[0] * (1.f / WFD), mi = s1[0] * (1.f / WFD);
        float var = s2[0] * (1.f / WFD) - (mr * mr + mi * mi);
        rsq[row] = 1.f / sqrtf(6.283185307179586f * var);
    }
}

// ------- scores: S[i,j] = sigmoid( (sum_h G[h,i]*X[h,j]) * rsq[i] )  (complex) -------
__global__ void scores_kernel(const float2* __restrict__ Gb, const float2* __restrict__ Xb,
                              const float* __restrict__ rsq, float2* __restrict__ Sb)
{
    int bc = blockIdx.z;
    const float2* Ap = Gb + (size_t)bc * 65536;
    const float2* Bp = Xb + (size_t)bc * 65536;
    float2* Cp = Sb + (size_t)bc * 65536;
    int n0 = blockIdx.x * 64, m0 = blockIdx.y * 64;
    __shared__ float2 As[16][66];
    __shared__ float2 Bs[16][66];
    int tx = threadIdx.x, ty = threadIdx.y, t = ty * 16 + tx;
    float2 acc[4][4];
#pragma unroll
    for (int i = 0; i < 4; i++)
#pragma unroll
        for (int j = 0; j < 4; j++) acc[i][j] = make_float2(0.f, 0.f);

    for (int k0 = 0; k0 < 256; k0 += 16) {
        int nb = t & 63, kb = t >> 6;
#pragma unroll
        for (int i = 0; i < 4; i++) {
            int k = kb + i * 4;
            As[k][nb] = Ap[(size_t)(k0 + k) * 256 + m0 + nb];
            Bs[k][nb] = Bp[(size_t)(k0 + k) * 256 + n0 + nb];
        }
        __syncthreads();
#pragma unroll
        for (int kk = 0; kk < 16; kk++) {
            float2 a[4], bv[4];
#pragma unroll
            for (int i = 0; i < 4; i++) a[i] = As[kk][i * 16 + ty];
#pragma unroll
            for (int j = 0; j < 4; j++) bv[j] = Bs[kk][j * 16 + tx];
#pragma unroll
            for (int i = 0; i < 4; i++)
#pragma unroll
                for (int j = 0; j < 4; j++) {
                    acc[i][j].x += a[i].x * bv[j].x;
                    acc[i][j].x -= a[i].y * bv[j].y;
                    acc[i][j].y += a[i].x * bv[j].y;
                    acc[i][j].y += a[i].y * bv[j].x;
                }
        }
        __syncthreads();
    }
#pragma unroll
    for (int i = 0; i < 4; i++) {
        int m = m0 + i * 16 + ty;
        float sc = rsq[bc * Hh + m];
#pragma unroll
        for (int j = 0; j < 4; j++) {
            int n = n0 + j * 16 + tx;
            float2 v = acc[i][j];
            v.x = sigm(v.x * sc);
            v.y = sigm(v.y * sc);
            Cp[(size_t)m * 256 + n] = v;
        }
    }
}

// ------- irfft along W (folded Hermitian real GEMM) + residual add x -------
__global__ void irfft_add_kernel(const float2* __restrict__ Tb, const float* __restrict__ x,
                                 float* __restrict__ r)
{
    int bc = blockIdx.z;
    const float2* Ap = Tb + (size_t)bc * 65536;
    int n0 = blockIdx.x * 64, m0 = blockIdx.y * 64;
    __shared__ float2 As[16][66];
    __shared__ float2 Bs[16][66];
    int tx = threadIdx.x, ty = threadIdx.y, t = ty * 16 + tx;
    float acc[4][4] = {};
    for (int k0 = 0; k0 < 256; k0 += 16) {
        int ka = t & 15, mb = t >> 4;
#pragma unroll
        for (int i = 0; i < 4; i++)
            As[ka][mb + i * 16] = Ap[(size_t)(m0 + mb + i * 16) * 256 + k0 + ka];
        int nb = t & 63, kb = t >> 6;
#pragma unroll
        for (int i = 0; i < 4; i++) {
            int k = kb + i * 4;
            int n = n0 + nb;
            Bs[k][nb] = (n < Ww) ? d_Cw[(size_t)(k0 + k) * Ww + n] : make_float2(0.f, 0.f);
        }
        __syncthreads();
#pragma unroll
        for (int kk = 0; kk < 16; kk++) {
            float2 a[4], bv[4];
#pragma unroll
            for (int i = 0; i < 4; i++) a[i] = As[kk][i * 16 + ty];
#pragma unroll
            for (int j = 0; j < 4; j++) bv[j] = Bs[kk][j * 16 + tx];
#pragma unroll
            for (int i = 0; i < 4; i++)
#pragma unroll
                for (int j = 0; j < 4; j++)
                    acc[i][j] += a[i].x * bv[j].x + a[i].y * bv[j].y;
        }
        __syncthreads();
    }
#pragma unroll
    for (int i = 0; i < 4; i++) {
        int m = m0 + i * 16 + ty;
#pragma unroll
        for (int j = 0; j < 4; j++) {
            int n = n0 + j * 16 + tx;
            if (n < Ww) {
                size_t idx = (size_t)bc * HWD + (size_t)m * Ww + n;
                r[idx] = acc[i][j] + x[idx];
            }
        }
    }
}

// ------- channel LayerNorm over C, two-pass, coalesced along w -------
__global__ void ln_kernel(const float* __restrict__ r, const float* __restrict__ gamma,
                          const float* __restrict__ beta, float* __restrict__ out)
{
    int p = blockIdx.x * 256 + threadIdx.x;   // p < Bb*HWD == 261120 exactly
    int b = p / HWD;
    int hw = p - b * HWD;
    size_t base = (size_t)b * Cc * HWD + hw;
    float sum = 0.f, sq = 0.f;
    for (int c = 0; c < Cc; c++) {
        float v = r[base + (size_t)c * HWD];
        sum += v; sq += v * v;
    }
    float mu = sum * (1.f / Cc);
    float var = sq * (1.f / Cc) - mu * mu;
    float inv = 1.f / sqrtf(var + 1e-6f);
    for (int c = 0; c < Cc; c++) {
        float v = r[base + (size_t)c * HWD];
        out[base + (size_t)c * HWD] = gamma[c] * (v - mu) * inv + beta[c];
    }
}

// ---------------- launch ----------------
extern "C" void kernel_launch(void* const* d_in, const int* in_sizes, int n_in,
                              void* d_out, int out_size)
{
    (void)in_sizes; (void)n_in; (void)out_size;
    const float*  g     = (const float*)d_in[0];
    const float*  x     = (const float*)d_in[1];
    const float*  wg    = (const float*)d_in[2];
    const float*  bg    = (const float*)d_in[3];
    const float*  wx    = (const float*)d_in[4];
    const float*  bx    = (const float*)d_in[5];
    const float2* fg    = (const float2*)d_in[6];
    const float2* fx    = (const float2*)d_in[7];
    const float*  gamma = (const float*)d_in[8];
    const float*  beta  = (const float*)d_in[9];
    float* out = (float*)d_out;

    float *yg, *yx, *rb, *rsq;
    float2 *Fg, *Fx, *Gg, *Gx, *S, *T, *Eh, *Ph;
    cudaGetSymbolAddress((void**)&yg,  d_yg);
    cudaGetSymbolAddress((void**)&yx,  d_yx);
    cudaGetSymbolAddress((void**)&Fg,  d_Fg);
    cudaGetSymbolAddress((void**)&Fx,  d_Fx);
    cudaGetSymbolAddress((void**)&Gg,  d_Gg);
    cudaGetSymbolAddress((void**)&Gx,  d_Gx);
    cudaGetSymbolAddress((void**)&S,   d_Sb);
    cudaGetSymbolAddress((void**)&T,   d_Tb);
    cudaGetSymbolAddress((void**)&rb,  d_rb);
    cudaGetSymbolAddress((void**)&rsq, d_rsq);
    cudaGetSymbolAddress((void**)&Eh,  d_EhM);
    cudaGetSymbolAddress((void**)&Ph,  d_PhM);

    dim3 blk(16, 16);

    build_tables_kernel<<<256, 256>>>();

    conv_kernel<<<dim3(HWD / 64, 2, Bb), blk>>>(g, wg, bg, yg);
    conv_kernel<<<dim3(HWD / 64, 2, Bb), blk>>>(x, wx, bx, yx);

    rfftw_kernel<<<dim3(4, 4, BCD), blk>>>(yg, Fg);
    rfftw_kernel<<<dim3(4, 4, BCD), blk>>>(yx, Fx);

    cgemm_ann_kernel<1><<<dim3(4, 4, BCD), blk>>>(Eh, Fg, Gg, fg);
    cgemm_ann_kernel<1><<<dim3(4, 4, BCD), blk>>>(Eh, Fx, Gx, fx);

    var_kernel<<<BCD * Hh, 256>>>(Gg, rsq);

    scores_kernel<<<dim3(4, 4, BCD), blk>>>(Gg, Gx, rsq, S);

    cgemm_ann_kernel<0><<<dim3(4, 4, BCD), blk>>>(Ph, S, T, nullptr);

    irfft_add_kernel<<<dim3(8, 4, BCD), blk>>>(T, x, rb);

    ln_kernel<<<Bb * HWD / 256, 256>>>(rb, gamma, beta, out);
}

// round 2
// speedup vs baseline: 1.0602x; 1.0602x over previous
#include <cuda_runtime.h>
#include <math.h>

#define Bb  2
#define Cc  128
#define Hh  256
#define Ww  510
#define WFD 256
#define HWD 130560   /* 256*510 */
#define BCD 256      /* Bb*Cc */

typedef unsigned long long u64;

__device__ __forceinline__ u64 pk2(float lo, float hi) {
    u64 r; asm("mov.b64 %0,{%1,%2};" : "=l"(r) : "f"(lo), "f"(hi)); return r;
}
__device__ __forceinline__ float2 up2(u64 v) {
    float2 r; asm("mov.b64 {%0,%1},%2;" : "=f"(r.x), "=f"(r.y) : "l"(v)); return r;
}
__device__ __forceinline__ u64 ffma2(u64 a, u64 b, u64 c) {
    u64 d; asm("fma.rn.f32x2 %0,%1,%2,%3;" : "=l"(d) : "l"(a), "l"(b), "l"(c)); return d;
}

// ---------------- scratch (static device globals; no allocation) ----------------
__device__ float  d_yg [(size_t)BCD * HWD];
__device__ float  d_yx [(size_t)BCD * HWD];
__device__ float2 d_Fg [(size_t)BCD * Hh * WFD];
__device__ float2 d_Fx [(size_t)BCD * Hh * WFD];
__device__ float2 d_Gg [(size_t)BCD * Hh * WFD];
__device__ float2 d_Gx [(size_t)BCD * Hh * WFD];
__device__ float2 d_Sb [(size_t)BCD * WFD * WFD];
__device__ float2 d_Tb [(size_t)BCD * Hh * WFD];
__device__ float  d_rb [(size_t)BCD * HWD];
__device__ float  d_rsq[BCD * Hh];
__device__ float2 d_Dw [Ww * WFD];
__device__ float2 d_EhM[Hh * Hh];
__device__ float2 d_PhM[Hh * Hh];
__device__ float2 d_Cw [WFD * Ww];

// ---------------- DFT table builder ----------------
__global__ void build_tables_kernel() {
    int idx = blockIdx.x * blockDim.x + threadIdx.x;
    int stride = gridDim.x * blockDim.x;
    float rsW = rsqrtf(510.0f);
    const float rsH = 1.0f / 16.0f;

    for (int i = idx; i < Ww * WFD; i += stride) {
        int w = i / WFD, v = i - w * WFD;
        int m = (int)(((long long)w * v) % Ww);
        float s, c; sincospif(2.0f * (float)m / (float)Ww, &s, &c);
        d_Dw[i] = make_float2(c * rsW, -s * rsW);
    }
    for (int i = idx; i < Hh * Hh; i += stride) {
        int u = i >> 8, h = i & 255;
        int m = (u * h) & 255;
        float s, c; sincospif(2.0f * (float)m / 256.0f, &s, &c);
        d_EhM[i] = make_float2(c * rsH, -s * rsH);
        d_PhM[i] = make_float2(c * rsH,  s * rsH);
    }
    for (int i = idx; i < WFD * Ww; i += stride) {
        int v = i / Ww, w = i - v * Ww;
        int m = (int)(((long long)v * w) % Ww);
        float s, c; sincospif(2.0f * (float)m / (float)Ww, &s, &c);
        float sv = (v == 0 || v == WFD - 1) ? 1.0f : 2.0f;
        d_Cw[i] = make_float2(sv * c * rsW, -sv * s * rsW);
    }
}

__device__ __forceinline__ float sigm(float v) { return 1.f / (1.f + expf(-v)); }

// ---------------- 1x1 conv: k-pair packed FFMA2 real GEMM ----------------
__global__ void __launch_bounds__(256) conv_kernel(
    const float* __restrict__ X, const float* __restrict__ Wm,
    const float* __restrict__ bias, float* __restrict__ Y)
{
    int b = blockIdx.z;
    const float* Xb = X + (size_t)b * Cc * HWD;
    float* Yb = Y + (size_t)b * Cc * HWD;
    int n0 = blockIdx.x * 64, m0 = blockIdx.y * 64;
    __shared__ float As2[64][18];   // [m][k] k-contiguous, even-padded for LDS.64
    __shared__ float Bs2[64][18];   // [n][k]
    int tx = threadIdx.x, ty = threadIdx.y, t = ty * 16 + tx;
    u64 acc[4][4];
#pragma unroll
    for (int i = 0; i < 4; i++)
#pragma unroll
        for (int j = 0; j < 4; j++) acc[i][j] = 0ull;

    for (int k0 = 0; k0 < Cc; k0 += 16) {
        int ka = t & 15, mb = t >> 4;
#pragma unroll
        for (int i = 0; i < 4; i++)
            As2[mb + i * 16][ka] = Wm[(m0 + mb + i * 16) * Cc + k0 + ka];
        int nb = t & 63, kb = t >> 6;
#pragma unroll
        for (int i = 0; i < 4; i++)
            Bs2[nb][kb + i * 4] = Xb[(size_t)(k0 + kb + i * 4) * HWD + n0 + nb];
        __syncthreads();
#pragma unroll
        for (int kp = 0; kp < 8; kp++) {
            u64 av[4], bv[4];
#pragma unroll
            for (int i = 0; i < 4; i++) av[i] = *(const u64*)&As2[i * 16 + ty][kp * 2];
#pragma unroll
            for (int j = 0; j < 4; j++) bv[j] = *(const u64*)&Bs2[j * 16 + tx][kp * 2];
#pragma unroll
            for (int i = 0; i < 4; i++)
#pragma unroll
                for (int j = 0; j < 4; j++) acc[i][j] = ffma2(av[i], bv[j], acc[i][j]);
        }
        __syncthreads();
    }
#pragma unroll
    for (int i = 0; i < 4; i++) {
        int m = m0 + i * 16 + ty;
        float bvv = bias[m];
#pragma unroll
        for (int j = 0; j < 4; j++) {
            float2 v = up2(acc[i][j]);
            Yb[(size_t)m * HWD + n0 + j * 16 + tx] = v.x + v.y + bvv;
        }
    }
}

// ---------------- rfft along W: real x complex, FFMA2 (re,im) packed ----------------
__global__ void __launch_bounds__(256) rfftw_kernel(
    const float* __restrict__ Y, float2* __restrict__ F)
{
    int bc = blockIdx.z;
    const float* A = Y + (size_t)bc * HWD;
    float2* Cp = F + (size_t)bc * Hh * WFD;
    int n0 = blockIdx.x * 64, m0 = blockIdx.y * 64;
    __shared__ float  As[16][65];
    __shared__ float2 Bs[16][66];
    int tx = threadIdx.x, ty = threadIdx.y, t = ty * 16 + tx;
    u64 acc[4][4];
#pragma unroll
    for (int i = 0; i < 4; i++)
#pragma unroll
        for (int j = 0; j < 4; j++) acc[i][j] = 0ull;

    for (int k0 = 0; k0 < Ww; k0 += 16) {
        int ka = t & 15, mb = t >> 4;
        bool oka = (k0 + ka) < Ww;
#pragma unroll
        for (int i = 0; i < 4; i++)
            As[ka][mb + i * 16] = oka ? A[(size_t)(m0 + mb + i * 16) * Ww + k0 + ka] : 0.f;
        int nb = t & 63, kb = t >> 6;
#pragma unroll
        for (int i = 0; i < 4; i++) {
            int k = kb + i * 4;
            Bs[k][nb] = (k0 + k) < Ww ? d_Dw[(size_t)(k0 + k) * WFD + n0 + nb]
                                      : make_float2(0.f, 0.f);
        }
        __syncthreads();
#pragma unroll
        for (int kk = 0; kk < 16; kk++) {
            u64 ad[4], bp[4];
#pragma unroll
            for (int i = 0; i < 4; i++) { float a = As[kk][i * 16 + ty]; ad[i] = pk2(a, a); }
#pragma unroll
            for (int j = 0; j < 4; j++) bp[j] = *(const u64*)&Bs[kk][j * 16 + tx];
#pragma unroll
            for (int i = 0; i < 4; i++)
#pragma unroll
                for (int j = 0; j < 4; j++) acc[i][j] = ffma2(ad[i], bp[j], acc[i][j]);
        }
        __syncthreads();
    }
#pragma unroll
    for (int i = 0; i < 4; i++)
#pragma unroll
        for (int j = 0; j < 4; j++)
            Cp[(size_t)(m0 + i * 16 + ty) * WFD + n0 + j * 16 + tx] = up2(acc[i][j]);
}

// ------- complex GEMM (A shared MxK row-major, B batched); EPI=1: * filt -------
// lane-split complex: accA += (ax,ay)*(bx,by), accB += (ay,ax)*(bx,by)
// re = accA.x - accA.y ; im = accB.x + accB.y
template<int EPI>
__global__ void __launch_bounds__(256) cgemm_ann_kernel(
    const float2* __restrict__ Amat, const float2* __restrict__ Bbat,
    float2* __restrict__ Cbat, const float2* __restrict__ filt)
{
    int bc = blockIdx.z;
    const float2* Bp = Bbat + (size_t)bc * 65536;
    float2* Cp = Cbat + (size_t)bc * 65536;
    int n0 = blockIdx.x * 64, m0 = blockIdx.y * 64;
    __shared__ float2 As[16][66];
    __shared__ float2 Bs[16][66];
    int tx = threadIdx.x, ty = threadIdx.y, t = ty * 16 + tx;
    u64 accA[4][4], accB[4][4];
#pragma unroll
    for (int i = 0; i < 4; i++)
#pragma unroll
        for (int j = 0; j < 4; j++) { accA[i][j] = 0ull; accB[i][j] = 0ull; }

    for (int k0 = 0; k0 < 256; k0 += 16) {
        int ka = t & 15, mb = t >> 4;
#pragma unroll
        for (int i = 0; i < 4; i++)
            As[ka][mb + i * 16] = Amat[(m0 + mb + i * 16) * 256 + k0 + ka];
        int nb = t & 63, kb = t >> 6;
#pragma unroll
        for (int i = 0; i < 4; i++)
            Bs[kb + i * 4][nb] = Bp[(size_t)(k0 + kb + i * 4) * 256 + n0 + nb];
        __syncthreads();
#pragma unroll
        for (int kk = 0; kk < 16; kk++) {
            u64 ap[4], aq[4], bp[4];
#pragma unroll
            for (int i = 0; i < 4; i++) {
                float2 a = As[kk][i * 16 + ty];
                ap[i] = pk2(a.x, a.y);
                aq[i] = pk2(a.y, a.x);
            }
#pragma unroll
            for (int j = 0; j < 4; j++) bp[j] = *(const u64*)&Bs[kk][j * 16 + tx];
#pragma unroll
            for (int i = 0; i < 4; i++)
#pragma unroll
                for (int j = 0; j < 4; j++) {
                    accA[i][j] = ffma2(ap[i], bp[j], accA[i][j]);
                    accB[i][j] = ffma2(aq[i], bp[j], accB[i][j]);
                }
        }
        __syncthreads();
    }
    int c = bc & (Cc - 1);
#pragma unroll
    for (int i = 0; i < 4; i++) {
        int m = m0 + i * 16 + ty;
#pragma unroll
        for (int j = 0; j < 4; j++) {
            int n = n0 + j * 16 + tx;
            float2 va = up2(accA[i][j]), vb = up2(accB[i][j]);
            float2 v = make_float2(va.x - va.y, vb.x + vb.y);
            if (EPI == 1) {
                float2 wc = filt[((size_t)c * Hh + m) * WFD + n];
                v = make_float2(v.x * wc.x - v.y * wc.y, v.x * wc.y + v.y * wc.x);
            }
            Cp[(size_t)m * 256 + n] = v;
        }
    }
}

// ------- variance over v per (bc,u) row; output 1/sqrt(2*pi*var) -------
__global__ void var_kernel(const float2* __restrict__ G, float* __restrict__ rsq)
{
    __shared__ float s0[256], s1[256], s2[256];
    int row = blockIdx.x;
    int tid = threadIdx.x;
    float2 z = G[(size_t)row * WFD + tid];
    s0[tid] = z.x; s1[tid] = z.y; s2[tid] = z.x * z.x + z.y * z.y;
    __syncthreads();
    for (int s = 128; s > 0; s >>= 1) {
        if (tid < s) { s0[tid] += s0[tid + s]; s1[tid] += s1[tid + s]; s2[tid] += s2[tid + s]; }
        __syncthreads();
    }
    if (tid == 0) {
        float mr = s0[0] * (1.f / WFD), mi = s1[0] * (1.f / WFD);
        float var = s2[0] * (1.f / WFD) - (mr * mr + mi * mi);
        rsq[row] = 1.f / sqrtf(6.283185307179586f * var);
    }
}

// ------- scores: S[i,j] = sigmoid( (sum_h G[h,i]*X[h,j]) * rsq[i] ) -------
__global__ void __launch_bounds__(256) scores_kernel(
    const float2* __restrict__ Gb, const float2* __restrict__ Xb,
    const float* __restrict__ rsq, float2* __restrict__ Sb)
{
    int bc = blockIdx.z;
    const float2* Ap = Gb + (size_t)bc * 65536;
    const float2* Bp = Xb + (size_t)bc * 65536;
    float2* Cp = Sb + (size_t)bc * 65536;
    int n0 = blockIdx.x * 64, m0 = blockIdx.y * 64;
    __shared__ float2 As[16][66];
    __shared__ float2 Bs[16][66];
    int tx = threadIdx.x, ty = threadIdx.y, t = ty * 16 + tx;
    u64 accA[4][4], accB[4][4];
#pragma unroll
    for (int i = 0; i < 4; i++)
#pragma unroll
        for (int j = 0; j < 4; j++) { accA[i][j] = 0ull; accB[i][j] = 0ull; }

    for (int k0 = 0; k0 < 256; k0 += 16) {
        int nb = t & 63, kb = t >> 6;
#pragma unroll
        for (int i = 0; i < 4; i++) {
            int k = kb + i * 4;
            As[k][nb] = Ap[(size_t)(k0 + k) * 256 + m0 + nb];
            Bs[k][nb] = Bp[(size_t)(k0 + k) * 256 + n0 + nb];
        }
        __syncthreads();
#pragma unroll
        for (int kk = 0; kk < 16; kk++) {
            u64 ap[4], aq[4], bp[4];
#pragma unroll
            for (int i = 0; i < 4; i++) {
                float2 a = As[kk][i * 16 + ty];
                ap[i] = pk2(a.x, a.y);
                aq[i] = pk2(a.y, a.x);
            }
#pragma unroll
            for (int j = 0; j < 4; j++) bp[j] = *(const u64*)&Bs[kk][j * 16 + tx];
#pragma unroll
            for (int i = 0; i < 4; i++)
#pragma unroll
                for (int j = 0; j < 4; j++) {
                    accA[i][j] = ffma2(ap[i], bp[j], accA[i][j]);
                    accB[i][j] = ffma2(aq[i], bp[j], accB[i][j]);
                }
        }
        __syncthreads();
    }
#pragma unroll
    for (int i = 0; i < 4; i++) {
        int m = m0 + i * 16 + ty;
        float sc = rsq[bc * Hh + m];
#pragma unroll
        for (int j = 0; j < 4; j++) {
            int n = n0 + j * 16 + tx;
            float2 va = up2(accA[i][j]), vb = up2(accB[i][j]);
            float2 v = make_float2(sigm((va.x - va.y) * sc), sigm((vb.x + vb.y) * sc));
            Cp[(size_t)m * 256 + n] = v;
        }
    }
}

// ------- irfft along W (folded Hermitian) + residual add; pure packed dot -------
__global__ void __launch_bounds__(256) irfft_add_kernel(
    const float2* __restrict__ Tb, const float* __restrict__ x, float* __restrict__ r)
{
    int bc = blockIdx.z;
    const float2* Ap = Tb + (size_t)bc * 65536;
    int n0 = blockIdx.x * 64, m0 = blockIdx.y * 64;
    __shared__ float2 As[16][66];
    __shared__ float2 Bs[16][66];
    int tx = threadIdx.x, ty = threadIdx.y, t = ty * 16 + tx;
    u64 acc[4][4];
#pragma unroll
    for (int i = 0; i < 4; i++)
#pragma unroll
        for (int j = 0; j < 4; j++) acc[i][j] = 0ull;

    for (int k0 = 0; k0 < 256; k0 += 16) {
        int ka = t & 15, mb = t >> 4;
#pragma unroll
        for (int i = 0; i < 4; i++)
            As[ka][mb + i * 16] = Ap[(size_t)(m0 + mb + i * 16) * 256 + k0 + ka];
        int nb = t & 63, kb = t >> 6;
#pragma unroll
        for (int i = 0; i < 4; i++) {
            int k = kb + i * 4;
            int n = n0 + nb;
            Bs[k][nb] = (n < Ww) ? d_Cw[(size_t)(k0 + k) * Ww + n] : make_float2(0.f, 0.f);
        }
        __syncthreads();
#pragma unroll
        for (int kk = 0; kk < 16; kk++) {
            u64 ap[4], bp[4];
#pragma unroll
            for (int i = 0; i < 4; i++) ap[i] = *(const u64*)&As[kk][i * 16 + ty];
#pragma unroll
            for (int j = 0; j < 4; j++) bp[j] = *(const u64*)&Bs[kk][j * 16 + tx];
#pragma unroll
            for (int i = 0; i < 4; i++)
#pragma unroll
                for (int j = 0; j < 4; j++) acc[i][j] = ffma2(ap[i], bp[j], acc[i][j]);
        }
        __syncthreads();
    }
#pragma unroll
    for (int i = 0; i < 4; i++) {
        int m = m0 + i * 16 + ty;
#pragma unroll
        for (int j = 0; j < 4; j++) {
            int n = n0 + j * 16 + tx;
            if (n < Ww) {
                size_t idx = (size_t)bc * HWD + (size_t)m * Ww + n;
                float2 v = up2(acc[i][j]);
                r[idx] = v.x + v.y + x[idx];
            }
        }
    }
}

// ------- channel LayerNorm over C -------
__global__ void ln_kernel(const float* __restrict__ r, const float* __restrict__ gamma,
                          const float* __restrict__ beta, float* __restrict__ out)
{
    int p = blockIdx.x * 256 + threadIdx.x;
    int b = p / HWD;
    int hw = p - b * HWD;
    size_t base = (size_t)b * Cc * HWD + hw;
    float sum = 0.f, sq = 0.f;
    for (int c = 0; c < Cc; c++) {
        float v = r[base + (size_t)c * HWD];
        sum += v; sq += v * v;
    }
    float mu = sum * (1.f / Cc);
    float var = sq * (1.f / Cc) - mu * mu;
    float inv = 1.f / sqrtf(var + 1e-6f);
    for (int c = 0; c < Cc; c++) {
        float v = r[base + (size_t)c * HWD];
        out[base + (size_t)c * HWD] = gamma[c] * (v - mu) * inv + beta[c];
    }
}

// ---------------- launch ----------------
extern "C" void kernel_launch(void* const* d_in, const int* in_sizes, int n_in,
                              void* d_out, int out_size)
{
    (void)in_sizes; (void)n_in; (void)out_size;
    const float*  g     = (const float*)d_in[0];
    const float*  x     = (const float*)d_in[1];
    const float*  wg    = (const float*)d_in[2];
    const float*  bg    = (const float*)d_in[3];
    const float*  wx    = (const float*)d_in[4];
    const float*  bx    = (const float*)d_in[5];
    const float2* fg    = (const float2*)d_in[6];
    const float2* fx    = (const float2*)d_in[7];
    const float*  gamma = (const float*)d_in[8];
    const float*  beta  = (const float*)d_in[9];
    float* out = (float*)d_out;

    float *yg, *yx, *rb, *rsq;
    float2 *Fg, *Fx, *Gg, *Gx, *S, *T, *Eh, *Ph;
    cudaGetSymbolAddress((void**)&yg,  d_yg);
    cudaGetSymbolAddress((void**)&yx,  d_yx);
    cudaGetSymbolAddress((void**)&Fg,  d_Fg);
    cudaGetSymbolAddress((void**)&Fx,  d_Fx);
    cudaGetSymbolAddress((void**)&Gg,  d_Gg);
    cudaGetSymbolAddress((void**)&Gx,  d_Gx);
    cudaGetSymbolAddress((void**)&S,   d_Sb);
    cudaGetSymbolAddress((void**)&T,   d_Tb);
    cudaGetSymbolAddress((void**)&rb,  d_rb);
    cudaGetSymbolAddress((void**)&rsq, d_rsq);
    cudaGetSymbolAddress((void**)&Eh,  d_EhM);
    cudaGetSymbolAddress((void**)&Ph,  d_PhM);

    dim3 blk(16, 16);

    build_tables_kernel<<<256, 256>>>();

    conv_kernel<<<dim3(HWD / 64, 2, Bb), blk>>>(g, wg, bg, yg);
    conv_kernel<<<dim3(HWD / 64, 2, Bb), blk>>>(x, wx, bx, yx);

    rfftw_kernel<<<dim3(4, 4, BCD), blk>>>(yg, Fg);
    rfftw_kernel<<<dim3(4, 4, BCD), blk>>>(yx, Fx);

    cgemm_ann_kernel<1><<<dim3(4, 4, BCD), blk>>>(Eh, Fg, Gg, fg);
    cgemm_ann_kernel<1><<<dim3(4, 4, BCD), blk>>>(Eh, Fx, Gx, fx);

    var_kernel<<<BCD * Hh, 256>>>(Gg, rsq);

    scores_kernel<<<dim3(4, 4, BCD), blk>>>(Gg, Gx, rsq, S);

    cgemm_ann_kernel<0><<<dim3(4, 4, BCD), blk>>>(Ph, S, T, nullptr);

    irfft_add_kernel<<<dim3(8, 4, BCD), blk>>>(T, x, rb);

    ln_kernel<<<Bb * HWD / 256, 256>>>(rb, gamma, beta, out);
}

// round 4
// speedup vs baseline: 1.5109x; 1.4251x over previous
#include <cuda_runtime.h>
#include <math.h>

#define Bb  2
#define Cc  128
#define Hh  256
#define Ww  510
#define WFD 256
#define HWD 130560   /* 256*510 */
#define BCD 256      /* Bb*Cc */

typedef unsigned long long u64;

__device__ __forceinline__ u64 pk2(float lo, float hi) {
    u64 r; asm("mov.b64 %0,{%1,%2};" : "=l"(r) : "f"(lo), "f"(hi)); return r;
}
__device__ __forceinline__ float2 up2(u64 v) {
    float2 r; asm("mov.b64 {%0,%1},%2;" : "=f"(r.x), "=f"(r.y) : "l"(v)); return r;
}
__device__ __forceinline__ u64 ffma2(u64 a, u64 b, u64 c) {
    u64 d; asm("fma.rn.f32x2 %0,%1,%2,%3;" : "=l"(d) : "l"(a), "l"(b), "l"(c)); return d;
}

// ---------------- scratch ----------------
__device__ float  d_yg [(size_t)BCD * HWD];
__device__ float  d_yx [(size_t)BCD * HWD];
__device__ float2 d_Fg [(size_t)BCD * Hh * WFD];
__device__ float2 d_Fx [(size_t)BCD * Hh * WFD];
__device__ float2 d_Gg [(size_t)BCD * Hh * WFD];
__device__ float2 d_Gx [(size_t)BCD * Hh * WFD];
__device__ float2 d_Sb [(size_t)BCD * WFD * WFD];
__device__ float2 d_Tb [(size_t)BCD * Hh * WFD];
__device__ float  d_rb [(size_t)BCD * HWD];
__device__ float  d_rsq[BCD * Hh];
__device__ float2 d_Dw [Ww * WFD];
__device__ float2 d_Cw [WFD * Ww];
__device__ float2 d_W256[256];     // e^{-2*pi*i*j/256}

// ---------------- table builder ----------------
__global__ void build_tables_kernel() {
    int idx = blockIdx.x * blockDim.x + threadIdx.x;
    int stride = gridDim.x * blockDim.x;
    float rsW = rsqrtf(510.0f);

    for (int i = idx; i < Ww * WFD; i += stride) {
        int w = i / WFD, v = i - w * WFD;
        int m = (int)(((long long)w * v) % Ww);
        float s, c; sincospif(2.0f * (float)m / (float)Ww, &s, &c);
        d_Dw[i] = make_float2(c * rsW, -s * rsW);
    }
    for (int i = idx; i < WFD * Ww; i += stride) {
        int v = i / Ww, w = i - v * Ww;
        int m = (int)(((long long)v * w) % Ww);
        float s, c; sincospif(2.0f * (float)m / (float)Ww, &s, &c);
        float sv = (v == 0 || v == WFD - 1) ? 1.0f : 2.0f;
        d_Cw[i] = make_float2(sv * c * rsW, -sv * s * rsW);
    }
    for (int j = idx; j < 256; j += stride) {
        float s, c; sincospif(2.0f * (float)j / 256.0f, &s, &c);
        d_W256[j] = make_float2(c, -s);
    }
}

__device__ __forceinline__ float sigm(float v) { return 1.f / (1.f + expf(-v)); }

// ---------------- 1x1 conv (unchanged) ----------------
__global__ void __launch_bounds__(256) conv_kernel(
    const float* __restrict__ X, const float* __restrict__ Wm,
    const float* __restrict__ bias, float* __restrict__ Y)
{
    int b = blockIdx.z;
    const float* Xb = X + (size_t)b * Cc * HWD;
    float* Yb = Y + (size_t)b * Cc * HWD;
    int n0 = blockIdx.x * 64, m0 = blockIdx.y * 64;
    __shared__ float As2[64][18];
    __shared__ float Bs2[64][18];
    int tx = threadIdx.x, ty = threadIdx.y, t = ty * 16 + tx;
    u64 acc[4][4];
#pragma unroll
    for (int i = 0; i < 4; i++)
#pragma unroll
        for (int j = 0; j < 4; j++) acc[i][j] = 0ull;

    for (int k0 = 0; k0 < Cc; k0 += 16) {
        int ka = t & 15, mb = t >> 4;
#pragma unroll
        for (int i = 0; i < 4; i++)
            As2[mb + i * 16][ka] = Wm[(m0 + mb + i * 16) * Cc + k0 + ka];
        int nb = t & 63, kb = t >> 6;
#pragma unroll
        for (int i = 0; i < 4; i++)
            Bs2[nb][kb + i * 4] = Xb[(size_t)(k0 + kb + i * 4) * HWD + n0 + nb];
        __syncthreads();
#pragma unroll
        for (int kp = 0; kp < 8; kp++) {
            u64 av[4], bv[4];
#pragma unroll
            for (int i = 0; i < 4; i++) av[i] = *(const u64*)&As2[i * 16 + ty][kp * 2];
#pragma unroll
            for (int j = 0; j < 4; j++) bv[j] = *(const u64*)&Bs2[j * 16 + tx][kp * 2];
#pragma unroll
            for (int i = 0; i < 4; i++)
#pragma unroll
                for (int j = 0; j < 4; j++) acc[i][j] = ffma2(av[i], bv[j], acc[i][j]);
        }
        __syncthreads();
    }
#pragma unroll
    for (int i = 0; i < 4; i++) {
        int m = m0 + i * 16 + ty;
        float bvv = bias[m];
#pragma unroll
        for (int j = 0; j < 4; j++) {
            float2 v = up2(acc[i][j]);
            Yb[(size_t)m * HWD + n0 + j * 16 + tx] = v.x + v.y + bvv;
        }
    }
}

// ---------------- rfft along W: 8m x 4n tile, real A pairs ----------------
__global__ void __launch_bounds__(256) rfftw_kernel(
    const float* __restrict__ Y, float2* __restrict__ F)
{
    int bc = blockIdx.z;
    const float* A = Y + (size_t)bc * HWD;
    float2* Cp = F + (size_t)bc * Hh * WFD;
    int n0 = blockIdx.x * 64, m0 = blockIdx.y * 128;
    __shared__ float  As[16][130];   // [k][m], m-contiguous (pairs via LDS.64)
    __shared__ float2 Bs[16][66];
    int tx = threadIdx.x, ty = threadIdx.y, t = ty * 16 + tx;
    u64 acc[4][2][4];
#pragma unroll
    for (int p = 0; p < 4; p++)
#pragma unroll
        for (int q = 0; q < 2; q++)
#pragma unroll
            for (int j = 0; j < 4; j++) acc[p][q][j] = 0ull;

    for (int k0 = 0; k0 < Ww; k0 += 16) {
        int ka = t & 15, mb = t >> 4;
        bool oka = (k0 + ka) < Ww;
#pragma unroll
        for (int i = 0; i < 8; i++)
            As[ka][mb + i * 16] = oka ? A[(size_t)(m0 + mb + i * 16) * Ww + k0 + ka] : 0.f;
        int nb = t & 63, kb = t >> 6;
#pragma unroll
        for (int i = 0; i < 4; i++) {
            int k = kb + i * 4;
            Bs[k][nb] = (k0 + k) < Ww ? d_Dw[(size_t)(k0 + k) * WFD + n0 + nb]
                                      : make_float2(0.f, 0.f);
        }
        __syncthreads();
#pragma unroll
        for (int kk = 0; kk < 16; kk++) {
            u64 bv[4];
#pragma unroll
            for (int j = 0; j < 4; j++) bv[j] = *(const u64*)&Bs[kk][j * 16 + tx];
#pragma unroll
            for (int p = 0; p < 4; p++) {
                float2 ap = *(const float2*)&As[kk][ty * 2 + p * 32];
                u64 s0 = pk2(ap.x, ap.x), s1 = pk2(ap.y, ap.y);
#pragma unroll
                for (int j = 0; j < 4; j++) {
                    acc[p][0][j] = ffma2(s0, bv[j], acc[p][0][j]);
                    acc[p][1][j] = ffma2(s1, bv[j], acc[p][1][j]);
                }
            }
        }
        __syncthreads();
    }
#pragma unroll
    for (int p = 0; p < 4; p++)
#pragma unroll
        for (int q = 0; q < 2; q++) {
            int m = m0 + p * 32 + ty * 2 + q;
#pragma unroll
            for (int j = 0; j < 4; j++)
                Cp[(size_t)m * WFD + n0 + j * 16 + tx] = up2(acc[p][q][j]);
        }
}

// ---------------- 256-pt FFT along slow axis (4-step 16x16), 16 columns/block ----
// in/out layout: [bc][row(256)][col(256)], FFT over row index. INV: conjugate twiddles.
// FILT: multiply output row u by filt[c][u][v] (forward g/x path).
template<int INV, int FILT>
__global__ void __launch_bounds__(256) ffth_kernel(
    const float2* __restrict__ in, float2* __restrict__ out,
    const float2* __restrict__ filt)
{
    __shared__ float2 Xs[256][17];
    __shared__ float2 Ws[256];
    int bc = blockIdx.y;
    int v0 = blockIdx.x * 16;
    int tx = threadIdx.x;        // column lane (16)
    int ty = threadIdx.y;        // k1 (phase1) / k2 (phase2)
    int t = ty * 16 + tx;
    const float2* inp = in + (size_t)bc * 65536 + v0;
    float2* outp = out + (size_t)bc * 65536 + v0;

    {
        float2 w = d_W256[t];
        if (INV) w.y = -w.y;
        Ws[t] = w;
    }
#pragma unroll
    for (int i = 0; i < 16; i++) {
        int h = i * 16 + ty;
        Xs[h][tx] = inp[(size_t)h * 256 + tx];
    }
    __syncthreads();

    // phase 1: A'[k1][n2] = W256^{n2*k1} * sum_n1 W16^{n1*k1} x[16*n1+n2]
    float2 r[16];
    {
        u64 tw[16];
#pragma unroll
        for (int n1 = 0; n1 < 16; n1++) {
            float2 w = Ws[(n1 * ty * 16) & 255];
            tw[n1] = pk2(w.x, w.y);
        }
#pragma unroll
        for (int n2 = 0; n2 < 16; n2++) {
            u64 accA = 0ull, accB = 0ull;
#pragma unroll
            for (int n1 = 0; n1 < 16; n1++) {
                float2 xv = Xs[16 * n1 + n2][tx];
                u64 xp = pk2(xv.x, xv.y);
                u64 xq = pk2(xv.y, xv.x);
                accA = ffma2(xp, tw[n1], accA);
                accB = ffma2(xq, tw[n1], accB);
            }
            float2 a = up2(accA), b = up2(accB);
            float ar = a.x - a.y, ai = b.x + b.y;
            float2 tm = Ws[(n2 * ty) & 255];
            r[n2] = make_float2(ar * tm.x - ai * tm.y, ar * tm.y + ai * tm.x);
        }
    }
    __syncthreads();
#pragma unroll
    for (int n2 = 0; n2 < 16; n2++)
        Xs[ty * 16 + n2][tx] = r[n2];
    __syncthreads();

    // phase 2: G[k1 + 16*k2] = (1/16) * sum_n2 W16^{n2*k2} * A'[k1][n2]
    {
        u64 tw[16];
#pragma unroll
        for (int n2 = 0; n2 < 16; n2++) {
            float2 w = Ws[(n2 * ty * 16) & 255];
            tw[n2] = pk2(w.x, w.y);
        }
        int c = bc & (Cc - 1);
#pragma unroll
        for (int k1 = 0; k1 < 16; k1++) {
            u64 accA = 0ull, accB = 0ull;
#pragma unroll
            for (int n2 = 0; n2 < 16; n2++) {
                float2 xv = Xs[k1 * 16 + n2][tx];
                u64 xp = pk2(xv.x, xv.y);
                u64 xq = pk2(xv.y, xv.x);
                accA = ffma2(xp, tw[n2], accA);
                accB = ffma2(xq, tw[n2], accB);
            }
            float2 a = up2(accA), b = up2(accB);
            int u = k1 + 16 * ty;
            float2 v = make_float2((a.x - a.y) * 0.0625f, (b.x + b.y) * 0.0625f);
            if (FILT) {
                float2 wc = filt[((size_t)c * Hh + u) * WFD + v0 + tx];
                v = make_float2(v.x * wc.x - v.y * wc.y, v.x * wc.y + v.y * wc.x);
            }
            outp[(size_t)u * 256 + tx] = v;
        }
    }
}

// ------- variance over v per (bc,u) row -------
__global__ void var_kernel(const float2* __restrict__ G, float* __restrict__ rsq)
{
    __shared__ float s0[256], s1[256], s2[256];
    int row = blockIdx.x;
    int tid = threadIdx.x;
    float2 z = G[(size_t)row * WFD + tid];
    s0[tid] = z.x; s1[tid] = z.y; s2[tid] = z.x * z.x + z.y * z.y;
    __syncthreads();
    for (int s = 128; s > 0; s >>= 1) {
        if (tid < s) { s0[tid] += s0[tid + s]; s1[tid] += s1[tid + s]; s2[tid] += s2[tid + s]; }
        __syncthreads();
    }
    if (tid == 0) {
        float mr = s0[0] * (1.f / WFD), mi = s1[0] * (1.f / WFD);
        float var = s2[0] * (1.f / WFD) - (mr * mr + mi * mi);
        rsq[row] = 1.f / sqrtf(6.283185307179586f * var);
    }
}

// ------- scores: S[i,j] = sigmoid( (sum_u G[u,i]*X[u,j]) * rsq[i] ) -------
__global__ void __launch_bounds__(256) scores_kernel(
    const float2* __restrict__ Gb, const float2* __restrict__ Xb,
    const float* __restrict__ rsq, float2* __restrict__ Sb)
{
    int bc = blockIdx.z;
    const float2* Ap = Gb + (size_t)bc * 65536;
    const float2* Bp = Xb + (size_t)bc * 65536;
    float2* Cp = Sb + (size_t)bc * 65536;
    int n0 = blockIdx.x * 64, m0 = blockIdx.y * 64;
    __shared__ float2 As[16][66];
    __shared__ float2 Bs[16][66];
    int tx = threadIdx.x, ty = threadIdx.y, t = ty * 16 + tx;
    u64 accA[4][4], accB[4][4];
#pragma unroll
    for (int i = 0; i < 4; i++)
#pragma unroll
        for (int j = 0; j < 4; j++) { accA[i][j] = 0ull; accB[i][j] = 0ull; }

    for (int k0 = 0; k0 < 256; k0 += 16) {
        int nb = t & 63, kb = t >> 6;
#pragma unroll
        for (int i = 0; i < 4; i++) {
            int k = kb + i * 4;
            As[k][nb] = Ap[(size_t)(k0 + k) * 256 + m0 + nb];
            Bs[k][nb] = Bp[(size_t)(k0 + k) * 256 + n0 + nb];
        }
        __syncthreads();
#pragma unroll
        for (int kk = 0; kk < 16; kk++) {
            u64 ap[4], aq[4], bp[4];
#pragma unroll
            for (int i = 0; i < 4; i++) {
                float2 a = As[kk][i * 16 + ty];
                ap[i] = pk2(a.x, a.y);
                aq[i] = pk2(a.y, a.x);
            }
#pragma unroll
            for (int j = 0; j < 4; j++) bp[j] = *(const u64*)&Bs[kk][j * 16 + tx];
#pragma unroll
            for (int i = 0; i < 4; i++)
#pragma unroll
                for (int j = 0; j < 4; j++) {
                    accA[i][j] = ffma2(ap[i], bp[j], accA[i][j]);
                    accB[i][j] = ffma2(aq[i], bp[j], accB[i][j]);
                }
        }
        __syncthreads();
    }
#pragma unroll
    for (int i = 0; i < 4; i++) {
        int m = m0 + i * 16 + ty;
        float sc = rsq[bc * Hh + m];
#pragma unroll
        for (int j = 0; j < 4; j++) {
            int n = n0 + j * 16 + tx;
            float2 va = up2(accA[i][j]), vb = up2(accB[i][j]);
            float2 v = make_float2(sigm((va.x - va.y) * sc), sigm((vb.x + vb.y) * sc));
            Cp[(size_t)m * 256 + n] = v;
        }
    }
}

// ------- irfft along W (folded Hermitian) + residual add -------
__global__ void __launch_bounds__(256) irfft_add_kernel(
    const float2* __restrict__ Tb, const float* __restrict__ x, float* __restrict__ r)
{
    int bc = blockIdx.z;
    const float2* Ap = Tb + (size_t)bc * 65536;
    int n0 = blockIdx.x * 64, m0 = blockIdx.y * 64;
    __shared__ float2 As[16][66];
    __shared__ float2 Bs[16][66];
    int tx = threadIdx.x, ty = threadIdx.y, t = ty * 16 + tx;
    u64 acc[4][4];
#pragma unroll
    for (int i = 0; i < 4; i++)
#pragma unroll
        for (int j = 0; j < 4; j++) acc[i][j] = 0ull;

    for (int k0 = 0; k0 < 256; k0 += 16) {
        int ka = t & 15, mb = t >> 4;
#pragma unroll
        for (int i = 0; i < 4; i++)
            As[ka][mb + i * 16] = Ap[(size_t)(m0 + mb + i * 16) * 256 + k0 + ka];
        int nb = t & 63, kb = t >> 6;
#pragma unroll
        for (int i = 0; i < 4; i++) {
            int k = kb + i * 4;
            int n = n0 + nb;
            Bs[k][nb] = (n < Ww) ? d_Cw[(size_t)(k0 + k) * Ww + n] : make_float2(0.f, 0.f);
        }
        __syncthreads();
#pragma unroll
        for (int kk = 0; kk < 16; kk++) {
            u64 ap[4], bp[4];
#pragma unroll
            for (int i = 0; i < 4; i++) ap[i] = *(const u64*)&As[kk][i * 16 + ty];
#pragma unroll
            for (int j = 0; j < 4; j++) bp[j] = *(const u64*)&Bs[kk][j * 16 + tx];
#pragma unroll
            for (int i = 0; i < 4; i++)
#pragma unroll
                for (int j = 0; j < 4; j++) acc[i][j] = ffma2(ap[i], bp[j], acc[i][j]);
        }
        __syncthreads();
    }
#pragma unroll
    for (int i = 0; i < 4; i++) {
        int m = m0 + i * 16 + ty;
#pragma unroll
        for (int j = 0; j < 4; j++) {
            int n = n0 + j * 16 + tx;
            if (n < Ww) {
                size_t idx = (size_t)bc * HWD + (size_t)m * Ww + n;
                float2 v = up2(acc[i][j]);
                r[idx] = v.x + v.y + x[idx];
            }
        }
    }
}

// ------- channel LayerNorm -------
__global__ void ln_kernel(const float* __restrict__ r, const float* __restrict__ gamma,
                          const float* __restrict__ beta, float* __restrict__ out)
{
    int p = blockIdx.x * 256 + threadIdx.x;
    int b = p / HWD;
    int hw = p - b * HWD;
    size_t base = (size_t)b * Cc * HWD + hw;
    float sum = 0.f, sq = 0.f;
    for (int c = 0; c < Cc; c++) {
        float v = r[base + (size_t)c * HWD];
        sum += v; sq += v * v;
    }
    float mu = sum * (1.f / Cc);
    float var = sq * (1.f / Cc) - mu * mu;
    float inv = 1.f / sqrtf(var + 1e-6f);
    for (int c = 0; c < Cc; c++) {
        float v = r[base + (size_t)c * HWD];
        out[base + (size_t)c * HWD] = gamma[c] * (v - mu) * inv + beta[c];
    }
}

// ---------------- launch ----------------
extern "C" void kernel_launch(void* const* d_in, const int* in_sizes, int n_in,
                              void* d_out, int out_size)
{
    (void)in_sizes; (void)n_in; (void)out_size;
    const float*  g     = (const float*)d_in[0];
    const float*  x     = (const float*)d_in[1];
    const float*  wg    = (const float*)d_in[2];
    const float*  bg    = (const float*)d_in[3];
    const float*  wx    = (const float*)d_in[4];
    const float*  bx    = (const float*)d_in[5];
    const float2* fg    = (const float2*)d_in[6];
    const float2* fx    = (const float2*)d_in[7];
    const float*  gamma = (const float*)d_in[8];
    const float*  beta  = (const float*)d_in[9];
    float* out = (float*)d_out;

    float *yg, *yx, *rb, *rsq;
    float2 *Fg, *Fx, *Gg, *Gx, *S, *T;
    cudaGetSymbolAddress((void**)&yg,  d_yg);
    cudaGetSymbolAddress((void**)&yx,  d_yx);
    cudaGetSymbolAddress((void**)&Fg,  d_Fg);
    cudaGetSymbolAddress((void**)&Fx,  d_Fx);
    cudaGetSymbolAddress((void**)&Gg,  d_Gg);
    cudaGetSymbolAddress((void**)&Gx,  d_Gx);
    cudaGetSymbolAddress((void**)&S,   d_Sb);
    cudaGetSymbolAddress((void**)&T,   d_Tb);
    cudaGetSymbolAddress((void**)&rb,  d_rb);
    cudaGetSymbolAddress((void**)&rsq, d_rsq);

    dim3 blk(16, 16);

    build_tables_kernel<<<256, 256>>>();

    conv_kernel<<<dim3(HWD / 64, 2, Bb), blk>>>(g, wg, bg, yg);
    conv_kernel<<<dim3(HWD / 64, 2, Bb), blk>>>(x, wx, bx, yx);

    rfftw_kernel<<<dim3(4, 2, BCD), blk>>>(yg, Fg);
    rfftw_kernel<<<dim3(4, 2, BCD), blk>>>(yx, Fx);

    ffth_kernel<0, 1><<<dim3(16, BCD), blk>>>(Fg, Gg, fg);
    ffth_kernel<0, 1><<<dim3(16, BCD), blk>>>(Fx, Gx, fx);

    var_kernel<<<BCD * Hh, 256>>>(Gg, rsq);

    scores_kernel<<<dim3(4, 4, BCD), blk>>>(Gg, Gx, rsq, S);

    ffth_kernel<1, 0><<<dim3(16, BCD), blk>>>(S, T, nullptr);

    irfft_add_kernel<<<dim3(8, 4, BCD), blk>>>(T, x, rb);

    ln_kernel<<<Bb * HWD / 256, 256>>>(rb, gamma, beta, out);
}

// round 5
// speedup vs baseline: 1.9481x; 1.2894x over previous
#include <cuda_runtime.h>
#include <cuda_bf16.h>
#include <math.h>

#define Bb  2
#define Cc  128
#define Hh  256
#define Ww  510
#define WFD 256
#define HWD 130560   /* 256*510 */
#define BCD 256      /* Bb*Cc */

typedef unsigned int u32;
typedef unsigned long long u64;

__device__ __forceinline__ u64 pk2(float lo, float hi) {
    u64 r; asm("mov.b64 %0,{%1,%2};" : "=l"(r) : "f"(lo), "f"(hi)); return r;
}
__device__ __forceinline__ float2 up2(u64 v) {
    float2 r; asm("mov.b64 {%0,%1},%2;" : "=f"(r.x), "=f"(r.y) : "l"(v)); return r;
}
__device__ __forceinline__ u64 ffma2(u64 a, u64 b, u64 c) {
    u64 d; asm("fma.rn.f32x2 %0,%1,%2,%3;" : "=l"(d) : "l"(a), "l"(b), "l"(c)); return d;
}

// ---- tensor-core helpers -------------------------------------------------
__device__ __forceinline__ void mma_bf16(float* c, const u32* a, const u32* b) {
    asm("mma.sync.aligned.m16n8k16.row.col.f32.bf16.bf16.f32 "
        "{%0,%1,%2,%3},{%4,%5,%6,%7},{%8,%9},{%0,%1,%2,%3};"
        : "+f"(c[0]), "+f"(c[1]), "+f"(c[2]), "+f"(c[3])
        : "r"(a[0]), "r"(a[1]), "r"(a[2]), "r"(a[3]), "r"(b[0]), "r"(b[1]));
}
__device__ __forceinline__ void ldmA(u32* a, u32 addr) {
    asm volatile("ldmatrix.sync.aligned.m8n8.x4.shared.b16 {%0,%1,%2,%3},[%4];"
        : "=r"(a[0]), "=r"(a[1]), "=r"(a[2]), "=r"(a[3]) : "r"(addr));
}
__device__ __forceinline__ void ldmB(u32* b, u32 addr) {
    asm volatile("ldmatrix.sync.aligned.m8n8.x2.shared.b16 {%0,%1},[%2];"
        : "=r"(b[0]), "=r"(b[1]) : "r"(addr));
}
__device__ __forceinline__ u32 smaddr(const void* p) {
    return (u32)__cvta_generic_to_shared(p);
}
__device__ __forceinline__ void bsplit2(float a, float b, u32& hi, u32& lo) {
    __nv_bfloat16 ha = __float2bfloat16(a), hb = __float2bfloat16(b);
    hi = (u32)__bfloat16_as_ushort(ha) | ((u32)__bfloat16_as_ushort(hb) << 16);
    float ra = a - __bfloat162float(ha), rb = b - __bfloat162float(hb);
    __nv_bfloat16 la = __float2bfloat16(ra), lb = __float2bfloat16(rb);
    lo = (u32)__bfloat16_as_ushort(la) | ((u32)__bfloat16_as_ushort(lb) << 16);
}

// ---------------- scratch ----------------
__device__ float  d_yg [(size_t)BCD * HWD];
__device__ float  d_yx [(size_t)BCD * HWD];
__device__ float2 d_Fg [(size_t)BCD * Hh * WFD];
__device__ float2 d_Fx [(size_t)BCD * Hh * WFD];
__device__ float2 d_Gg [(size_t)BCD * Hh * WFD];
__device__ float2 d_Gx [(size_t)BCD * Hh * WFD];
__device__ float2 d_Sb [(size_t)BCD * WFD * WFD];
__device__ float2 d_Tb [(size_t)BCD * Hh * WFD];
__device__ float  d_rb [(size_t)BCD * HWD];
__device__ float  d_rsq[BCD * Hh];
__device__ float2 d_W256[256];
// bf16 hi/lo split transposed DFT tables
__device__ __nv_bfloat16 d_DwTreh[256 * 512];   // [v][w]  cos*rsW
__device__ __nv_bfloat16 d_DwTrel[256 * 512];
__device__ __nv_bfloat16 d_DwTimh[256 * 512];   // -sin*rsW
__device__ __nv_bfloat16 d_DwTiml[256 * 512];
__device__ __nv_bfloat16 d_CwT1h [512 * 256];   // [w][v]  sv*cos*rsW
__device__ __nv_bfloat16 d_CwT1l [512 * 256];
__device__ __nv_bfloat16 d_CwT2h [512 * 256];   // -sv*sin*rsW
__device__ __nv_bfloat16 d_CwT2l [512 * 256];

// ---------------- table builder ----------------
__global__ void build_tables_kernel() {
    int idx = blockIdx.x * blockDim.x + threadIdx.x;
    int stride = gridDim.x * blockDim.x;
    float rsW = rsqrtf(510.0f);

    for (int i = idx; i < 256 * 512; i += stride) {
        int v = i >> 9, w = i & 511;
        float re = 0.f, im = 0.f;
        if (w < Ww) {
            int m = (int)(((long long)w * v) % Ww);
            float s, c; sincospif(2.0f * (float)m / (float)Ww, &s, &c);
            re = c * rsW; im = -s * rsW;
        }
        __nv_bfloat16 h = __float2bfloat16(re);
        d_DwTreh[i] = h;
        d_DwTrel[i] = __float2bfloat16(re - __bfloat162float(h));
        h = __float2bfloat16(im);
        d_DwTimh[i] = h;
        d_DwTiml[i] = __float2bfloat16(im - __bfloat162float(h));
    }
    for (int i = idx; i < 512 * 256; i += stride) {
        int w = i >> 8, v = i & 255;
        float b1 = 0.f, b2 = 0.f;
        if (w < Ww) {
            int m = (int)(((long long)v * w) % Ww);
            float s, c; sincospif(2.0f * (float)m / (float)Ww, &s, &c);
            float sv = (v == 0 || v == 255) ? 1.0f : 2.0f;
            b1 = sv * c * rsW; b2 = -sv * s * rsW;
        }
        __nv_bfloat16 h = __float2bfloat16(b1);
        d_CwT1h[i] = h;
        d_CwT1l[i] = __float2bfloat16(b1 - __bfloat162float(h));
        h = __float2bfloat16(b2);
        d_CwT2h[i] = h;
        d_CwT2l[i] = __float2bfloat16(b2 - __bfloat162float(h));
    }
    for (int j = idx; j < 256; j += stride) {
        float s, c; sincospif(2.0f * (float)j / 256.0f, &s, &c);
        d_W256[j] = make_float2(c, -s);
    }
}

__device__ __forceinline__ float sigm(float v) { return 1.f / (1.f + expf(-v)); }

// ---------------- 1x1 conv (FFMA2 SIMT) ----------------
__global__ void __launch_bounds__(256) conv_kernel(
    const float* __restrict__ X, const float* __restrict__ Wm,
    const float* __restrict__ bias, float* __restrict__ Y)
{
    int b = blockIdx.z;
    const float* Xb = X + (size_t)b * Cc * HWD;
    float* Yb = Y + (size_t)b * Cc * HWD;
    int n0 = blockIdx.x * 64, m0 = blockIdx.y * 64;
    __shared__ float As2[64][18];
    __shared__ float Bs2[64][18];
    int tx = threadIdx.x, ty = threadIdx.y, t = ty * 16 + tx;
    u64 acc[4][4];
#pragma unroll
    for (int i = 0; i < 4; i++)
#pragma unroll
        for (int j = 0; j < 4; j++) acc[i][j] = 0ull;

    for (int k0 = 0; k0 < Cc; k0 += 16) {
        int ka = t & 15, mb = t >> 4;
#pragma unroll
        for (int i = 0; i < 4; i++)
            As2[mb + i * 16][ka] = Wm[(m0 + mb + i * 16) * Cc + k0 + ka];
        int nb = t & 63, kb = t >> 6;
#pragma unroll
        for (int i = 0; i < 4; i++)
            Bs2[nb][kb + i * 4] = Xb[(size_t)(k0 + kb + i * 4) * HWD + n0 + nb];
        __syncthreads();
#pragma unroll
        for (int kp = 0; kp < 8; kp++) {
            u64 av[4], bv[4];
#pragma unroll
            for (int i = 0; i < 4; i++) av[i] = *(const u64*)&As2[i * 16 + ty][kp * 2];
#pragma unroll
            for (int j = 0; j < 4; j++) bv[j] = *(const u64*)&Bs2[j * 16 + tx][kp * 2];
#pragma unroll
            for (int i = 0; i < 4; i++)
#pragma unroll
                for (int j = 0; j < 4; j++) acc[i][j] = ffma2(av[i], bv[j], acc[i][j]);
        }
        __syncthreads();
    }
#pragma unroll
    for (int i = 0; i < 4; i++) {
        int m = m0 + i * 16 + ty;
        float bvv = bias[m];
#pragma unroll
        for (int j = 0; j < 4; j++) {
            float2 v = up2(acc[i][j]);
            Yb[(size_t)m * HWD + n0 + j * 16 + tx] = v.x + v.y + bvv;
        }
    }
}

// ---------------- rfft along W — TENSOR CORE (bf16 3-split) ----------------
#define PIT 40   // smem pitch in bf16 (80B rows, 16B-aligned, ldmatrix conflict-free)

__global__ void __launch_bounds__(256) rfftw_tc(
    const float* __restrict__ Y, float2* __restrict__ F)
{
    __shared__ __nv_bfloat16 sAh[64 * PIT], sAl[64 * PIT];
    __shared__ __nv_bfloat16 sBrh[64 * PIT], sBrl[64 * PIT], sBih[64 * PIT], sBil[64 * PIT];
    int bc = blockIdx.z;
    const float* A = Y + (size_t)bc * HWD;
    float2* Cp = F + (size_t)bc * Hh * WFD;
    int n0 = blockIdx.x * 64, m0 = blockIdx.y * 64;
    int t = threadIdx.x, lane = t & 31, wid = t >> 5;
    int wm = (wid >> 2) * 32, wn = (wid & 3) * 16;
    int g = lane >> 2, tc = lane & 3;

    float cre[2][2][4], cim[2][2][4];
#pragma unroll
    for (int i = 0; i < 2; i++)
#pragma unroll
        for (int j = 0; j < 2; j++)
#pragma unroll
            for (int q = 0; q < 4; q++) { cre[i][j][q] = 0.f; cim[i][j][q] = 0.f; }

    u32 aAh = smaddr(sAh), aAl = smaddr(sAl);
    u32 aBrh = smaddr(sBrh), aBrl = smaddr(sBrl), aBih = smaddr(sBih), aBil = smaddr(sBil);
    int lrA = lane & 15, lkA = (lane >> 4) * 8;
    int lrB = lane & 7,  lkB = ((lane >> 3) & 1) * 8;

    int sc = t & 15, sr = t >> 4;
    for (int k0 = 0; k0 < 512; k0 += 32) {
        // stage A (split on the fly)
#pragma unroll
        for (int i = 0; i < 4; i++) {
            int r = sr + i * 16;
            int w = k0 + 2 * sc;
            const float* row = A + (size_t)(m0 + r) * Ww;
            float a0 = (w < Ww) ? row[w] : 0.f;
            float a1 = (w + 1 < Ww) ? row[w + 1] : 0.f;
            u32 hi, lo; bsplit2(a0, a1, hi, lo);
            *(u32*)&sAh[r * PIT + 2 * sc] = hi;
            *(u32*)&sAl[r * PIT + 2 * sc] = lo;
        }
        // stage B (prebuilt split tables, plain copies)
#pragma unroll
        for (int i = 0; i < 4; i++) {
            int r = sr + i * 16;
            size_t gi = (size_t)(n0 + r) * 512 + k0 + 2 * sc;
            int so = r * PIT + 2 * sc;
            *(u32*)&sBrh[so] = *(const u32*)&d_DwTreh[gi];
            *(u32*)&sBrl[so] = *(const u32*)&d_DwTrel[gi];
            *(u32*)&sBih[so] = *(const u32*)&d_DwTimh[gi];
            *(u32*)&sBil[so] = *(const u32*)&d_DwTiml[gi];
        }
        __syncthreads();
#pragma unroll
        for (int ks = 0; ks < 2; ks++) {
            int kb = ks * 16;
            u32 ah[2][4], al[2][4];
#pragma unroll
            for (int tm = 0; tm < 2; tm++) {
                u32 off = ((wm + 16 * tm + lrA) * PIT + kb + lkA) * 2;
                ldmA(ah[tm], aAh + off);
                ldmA(al[tm], aAl + off);
            }
            u32 brh[2][2], brl[2][2], bih[2][2], bil[2][2];
#pragma unroll
            for (int tn = 0; tn < 2; tn++) {
                u32 off = ((wn + 8 * tn + lrB) * PIT + kb + lkB) * 2;
                ldmB(brh[tn], aBrh + off);
                ldmB(brl[tn], aBrl + off);
                ldmB(bih[tn], aBih + off);
                ldmB(bil[tn], aBil + off);
            }
#pragma unroll
            for (int tm = 0; tm < 2; tm++)
#pragma unroll
                for (int tn = 0; tn < 2; tn++) {
                    mma_bf16(cre[tm][tn], ah[tm], brh[tn]);
                    mma_bf16(cre[tm][tn], ah[tm], brl[tn]);
                    mma_bf16(cre[tm][tn], al[tm], brh[tn]);
                    mma_bf16(cim[tm][tn], ah[tm], bih[tn]);
                    mma_bf16(cim[tm][tn], ah[tm], bil[tn]);
                    mma_bf16(cim[tm][tn], al[tm], bih[tn]);
                }
        }
        __syncthreads();
    }
#pragma unroll
    for (int tm = 0; tm < 2; tm++)
#pragma unroll
        for (int tn = 0; tn < 2; tn++) {
            int r0 = m0 + wm + 16 * tm + g;
            int col = n0 + wn + 8 * tn + 2 * tc;
            float4 v0 = make_float4(cre[tm][tn][0], cim[tm][tn][0], cre[tm][tn][1], cim[tm][tn][1]);
            *(float4*)&Cp[(size_t)r0 * WFD + col] = v0;
            float4 v1 = make_float4(cre[tm][tn][2], cim[tm][tn][2], cre[tm][tn][3], cim[tm][tn][3]);
            *(float4*)&Cp[(size_t)(r0 + 8) * WFD + col] = v1;
        }
}

// ------- irfft along W + residual — TENSOR CORE (bf16 3-split, folded real) ----
__global__ void __launch_bounds__(256) irfft_add_tc(
    const float2* __restrict__ T, const float* __restrict__ x, float* __restrict__ r)
{
    __shared__ __nv_bfloat16 sArh[64 * PIT], sArl[64 * PIT], sAih[64 * PIT], sAil[64 * PIT];
    __shared__ __nv_bfloat16 sB1h[64 * PIT], sB1l[64 * PIT], sB2h[64 * PIT], sB2l[64 * PIT];
    int bc = blockIdx.z;
    const float2* Ap = T + (size_t)bc * 65536;
    int n0 = blockIdx.x * 64, m0 = blockIdx.y * 64;
    int t = threadIdx.x, lane = t & 31, wid = t >> 5;
    int wm = (wid >> 2) * 32, wn = (wid & 3) * 16;
    int g = lane >> 2, tc = lane & 3;

    float acc[2][2][4];
#pragma unroll
    for (int i = 0; i < 2; i++)
#pragma unroll
        for (int j = 0; j < 2; j++)
#pragma unroll
            for (int q = 0; q < 4; q++) acc[i][j][q] = 0.f;

    u32 aArh = smaddr(sArh), aArl = smaddr(sArl), aAih = smaddr(sAih), aAil = smaddr(sAil);
    u32 aB1h = smaddr(sB1h), aB1l = smaddr(sB1l), aB2h = smaddr(sB2h), aB2l = smaddr(sB2l);
    int lrA = lane & 15, lkA = (lane >> 4) * 8;
    int lrB = lane & 7,  lkB = ((lane >> 3) & 1) * 8;

    int sc = t & 15, sr = t >> 4;
    for (int k0 = 0; k0 < 256; k0 += 32) {
#pragma unroll
        for (int i = 0; i < 4; i++) {
            int rr = sr + i * 16;
            float4 v = *(const float4*)&Ap[(size_t)(m0 + rr) * 256 + k0 + 2 * sc];
            u32 hi, lo;
            int so = rr * PIT + 2 * sc;
            bsplit2(v.x, v.z, hi, lo);
            *(u32*)&sArh[so] = hi; *(u32*)&sArl[so] = lo;
            bsplit2(v.y, v.w, hi, lo);
            *(u32*)&sAih[so] = hi; *(u32*)&sAil[so] = lo;
        }
#pragma unroll
        for (int i = 0; i < 4; i++) {
            int rr = sr + i * 16;
            size_t gi = (size_t)(n0 + rr) * 256 + k0 + 2 * sc;
            int so = rr * PIT + 2 * sc;
            *(u32*)&sB1h[so] = *(const u32*)&d_CwT1h[gi];
            *(u32*)&sB1l[so] = *(const u32*)&d_CwT1l[gi];
            *(u32*)&sB2h[so] = *(const u32*)&d_CwT2h[gi];
            *(u32*)&sB2l[so] = *(const u32*)&d_CwT2l[gi];
        }
        __syncthreads();
#pragma unroll
        for (int ks = 0; ks < 2; ks++) {
            int kb = ks * 16;
            u32 arh[2][4], arl[2][4], aih[2][4], ail[2][4];
#pragma unroll
            for (int tm = 0; tm < 2; tm++) {
                u32 off = ((wm + 16 * tm + lrA) * PIT + kb + lkA) * 2;
                ldmA(arh[tm], aArh + off);
                ldmA(arl[tm], aArl + off);
                ldmA(aih[tm], aAih + off);
                ldmA(ail[tm], aAil + off);
            }
            u32 b1h[2][2], b1l[2][2], b2h[2][2], b2l[2][2];
#pragma unroll
            for (int tn = 0; tn < 2; tn++) {
                u32 off = ((wn + 8 * tn + lrB) * PIT + kb + lkB) * 2;
                ldmB(b1h[tn], aB1h + off);
                ldmB(b1l[tn], aB1l + off);
                ldmB(b2h[tn], aB2h + off);
                ldmB(b2l[tn], aB2l + off);
            }
#pragma unroll
            for (int tm = 0; tm < 2; tm++)
#pragma unroll
                for (int tn = 0; tn < 2; tn++) {
                    mma_bf16(acc[tm][tn], arh[tm], b1h[tn]);
                    mma_bf16(acc[tm][tn], arh[tm], b1l[tn]);
                    mma_bf16(acc[tm][tn], arl[tm], b1h[tn]);
                    mma_bf16(acc[tm][tn], aih[tm], b2h[tn]);
                    mma_bf16(acc[tm][tn], aih[tm], b2l[tn]);
                    mma_bf16(acc[tm][tn], ail[tm], b2h[tn]);
                }
        }
        __syncthreads();
    }
#pragma unroll
    for (int tm = 0; tm < 2; tm++)
#pragma unroll
        for (int tn = 0; tn < 2; tn++) {
            int col = n0 + wn + 8 * tn + 2 * tc;
            if (col < Ww) {
                int r0 = m0 + wm + 16 * tm + g;
                size_t i0 = (size_t)bc * HWD + (size_t)r0 * Ww + col;
                size_t i1 = i0 + (size_t)8 * Ww;
                float2 xv = *(const float2*)&x[i0];
                *(float2*)&r[i0] = make_float2(acc[tm][tn][0] + xv.x, acc[tm][tn][1] + xv.y);
                xv = *(const float2*)&x[i1];
                *(float2*)&r[i1] = make_float2(acc[tm][tn][2] + xv.x, acc[tm][tn][3] + xv.y);
            }
        }
}

// ---------------- 256-pt FFT along slow axis (4-step 16x16) ----------------
template<int INV, int FILT>
__global__ void __launch_bounds__(256) ffth_kernel(
    const float2* __restrict__ in, float2* __restrict__ out,
    const float2* __restrict__ filt)
{
    __shared__ float2 Xs[256][17];
    __shared__ float2 Ws[256];
    int bc = blockIdx.y;
    int v0 = blockIdx.x * 16;
    int tx = threadIdx.x;
    int ty = threadIdx.y;
    int t = ty * 16 + tx;
    const float2* inp = in + (size_t)bc * 65536 + v0;
    float2* outp = out + (size_t)bc * 65536 + v0;

    {
        float2 w = d_W256[t];
        if (INV) w.y = -w.y;
        Ws[t] = w;
    }
#pragma unroll
    for (int i = 0; i < 16; i++) {
        int h = i * 16 + ty;
        Xs[h][tx] = inp[(size_t)h * 256 + tx];
    }
    __syncthreads();

    float2 rr[16];
    {
        u64 tw[16];
#pragma unroll
        for (int n1 = 0; n1 < 16; n1++) {
            float2 w = Ws[(n1 * ty * 16) & 255];
            tw[n1] = pk2(w.x, w.y);
        }
#pragma unroll
        for (int n2 = 0; n2 < 16; n2++) {
            u64 accA = 0ull, accB = 0ull;
#pragma unroll
            for (int n1 = 0; n1 < 16; n1++) {
                float2 xv = Xs[16 * n1 + n2][tx];
                u64 xp = pk2(xv.x, xv.y);
                u64 xq = pk2(xv.y, xv.x);
                accA = ffma2(xp, tw[n1], accA);
                accB = ffma2(xq, tw[n1], accB);
            }
            float2 a = up2(accA), b = up2(accB);
            float ar = a.x - a.y, ai = b.x + b.y;
            float2 tm = Ws[(n2 * ty) & 255];
            rr[n2] = make_float2(ar * tm.x - ai * tm.y, ar * tm.y + ai * tm.x);
        }
    }
    __syncthreads();
#pragma unroll
    for (int n2 = 0; n2 < 16; n2++)
        Xs[ty * 16 + n2][tx] = rr[n2];
    __syncthreads();

    {
        u64 tw[16];
#pragma unroll
        for (int n2 = 0; n2 < 16; n2++) {
            float2 w = Ws[(n2 * ty * 16) & 255];
            tw[n2] = pk2(w.x, w.y);
        }
        int c = bc & (Cc - 1);
#pragma unroll
        for (int k1 = 0; k1 < 16; k1++) {
            u64 accA = 0ull, accB = 0ull;
#pragma unroll
            for (int n2 = 0; n2 < 16; n2++) {
                float2 xv = Xs[k1 * 16 + n2][tx];
                u64 xp = pk2(xv.x, xv.y);
                u64 xq = pk2(xv.y, xv.x);
                accA = ffma2(xp, tw[n2], accA);
                accB = ffma2(xq, tw[n2], accB);
            }
            float2 a = up2(accA), b = up2(accB);
            int u = k1 + 16 * ty;
            float2 v = make_float2((a.x - a.y) * 0.0625f, (b.x + b.y) * 0.0625f);
            if (FILT) {
                float2 wc = filt[((size_t)c * Hh + u) * WFD + v0 + tx];
                v = make_float2(v.x * wc.x - v.y * wc.y, v.x * wc.y + v.y * wc.x);
            }
            outp[(size_t)u * 256 + tx] = v;
        }
    }
}

// ------- variance over v per (bc,u) row -------
__global__ void var_kernel(const float2* __restrict__ G, float* __restrict__ rsq)
{
    __shared__ float s0[256], s1[256], s2[256];
    int row = blockIdx.x;
    int tid = threadIdx.x;
    float2 z = G[(size_t)row * WFD + tid];
    s0[tid] = z.x; s1[tid] = z.y; s2[tid] = z.x * z.x + z.y * z.y;
    __syncthreads();
    for (int s = 128; s > 0; s >>= 1) {
        if (tid < s) { s0[tid] += s0[tid + s]; s1[tid] += s1[tid + s]; s2[tid] += s2[tid + s]; }
        __syncthreads();
    }
    if (tid == 0) {
        float mr = s0[0] * (1.f / WFD), mi = s1[0] * (1.f / WFD);
        float var = s2[0] * (1.f / WFD) - (mr * mr + mi * mi);
        rsq[row] = 1.f / sqrtf(6.283185307179586f * var);
    }
}

// ------- scores (FFMA2 SIMT) -------
__global__ void __launch_bounds__(256) scores_kernel(
    const float2* __restrict__ Gb, const float2* __restrict__ Xb,
    const float* __restrict__ rsq, float2* __restrict__ Sb)
{
    int bc = blockIdx.z;
    const float2* Ap = Gb + (size_t)bc * 65536;
    const float2* Bp = Xb + (size_t)bc * 65536;
    float2* Cp = Sb + (size_t)bc * 65536;
    int n0 = blockIdx.x * 64, m0 = blockIdx.y * 64;
    __shared__ float2 As[16][66];
    __shared__ float2 Bs[16][66];
    int tx = threadIdx.x, ty = threadIdx.y, t = ty * 16 + tx;
    u64 accA[4][4], accB[4][4];
#pragma unroll
    for (int i = 0; i < 4; i++)
#pragma unroll
        for (int j = 0; j < 4; j++) { accA[i][j] = 0ull; accB[i][j] = 0ull; }

    for (int k0 = 0; k0 < 256; k0 += 16) {
        int nb = t & 63, kb = t >> 6;
#pragma unroll
        for (int i = 0; i < 4; i++) {
            int k = kb + i * 4;
            As[k][nb] = Ap[(size_t)(k0 + k) * 256 + m0 + nb];
            Bs[k][nb] = Bp[(size_t)(k0 + k) * 256 + n0 + nb];
        }
        __syncthreads();
#pragma unroll
        for (int kk = 0; kk < 16; kk++) {
            u64 ap[4], aq[4], bp[4];
#pragma unroll
            for (int i = 0; i < 4; i++) {
                float2 a = As[kk][i * 16 + ty];
                ap[i] = pk2(a.x, a.y);
                aq[i] = pk2(a.y, a.x);
            }
#pragma unroll
            for (int j = 0; j < 4; j++) bp[j] = *(const u64*)&Bs[kk][j * 16 + tx];
#pragma unroll
            for (int i = 0; i < 4; i++)
#pragma unroll
                for (int j = 0; j < 4; j++) {
                    accA[i][j] = ffma2(ap[i], bp[j], accA[i][j]);
                    accB[i][j] = ffma2(aq[i], bp[j], accB[i][j]);
                }
        }
        __syncthreads();
    }
#pragma unroll
    for (int i = 0; i < 4; i++) {
        int m = m0 + i * 16 + ty;
        float sc = rsq[bc * Hh + m];
#pragma unroll
        for (int j = 0; j < 4; j++) {
            int n = n0 + j * 16 + tx;
            float2 va = up2(accA[i][j]), vb = up2(accB[i][j]);
            float2 v = make_float2(sigm((va.x - va.y) * sc), sigm((vb.x + vb.y) * sc));
            Cp[(size_t)m * 256 + n] = v;
        }
    }
}

// ------- channel LayerNorm -------
__global__ void ln_kernel(const float* __restrict__ r, const float* __restrict__ gamma,
                          const float* __restrict__ beta, float* __restrict__ out)
{
    int p = blockIdx.x * 256 + threadIdx.x;
    int b = p / HWD;
    int hw = p - b * HWD;
    size_t base = (size_t)b * Cc * HWD + hw;
    float sum = 0.f, sq = 0.f;
    for (int c = 0; c < Cc; c++) {
        float v = r[base + (size_t)c * HWD];
        sum += v; sq += v * v;
    }
    float mu = sum * (1.f / Cc);
    float var = sq * (1.f / Cc) - mu * mu;
    float inv = 1.f / sqrtf(var + 1e-6f);
    for (int c = 0; c < Cc; c++) {
        float v = r[base + (size_t)c * HWD];
        out[base + (size_t)c * HWD] = gamma[c] * (v - mu) * inv + beta[c];
    }
}

// ---------------- launch ----------------
extern "C" void kernel_launch(void* const* d_in, const int* in_sizes, int n_in,
                              void* d_out, int out_size)
{
    (void)in_sizes; (void)n_in; (void)out_size;
    const float*  g     = (const float*)d_in[0];
    const float*  x     = (const float*)d_in[1];
    const float*  wg    = (const float*)d_in[2];
    const float*  bg    = (const float*)d_in[3];
    const float*  wx    = (const float*)d_in[4];
    const float*  bx    = (const float*)d_in[5];
    const float2* fg    = (const float2*)d_in[6];
    const float2* fx    = (const float2*)d_in[7];
    const float*  gamma = (const float*)d_in[8];
    const float*  beta  = (const float*)d_in[9];
    float* out = (float*)d_out;

    float *yg, *yx, *rb, *rsq;
    float2 *Fg, *Fx, *Gg, *Gx, *S, *T;
    cudaGetSymbolAddress((void**)&yg,  d_yg);
    cudaGetSymbolAddress((void**)&yx,  d_yx);
    cudaGetSymbolAddress((void**)&Fg,  d_Fg);
    cudaGetSymbolAddress((void**)&Fx,  d_Fx);
    cudaGetSymbolAddress((void**)&Gg,  d_Gg);
    cudaGetSymbolAddress((void**)&Gx,  d_Gx);
    cudaGetSymbolAddress((void**)&S,   d_Sb);
    cudaGetSymbolAddress((void**)&T,   d_Tb);
    cudaGetSymbolAddress((void**)&rb,  d_rb);
    cudaGetSymbolAddress((void**)&rsq, d_rsq);

    dim3 blk(16, 16);

    build_tables_kernel<<<256, 256>>>();

    conv_kernel<<<dim3(HWD / 64, 2, Bb), blk>>>(g, wg, bg, yg);
    conv_kernel<<<dim3(HWD / 64, 2, Bb), blk>>>(x, wx, bx, yx);

    rfftw_tc<<<dim3(4, 4, BCD), 256>>>(yg, Fg);
    rfftw_tc<<<dim3(4, 4, BCD), 256>>>(yx, Fx);

    ffth_kernel<0, 1><<<dim3(16, BCD), blk>>>(Fg, Gg, fg);
    ffth_kernel<0, 1><<<dim3(16, BCD), blk>>>(Fx, Gx, fx);

    var_kernel<<<BCD * Hh, 256>>>(Gg, rsq);

    scores_kernel<<<dim3(4, 4, BCD), blk>>>(Gg, Gx, rsq, S);

    ffth_kernel<1, 0><<<dim3(16, BCD), blk>>>(S, T, nullptr);

    irfft_add_tc<<<dim3(8, 4, BCD), 256>>>(T, x, rb);

    ln_kernel<<<Bb * HWD / 256, 256>>>(rb, gamma, beta, out);
}

// round 6
// speedup vs baseline: 2.3684x; 1.2157x over previous
#include <cuda_runtime.h>
#include <cuda_bf16.h>
#include <math.h>

#define Bb  2
#define Cc  128
#define Hh  256
#define Ww  510
#define WFD 256
#define HWD 130560   /* 256*510 */
#define BCD 256      /* Bb*Cc */

typedef unsigned int u32;
typedef unsigned long long u64;

__device__ __forceinline__ u64 pk2(float lo, float hi) {
    u64 r; asm("mov.b64 %0,{%1,%2};" : "=l"(r) : "f"(lo), "f"(hi)); return r;
}
__device__ __forceinline__ float2 up2(u64 v) {
    float2 r; asm("mov.b64 {%0,%1},%2;" : "=f"(r.x), "=f"(r.y) : "l"(v)); return r;
}
__device__ __forceinline__ u64 ffma2(u64 a, u64 b, u64 c) {
    u64 d; asm("fma.rn.f32x2 %0,%1,%2,%3;" : "=l"(d) : "l"(a), "l"(b), "l"(c)); return d;
}

// ---- tensor-core helpers -------------------------------------------------
__device__ __forceinline__ void mma_bf16(float* c, const u32* a, const u32* b) {
    asm("mma.sync.aligned.m16n8k16.row.col.f32.bf16.bf16.f32 "
        "{%0,%1,%2,%3},{%4,%5,%6,%7},{%8,%9},{%0,%1,%2,%3};"
        : "+f"(c[0]), "+f"(c[1]), "+f"(c[2]), "+f"(c[3])
        : "r"(a[0]), "r"(a[1]), "r"(a[2]), "r"(a[3]), "r"(b[0]), "r"(b[1]));
}
__device__ __forceinline__ void ldmA(u32* a, u32 addr) {
    asm volatile("ldmatrix.sync.aligned.m8n8.x4.shared.b16 {%0,%1,%2,%3},[%4];"
        : "=r"(a[0]), "=r"(a[1]), "=r"(a[2]), "=r"(a[3]) : "r"(addr));
}
__device__ __forceinline__ void ldmAT(u32* a, u32 addr) {
    asm volatile("ldmatrix.sync.aligned.m8n8.x4.trans.shared.b16 {%0,%1,%2,%3},[%4];"
        : "=r"(a[0]), "=r"(a[1]), "=r"(a[2]), "=r"(a[3]) : "r"(addr));
}
__device__ __forceinline__ void ldmB(u32* b, u32 addr) {
    asm volatile("ldmatrix.sync.aligned.m8n8.x2.shared.b16 {%0,%1},[%2];"
        : "=r"(b[0]), "=r"(b[1]) : "r"(addr));
}
__device__ __forceinline__ void ldmBT(u32* b, u32 addr) {
    asm volatile("ldmatrix.sync.aligned.m8n8.x2.trans.shared.b16 {%0,%1},[%2];"
        : "=r"(b[0]), "=r"(b[1]) : "r"(addr));
}
__device__ __forceinline__ u32 smaddr(const void* p) {
    return (u32)__cvta_generic_to_shared(p);
}
__device__ __forceinline__ void bsplit2(float a, float b, u32& hi, u32& lo) {
    __nv_bfloat16 ha = __float2bfloat16(a), hb = __float2bfloat16(b);
    hi = (u32)__bfloat16_as_ushort(ha) | ((u32)__bfloat16_as_ushort(hb) << 16);
    float ra = a - __bfloat162float(ha), rb = b - __bfloat162float(hb);
    __nv_bfloat16 la = __float2bfloat16(ra), lb = __float2bfloat16(rb);
    lo = (u32)__bfloat16_as_ushort(la) | ((u32)__bfloat16_as_ushort(lb) << 16);
}

// ---------------- scratch ----------------
__device__ float  d_yg [(size_t)BCD * HWD];
__device__ float  d_yx [(size_t)BCD * HWD];
__device__ float2 d_Fg [(size_t)BCD * Hh * WFD];
__device__ float2 d_Fx [(size_t)BCD * Hh * WFD];
__device__ float2 d_Gg [(size_t)BCD * Hh * WFD];
__device__ float2 d_Gx [(size_t)BCD * Hh * WFD];
__device__ float2 d_Sb [(size_t)BCD * WFD * WFD];
__device__ float2 d_Tb [(size_t)BCD * Hh * WFD];
__device__ float  d_rb [(size_t)BCD * HWD];
__device__ float  d_rsq[BCD * Hh];
__device__ float2 d_W256[256];
__device__ __nv_bfloat16 d_DwTreh[256 * 512];
__device__ __nv_bfloat16 d_DwTrel[256 * 512];
__device__ __nv_bfloat16 d_DwTimh[256 * 512];
__device__ __nv_bfloat16 d_DwTiml[256 * 512];
__device__ __nv_bfloat16 d_CwT1h [512 * 256];
__device__ __nv_bfloat16 d_CwT1l [512 * 256];
__device__ __nv_bfloat16 d_CwT2h [512 * 256];
__device__ __nv_bfloat16 d_CwT2l [512 * 256];

// ---------------- table builder ----------------
__global__ void build_tables_kernel() {
    int idx = blockIdx.x * blockDim.x + threadIdx.x;
    int stride = gridDim.x * blockDim.x;
    float rsW = rsqrtf(510.0f);

    for (int i = idx; i < 256 * 512; i += stride) {
        int v = i >> 9, w = i & 511;
        float re = 0.f, im = 0.f;
        if (w < Ww) {
            int m = (int)(((long long)w * v) % Ww);
            float s, c; sincospif(2.0f * (float)m / (float)Ww, &s, &c);
            re = c * rsW; im = -s * rsW;
        }
        __nv_bfloat16 h = __float2bfloat16(re);
        d_DwTreh[i] = h;
        d_DwTrel[i] = __float2bfloat16(re - __bfloat162float(h));
        h = __float2bfloat16(im);
        d_DwTimh[i] = h;
        d_DwTiml[i] = __float2bfloat16(im - __bfloat162float(h));
    }
    for (int i = idx; i < 512 * 256; i += stride) {
        int w = i >> 8, v = i & 255;
        float b1 = 0.f, b2 = 0.f;
        if (w < Ww) {
            int m = (int)(((long long)v * w) % Ww);
            float s, c; sincospif(2.0f * (float)m / (float)Ww, &s, &c);
            float sv = (v == 0 || v == 255) ? 1.0f : 2.0f;
            b1 = sv * c * rsW; b2 = -sv * s * rsW;
        }
        __nv_bfloat16 h = __float2bfloat16(b1);
        d_CwT1h[i] = h;
        d_CwT1l[i] = __float2bfloat16(b1 - __bfloat162float(h));
        h = __float2bfloat16(b2);
        d_CwT2h[i] = h;
        d_CwT2l[i] = __float2bfloat16(b2 - __bfloat162float(h));
    }
    for (int j = idx; j < 256; j += stride) {
        float s, c; sincospif(2.0f * (float)j / 256.0f, &s, &c);
        d_W256[j] = make_float2(c, -s);
    }
}

__device__ __forceinline__ float sigm(float v) { return 1.f / (1.f + expf(-v)); }

#define PIT  40   // pitch for [row][k32] tiles
#define PITS 72   // pitch for [k32][col64] tiles (trans loads)

// ---------------- 1x1 conv — TENSOR CORE ----------------
__global__ void __launch_bounds__(256) conv_tc(
    const float* __restrict__ X, const float* __restrict__ Wm,
    const float* __restrict__ bias, float* __restrict__ Y)
{
    __shared__ __nv_bfloat16 sWh[64 * PIT], sWl[64 * PIT];
    __shared__ __nv_bfloat16 sXh[32 * PITS], sXl[32 * PITS];
    int b = blockIdx.z;
    const float* Xb = X + (size_t)b * Cc * HWD;
    float* Yb = Y + (size_t)b * Cc * HWD;
    int n0 = blockIdx.x * 64, m0 = blockIdx.y * 64;
    int t = threadIdx.x, lane = t & 31, wid = t >> 5;
    int wm = (wid >> 2) * 32, wn = (wid & 3) * 16;
    int g = lane >> 2, tc4 = lane & 3;

    float acc[2][2][4];
#pragma unroll
    for (int i = 0; i < 2; i++)
#pragma unroll
        for (int j = 0; j < 2; j++)
#pragma unroll
            for (int q = 0; q < 4; q++) acc[i][j][q] = 0.f;

    int lrA = lane & 15, lkA = (lane >> 4) * 8;
    int kB = (lane & 7) + ((lane >> 3) & 1) * 8;

    int scA = t & 15, srA = t >> 4;        // W staging: k-pair, m-row
    int scB = t & 31, srB = t >> 5;        // X staging: n-pair, k-row
    for (int k0 = 0; k0 < 128; k0 += 32) {
#pragma unroll
        for (int i = 0; i < 4; i++) {
            int m = srA + i * 16;
            float2 wv = *(const float2*)&Wm[(m0 + m) * Cc + k0 + 2 * scA];
            u32 hi, lo; bsplit2(wv.x, wv.y, hi, lo);
            *(u32*)&sWh[m * PIT + 2 * scA] = hi;
            *(u32*)&sWl[m * PIT + 2 * scA] = lo;
        }
#pragma unroll
        for (int i = 0; i < 4; i++) {
            int k = srB + i * 8;
            float2 xv = *(const float2*)&Xb[(size_t)(k0 + k) * HWD + n0 + 2 * scB];
            u32 hi, lo; bsplit2(xv.x, xv.y, hi, lo);
            *(u32*)&sXh[k * PITS + 2 * scB] = hi;
            *(u32*)&sXl[k * PITS + 2 * scB] = lo;
        }
        __syncthreads();
#pragma unroll
        for (int ks = 0; ks < 2; ks++) {
            int kb = ks * 16;
            u32 ah[2][4], al[2][4];
#pragma unroll
            for (int tm = 0; tm < 2; tm++) {
                u32 off = ((wm + 16 * tm + lrA) * PIT + kb + lkA) * 2;
                ldmA(ah[tm], smaddr(sWh) + off);
                ldmA(al[tm], smaddr(sWl) + off);
            }
            u32 bh[2][2], bl[2][2];
#pragma unroll
            for (int tn = 0; tn < 2; tn++) {
                u32 off = ((kb + kB) * PITS + wn + 8 * tn) * 2;
                ldmBT(bh[tn], smaddr(sXh) + off);
                ldmBT(bl[tn], smaddr(sXl) + off);
            }
#pragma unroll
            for (int tm = 0; tm < 2; tm++)
#pragma unroll
                for (int tn = 0; tn < 2; tn++) {
                    mma_bf16(acc[tm][tn], ah[tm], bh[tn]);
                    mma_bf16(acc[tm][tn], ah[tm], bl[tn]);
                    mma_bf16(acc[tm][tn], al[tm], bh[tn]);
                }
        }
        __syncthreads();
    }
#pragma unroll
    for (int tm = 0; tm < 2; tm++)
#pragma unroll
        for (int tn = 0; tn < 2; tn++) {
            int r0 = m0 + wm + 16 * tm + g;
            int col = n0 + wn + 8 * tn + 2 * tc4;
            float bv0 = bias[r0], bv1 = bias[r0 + 8];
            *(float2*)&Yb[(size_t)r0 * HWD + col] =
                make_float2(acc[tm][tn][0] + bv0, acc[tm][tn][1] + bv0);
            *(float2*)&Yb[(size_t)(r0 + 8) * HWD + col] =
                make_float2(acc[tm][tn][2] + bv1, acc[tm][tn][3] + bv1);
        }
}

// ---------------- rfft along W — TENSOR CORE (bf16 3-split) ----------------
__global__ void __launch_bounds__(256) rfftw_tc(
    const float* __restrict__ Y, float2* __restrict__ F)
{
    __shared__ __nv_bfloat16 sAh[64 * PIT], sAl[64 * PIT];
    __shared__ __nv_bfloat16 sBrh[64 * PIT], sBrl[64 * PIT], sBih[64 * PIT], sBil[64 * PIT];
    int bc = blockIdx.z;
    const float* A = Y + (size_t)bc * HWD;
    float2* Cp = F + (size_t)bc * Hh * WFD;
    int n0 = blockIdx.x * 64, m0 = blockIdx.y * 64;
    int t = threadIdx.x, lane = t & 31, wid = t >> 5;
    int wm = (wid >> 2) * 32, wn = (wid & 3) * 16;
    int g = lane >> 2, tc = lane & 3;

    float cre[2][2][4], cim[2][2][4];
#pragma unroll
    for (int i = 0; i < 2; i++)
#pragma unroll
        for (int j = 0; j < 2; j++)
#pragma unroll
            for (int q = 0; q < 4; q++) { cre[i][j][q] = 0.f; cim[i][j][q] = 0.f; }

    u32 aAh = smaddr(sAh), aAl = smaddr(sAl);
    u32 aBrh = smaddr(sBrh), aBrl = smaddr(sBrl), aBih = smaddr(sBih), aBil = smaddr(sBil);
    int lrA = lane & 15, lkA = (lane >> 4) * 8;
    int lrB = lane & 7,  lkB = ((lane >> 3) & 1) * 8;

    int sc = t & 15, sr = t >> 4;
    for (int k0 = 0; k0 < 512; k0 += 32) {
#pragma unroll
        for (int i = 0; i < 4; i++) {
            int r = sr + i * 16;
            int w = k0 + 2 * sc;
            const float* row = A + (size_t)(m0 + r) * Ww;
            float a0 = (w < Ww) ? row[w] : 0.f;
            float a1 = (w + 1 < Ww) ? row[w + 1] : 0.f;
            u32 hi, lo; bsplit2(a0, a1, hi, lo);
            *(u32*)&sAh[r * PIT + 2 * sc] = hi;
            *(u32*)&sAl[r * PIT + 2 * sc] = lo;
        }
#pragma unroll
        for (int i = 0; i < 4; i++) {
            int r = sr + i * 16;
            size_t gi = (size_t)(n0 + r) * 512 + k0 + 2 * sc;
            int so = r * PIT + 2 * sc;
            *(u32*)&sBrh[so] = *(const u32*)&d_DwTreh[gi];
            *(u32*)&sBrl[so] = *(const u32*)&d_DwTrel[gi];
            *(u32*)&sBih[so] = *(const u32*)&d_DwTimh[gi];
            *(u32*)&sBil[so] = *(const u32*)&d_DwTiml[gi];
        }
        __syncthreads();
#pragma unroll
        for (int ks = 0; ks < 2; ks++) {
            int kb = ks * 16;
            u32 ah[2][4], al[2][4];
#pragma unroll
            for (int tm = 0; tm < 2; tm++) {
                u32 off = ((wm + 16 * tm + lrA) * PIT + kb + lkA) * 2;
                ldmA(ah[tm], aAh + off);
                ldmA(al[tm], aAl + off);
            }
            u32 brh[2][2], brl[2][2], bih[2][2], bil[2][2];
#pragma unroll
            for (int tn = 0; tn < 2; tn++) {
                u32 off = ((wn + 8 * tn + lrB) * PIT + kb + lkB) * 2;
                ldmB(brh[tn], aBrh + off);
                ldmB(brl[tn], aBrl + off);
                ldmB(bih[tn], aBih + off);
                ldmB(bil[tn], aBil + off);
            }
#pragma unroll
            for (int tm = 0; tm < 2; tm++)
#pragma unroll
                for (int tn = 0; tn < 2; tn++) {
                    mma_bf16(cre[tm][tn], ah[tm], brh[tn]);
                    mma_bf16(cre[tm][tn], ah[tm], brl[tn]);
                    mma_bf16(cre[tm][tn], al[tm], brh[tn]);
                    mma_bf16(cim[tm][tn], ah[tm], bih[tn]);
                    mma_bf16(cim[tm][tn], ah[tm], bil[tn]);
                    mma_bf16(cim[tm][tn], al[tm], bih[tn]);
                }
        }
        __syncthreads();
    }
#pragma unroll
    for (int tm = 0; tm < 2; tm++)
#pragma unroll
        for (int tn = 0; tn < 2; tn++) {
            int r0 = m0 + wm + 16 * tm + g;
            int col = n0 + wn + 8 * tn + 2 * tc;
            float4 v0 = make_float4(cre[tm][tn][0], cim[tm][tn][0], cre[tm][tn][1], cim[tm][tn][1]);
            *(float4*)&Cp[(size_t)r0 * WFD + col] = v0;
            float4 v1 = make_float4(cre[tm][tn][2], cim[tm][tn][2], cre[tm][tn][3], cim[tm][tn][3]);
            *(float4*)&Cp[(size_t)(r0 + 8) * WFD + col] = v1;
        }
}

// ------- irfft along W + residual — TENSOR CORE ----
__global__ void __launch_bounds__(256) irfft_add_tc(
    const float2* __restrict__ T, const float* __restrict__ x, float* __restrict__ r)
{
    __shared__ __nv_bfloat16 sArh[64 * PIT], sArl[64 * PIT], sAih[64 * PIT], sAil[64 * PIT];
    __shared__ __nv_bfloat16 sB1h[64 * PIT], sB1l[64 * PIT], sB2h[64 * PIT], sB2l[64 * PIT];
    int bc = blockIdx.z;
    const float2* Ap = T + (size_t)bc * 65536;
    int n0 = blockIdx.x * 64, m0 = blockIdx.y * 64;
    int t = threadIdx.x, lane = t & 31, wid = t >> 5;
    int wm = (wid >> 2) * 32, wn = (wid & 3) * 16;
    int g = lane >> 2, tc = lane & 3;

    float acc[2][2][4];
#pragma unroll
    for (int i = 0; i < 2; i++)
#pragma unroll
        for (int j = 0; j < 2; j++)
#pragma unroll
            for (int q = 0; q < 4; q++) acc[i][j][q] = 0.f;

    u32 aArh = smaddr(sArh), aArl = smaddr(sArl), aAih = smaddr(sAih), aAil = smaddr(sAil);
    u32 aB1h = smaddr(sB1h), aB1l = smaddr(sB1l), aB2h = smaddr(sB2h), aB2l = smaddr(sB2l);
    int lrA = lane & 15, lkA = (lane >> 4) * 8;
    int lrB = lane & 7,  lkB = ((lane >> 3) & 1) * 8;

    int sc = t & 15, sr = t >> 4;
    for (int k0 = 0; k0 < 256; k0 += 32) {
#pragma unroll
        for (int i = 0; i < 4; i++) {
            int rr = sr + i * 16;
            float4 v = *(const float4*)&Ap[(size_t)(m0 + rr) * 256 + k0 + 2 * sc];
            u32 hi, lo;
            int so = rr * PIT + 2 * sc;
            bsplit2(v.x, v.z, hi, lo);
            *(u32*)&sArh[so] = hi; *(u32*)&sArl[so] = lo;
            bsplit2(v.y, v.w, hi, lo);
            *(u32*)&sAih[so] = hi; *(u32*)&sAil[so] = lo;
        }
#pragma unroll
        for (int i = 0; i < 4; i++) {
            int rr = sr + i * 16;
            size_t gi = (size_t)(n0 + rr) * 256 + k0 + 2 * sc;
            int so = rr * PIT + 2 * sc;
            *(u32*)&sB1h[so] = *(const u32*)&d_CwT1h[gi];
            *(u32*)&sB1l[so] = *(const u32*)&d_CwT1l[gi];
            *(u32*)&sB2h[so] = *(const u32*)&d_CwT2h[gi];
            *(u32*)&sB2l[so] = *(const u32*)&d_CwT2l[gi];
        }
        __syncthreads();
#pragma unroll
        for (int ks = 0; ks < 2; ks++) {
            int kb = ks * 16;
            u32 arh[2][4], arl[2][4], aih[2][4], ail[2][4];
#pragma unroll
            for (int tm = 0; tm < 2; tm++) {
                u32 off = ((wm + 16 * tm + lrA) * PIT + kb + lkA) * 2;
                ldmA(arh[tm], aArh + off);
                ldmA(arl[tm], aArl + off);
                ldmA(aih[tm], aAih + off);
                ldmA(ail[tm], aAil + off);
            }
            u32 b1h[2][2], b1l[2][2], b2h[2][2], b2l[2][2];
#pragma unroll
            for (int tn = 0; tn < 2; tn++) {
                u32 off = ((wn + 8 * tn + lrB) * PIT + kb + lkB) * 2;
                ldmB(b1h[tn], aB1h + off);
                ldmB(b1l[tn], aB1l + off);
                ldmB(b2h[tn], aB2h + off);
                ldmB(b2l[tn], aB2l + off);
            }
#pragma unroll
            for (int tm = 0; tm < 2; tm++)
#pragma unroll
                for (int tn = 0; tn < 2; tn++) {
                    mma_bf16(acc[tm][tn], arh[tm], b1h[tn]);
                    mma_bf16(acc[tm][tn], arh[tm], b1l[tn]);
                    mma_bf16(acc[tm][tn], arl[tm], b1h[tn]);
                    mma_bf16(acc[tm][tn], aih[tm], b2h[tn]);
                    mma_bf16(acc[tm][tn], aih[tm], b2l[tn]);
                    mma_bf16(acc[tm][tn], ail[tm], b2h[tn]);
                }
        }
        __syncthreads();
    }
#pragma unroll
    for (int tm = 0; tm < 2; tm++)
#pragma unroll
        for (int tn = 0; tn < 2; tn++) {
            int col = n0 + wn + 8 * tn + 2 * tc;
            if (col < Ww) {
                int r0 = m0 + wm + 16 * tm + g;
                size_t i0 = (size_t)bc * HWD + (size_t)r0 * Ww + col;
                size_t i1 = i0 + (size_t)8 * Ww;
                float2 xv = *(const float2*)&x[i0];
                *(float2*)&r[i0] = make_float2(acc[tm][tn][0] + xv.x, acc[tm][tn][1] + xv.y);
                xv = *(const float2*)&x[i1];
                *(float2*)&r[i1] = make_float2(acc[tm][tn][2] + xv.x, acc[tm][tn][3] + xv.y);
            }
        }
}

// ---------------- 256-pt FFT along slow axis (4-step 16x16) ----------------
template<int INV, int FILT>
__global__ void __launch_bounds__(256) ffth_kernel(
    const float2* __restrict__ in, float2* __restrict__ out,
    const float2* __restrict__ filt)
{
    __shared__ float2 Xs[256][17];
    __shared__ float2 Ws[256];
    int bc = blockIdx.y;
    int v0 = blockIdx.x * 16;
    int tx = threadIdx.x;
    int ty = threadIdx.y;
    int t = ty * 16 + tx;
    const float2* inp = in + (size_t)bc * 65536 + v0;
    float2* outp = out + (size_t)bc * 65536 + v0;

    {
        float2 w = d_W256[t];
        if (INV) w.y = -w.y;
        Ws[t] = w;
    }
#pragma unroll
    for (int i = 0; i < 16; i++) {
        int h = i * 16 + ty;
        Xs[h][tx] = inp[(size_t)h * 256 + tx];
    }
    __syncthreads();

    float2 rr[16];
    {
        u64 tw[16];
#pragma unroll
        for (int n1 = 0; n1 < 16; n1++) {
            float2 w = Ws[(n1 * ty * 16) & 255];
            tw[n1] = pk2(w.x, w.y);
        }
#pragma unroll
        for (int n2 = 0; n2 < 16; n2++) {
            u64 accA = 0ull, accB = 0ull;
#pragma unroll
            for (int n1 = 0; n1 < 16; n1++) {
                float2 xv = Xs[16 * n1 + n2][tx];
                u64 xp = pk2(xv.x, xv.y);
                u64 xq = pk2(xv.y, xv.x);
                accA = ffma2(xp, tw[n1], accA);
                accB = ffma2(xq, tw[n1], accB);
            }
            float2 a = up2(accA), b = up2(accB);
            float ar = a.x - a.y, ai = b.x + b.y;
            float2 tm = Ws[(n2 * ty) & 255];
            rr[n2] = make_float2(ar * tm.x - ai * tm.y, ar * tm.y + ai * tm.x);
        }
    }
    __syncthreads();
#pragma unroll
    for (int n2 = 0; n2 < 16; n2++)
        Xs[ty * 16 + n2][tx] = rr[n2];
    __syncthreads();

    {
        u64 tw[16];
#pragma unroll
        for (int n2 = 0; n2 < 16; n2++) {
            float2 w = Ws[(n2 * ty * 16) & 255];
            tw[n2] = pk2(w.x, w.y);
        }
        int c = bc & (Cc - 1);
#pragma unroll
        for (int k1 = 0; k1 < 16; k1++) {
            u64 accA = 0ull, accB = 0ull;
#pragma unroll
            for (int n2 = 0; n2 < 16; n2++) {
                float2 xv = Xs[k1 * 16 + n2][tx];
                u64 xp = pk2(xv.x, xv.y);
                u64 xq = pk2(xv.y, xv.x);
                accA = ffma2(xp, tw[n2], accA);
                accB = ffma2(xq, tw[n2], accB);
            }
            float2 a = up2(accA), b = up2(accB);
            int u = k1 + 16 * ty;
            float2 v = make_float2((a.x - a.y) * 0.0625f, (b.x + b.y) * 0.0625f);
            if (FILT) {
                float2 wc = filt[((size_t)c * Hh + u) * WFD + v0 + tx];
                v = make_float2(v.x * wc.x - v.y * wc.y, v.x * wc.y + v.y * wc.x);
            }
            outp[(size_t)u * 256 + tx] = v;
        }
    }
}

// ------- variance over v per (bc,u) row -------
__global__ void var_kernel(const float2* __restrict__ G, float* __restrict__ rsq)
{
    __shared__ float s0[256], s1[256], s2[256];
    int row = blockIdx.x;
    int tid = threadIdx.x;
    float2 z = G[(size_t)row * WFD + tid];
    s0[tid] = z.x; s1[tid] = z.y; s2[tid] = z.x * z.x + z.y * z.y;
    __syncthreads();
    for (int s = 128; s > 0; s >>= 1) {
        if (tid < s) { s0[tid] += s0[tid + s]; s1[tid] += s1[tid + s]; s2[tid] += s2[tid + s]; }
        __syncthreads();
    }
    if (tid == 0) {
        float mr = s0[0] * (1.f / WFD), mi = s1[0] * (1.f / WFD);
        float var = s2[0] * (1.f / WFD) - (mr * mr + mi * mi);
        rsq[row] = 1.f / sqrtf(6.283185307179586f * var);
    }
}

// ------- scores — TENSOR CORE (complex, trans-ldmatrix, bf16 3-split) -------
__global__ void __launch_bounds__(256) scores_tc(
    const float2* __restrict__ Gb, const float2* __restrict__ Xb,
    const float* __restrict__ rsq, float2* __restrict__ Sb)
{
    __shared__ __nv_bfloat16 sGrh[32 * PITS], sGrl[32 * PITS], sGih[32 * PITS], sGil[32 * PITS];
    __shared__ __nv_bfloat16 sXrh[32 * PITS], sXrl[32 * PITS], sXih[32 * PITS], sXil[32 * PITS];
    int bc = blockIdx.z;
    const float2* Ap = Gb + (size_t)bc * 65536;
    const float2* Bp = Xb + (size_t)bc * 65536;
    float2* Cp = Sb + (size_t)bc * 65536;
    int n0 = blockIdx.x * 64, m0 = blockIdx.y * 64;
    int t = threadIdx.x, lane = t & 31, wid = t >> 5;
    int wm = (wid >> 2) * 32, wn = (wid & 3) * 16;
    int g = lane >> 2, tc4 = lane & 3;

    float are[2][2][4], aim[2][2][4];
#pragma unroll
    for (int i = 0; i < 2; i++)
#pragma unroll
        for (int j = 0; j < 2; j++)
#pragma unroll
            for (int q = 0; q < 4; q++) { are[i][j][q] = 0.f; aim[i][j][q] = 0.f; }

    // trans ldmatrix addressing: A.x4.trans from [k][m], B.x2.trans from [k][n]
    int kA = (lane & 7) + ((lane >> 4) & 1) * 8;
    int mA = ((lane >> 3) & 1) * 8;
    int kB = (lane & 7) + ((lane >> 3) & 1) * 8;

    int sc = t & 31, sr = t >> 5;
    for (int k0 = 0; k0 < 256; k0 += 32) {
#pragma unroll
        for (int i = 0; i < 4; i++) {
            int k = sr + i * 8;
            int so = k * PITS + 2 * sc;
            float4 v = *(const float4*)&Ap[(size_t)(k0 + k) * 256 + m0 + 2 * sc];
            u32 hi, lo;
            bsplit2(v.x, v.z, hi, lo); *(u32*)&sGrh[so] = hi; *(u32*)&sGrl[so] = lo;
            bsplit2(v.y, v.w, hi, lo); *(u32*)&sGih[so] = hi; *(u32*)&sGil[so] = lo;
            v = *(const float4*)&Bp[(size_t)(k0 + k) * 256 + n0 + 2 * sc];
            bsplit2(v.x, v.z, hi, lo); *(u32*)&sXrh[so] = hi; *(u32*)&sXrl[so] = lo;
            bsplit2(v.y, v.w, hi, lo); *(u32*)&sXih[so] = hi; *(u32*)&sXil[so] = lo;
        }
        __syncthreads();
#pragma unroll
        for (int ks = 0; ks < 2; ks++) {
            int kb = ks * 16;
            u32 grh[2][4], grl[2][4], gih[2][4], gil[2][4];
#pragma unroll
            for (int tm = 0; tm < 2; tm++) {
                u32 off = ((kb + kA) * PITS + wm + 16 * tm + mA) * 2;
                ldmAT(grh[tm], smaddr(sGrh) + off);
                ldmAT(grl[tm], smaddr(sGrl) + off);
                ldmAT(gih[tm], smaddr(sGih) + off);
                ldmAT(gil[tm], smaddr(sGil) + off);
            }
            u32 xrh[2][2], xrl[2][2], xih[2][2], xil[2][2];
#pragma unroll
            for (int tn = 0; tn < 2; tn++) {
                u32 off = ((kb + kB) * PITS + wn + 8 * tn) * 2;
                ldmBT(xrh[tn], smaddr(sXrh) + off);
                ldmBT(xrl[tn], smaddr(sXrl) + off);
                ldmBT(xih[tn], smaddr(sXih) + off);
                ldmBT(xil[tn], smaddr(sXil) + off);
            }
#pragma unroll
            for (int tm = 0; tm < 2; tm++) {
                u32 nih[4], nil_[4];
#pragma unroll
                for (int q = 0; q < 4; q++) {
                    nih[q]  = gih[tm][q] ^ 0x80008000u;
                    nil_[q] = gil[tm][q] ^ 0x80008000u;
                }
#pragma unroll
                for (int tn = 0; tn < 2; tn++) {
                    // re = gr*xr - gi*xi
                    mma_bf16(are[tm][tn], grh[tm], xrh[tn]);
                    mma_bf16(are[tm][tn], grh[tm], xrl[tn]);
                    mma_bf16(are[tm][tn], grl[tm], xrh[tn]);
                    mma_bf16(are[tm][tn], nih,     xih[tn]);
                    mma_bf16(are[tm][tn], nih,     xil[tn]);
                    mma_bf16(are[tm][tn], nil_,    xih[tn]);
                    // im = gr*xi + gi*xr
                    mma_bf16(aim[tm][tn], grh[tm], xih[tn]);
                    mma_bf16(aim[tm][tn], grh[tm], xil[tn]);
                    mma_bf16(aim[tm][tn], grl[tm], xih[tn]);
                    mma_bf16(aim[tm][tn], gih[tm], xrh[tn]);
                    mma_bf16(aim[tm][tn], gih[tm], xrl[tn]);
                    mma_bf16(aim[tm][tn], gil[tm], xrh[tn]);
                }
            }
        }
        __syncthreads();
    }
#pragma unroll
    for (int tm = 0; tm < 2; tm++)
#pragma unroll
        for (int tn = 0; tn < 2; tn++) {
            int r0 = m0 + wm + 16 * tm + g;
            int col = n0 + wn + 8 * tn + 2 * tc4;
            float s0 = rsq[bc * Hh + r0], s1 = rsq[bc * Hh + r0 + 8];
            float4 o0 = make_float4(
                sigm(are[tm][tn][0] * s0), sigm(aim[tm][tn][0] * s0),
                sigm(are[tm][tn][1] * s0), sigm(aim[tm][tn][1] * s0));
            *(float4*)&Cp[(size_t)r0 * 256 + col] = o0;
            float4 o1 = make_float4(
                sigm(are[tm][tn][2] * s1), sigm(aim[tm][tn][2] * s1),
                sigm(are[tm][tn][3] * s1), sigm(aim[tm][tn][3] * s1));
            *(float4*)&Cp[(size_t)(r0 + 8) * 256 + col] = o1;
        }
}

// ------- channel LayerNorm — single-read smem-tiled -------
__global__ void __launch_bounds__(256) ln_kernel(
    const float* __restrict__ r, const float* __restrict__ gamma,
    const float* __restrict__ beta, float* __restrict__ out)
{
    __shared__ float tile[128][64];
    __shared__ float ps[4][64], qs[4][64];
    __shared__ float mu[64], inv[64];
    int blk = blockIdx.x;
    int b = blk / 2040;
    int w0 = (blk - b * 2040) * 64;
    int t = threadIdx.x;
    int wl = t & 63, cq = t >> 6;

#pragma unroll 8
    for (int c0 = 0; c0 < 128; c0 += 4) {
        int c = c0 + cq;
        tile[c][wl] = r[(size_t)(b * Cc + c) * HWD + w0 + wl];
    }
    __syncthreads();
    {
        float s = 0.f, q = 0.f;
#pragma unroll
        for (int c = 0; c < 32; c++) {
            float v = tile[cq * 32 + c][wl];
            s += v; q += v * v;
        }
        ps[cq][wl] = s; qs[cq][wl] = q;
    }
    __syncthreads();
    if (t < 64) {
        float s = ps[0][t] + ps[1][t] + ps[2][t] + ps[3][t];
        float q = qs[0][t] + qs[1][t] + qs[2][t] + qs[3][t];
        float m = s * (1.f / 128.f);
        mu[t] = m;
        inv[t] = rsqrtf(q * (1.f / 128.f) - m * m + 1e-6f);
    }
    __syncthreads();
#pragma unroll 8
    for (int c0 = 0; c0 < 128; c0 += 4) {
        int c = c0 + cq;
        out[(size_t)(b * Cc + c) * HWD + w0 + wl] =
            gamma[c] * (tile[c][wl] - mu[wl]) * inv[wl] + beta[c];
    }
}

// ---------------- launch ----------------
extern "C" void kernel_launch(void* const* d_in, const int* in_sizes, int n_in,
                              void* d_out, int out_size)
{
    (void)in_sizes; (void)n_in; (void)out_size;
    const float*  g     = (const float*)d_in[0];
    const float*  x     = (const float*)d_in[1];
    const float*  wg    = (const float*)d_in[2];
    const float*  bg    = (const float*)d_in[3];
    const float*  wx    = (const float*)d_in[4];
    const float*  bx    = (const float*)d_in[5];
    const float2* fg    = (const float2*)d_in[6];
    const float2* fx    = (const float2*)d_in[7];
    const float*  gamma = (const float*)d_in[8];
    const float*  beta  = (const float*)d_in[9];
    float* out = (float*)d_out;

    float *yg, *yx, *rb, *rsq;
    float2 *Fg, *Fx, *Gg, *Gx, *S, *T;
    cudaGetSymbolAddress((void**)&yg,  d_yg);
    cudaGetSymbolAddress((void**)&yx,  d_yx);
    cudaGetSymbolAddress((void**)&Fg,  d_Fg);
    cudaGetSymbolAddress((void**)&Fx,  d_Fx);
    cudaGetSymbolAddress((void**)&Gg,  d_Gg);
    cudaGetSymbolAddress((void**)&Gx,  d_Gx);
    cudaGetSymbolAddress((void**)&S,   d_Sb);
    cudaGetSymbolAddress((void**)&T,   d_Tb);
    cudaGetSymbolAddress((void**)&rb,  d_rb);
    cudaGetSymbolAddress((void**)&rsq, d_rsq);

    dim3 blk(16, 16);

    build_tables_kernel<<<256, 256>>>();

    conv_tc<<<dim3(HWD / 64, 2, Bb), 256>>>(g, wg, bg, yg);
    conv_tc<<<dim3(HWD / 64, 2, Bb), 256>>>(x, wx, bx, yx);

    rfftw_tc<<<dim3(4, 4, BCD), 256>>>(yg, Fg);
    rfftw_tc<<<dim3(4, 4, BCD), 256>>>(yx, Fx);

    ffth_kernel<0, 1><<<dim3(16, BCD), blk>>>(Fg, Gg, fg);
    ffth_kernel<0, 1><<<dim3(16, BCD), blk>>>(Fx, Gx, fx);

    var_kernel<<<BCD * Hh, 256>>>(Gg, rsq);

    scores_tc<<<dim3(4, 4, BCD), 256>>>(Gg, Gx, rsq, S);

    ffth_kernel<1, 0><<<dim3(16, BCD), blk>>>(S, T, nullptr);

    irfft_add_tc<<<dim3(8, 4, BCD), 256>>>(T, x, rb);

    ln_kernel<<<Bb * 2040, 256>>>(rb, gamma, beta, out);
}

// round 7
// speedup vs baseline: 2.5322x; 1.0692x over previous
#include <cuda_runtime.h>
#include <cuda_bf16.h>
#include <math.h>

#define Bb  2
#define Cc  128
#define Hh  256
#define Ww  510
#define WFD 256
#define HWD 130560   /* 256*510 */
#define BCD 256      /* Bb*Cc */

typedef unsigned int u32;
typedef unsigned long long u64;

__device__ __forceinline__ u64 pk2(float lo, float hi) {
    u64 r; asm("mov.b64 %0,{%1,%2};" : "=l"(r) : "f"(lo), "f"(hi)); return r;
}
__device__ __forceinline__ float2 up2(u64 v) {
    float2 r; asm("mov.b64 {%0,%1},%2;" : "=f"(r.x), "=f"(r.y) : "l"(v)); return r;
}
__device__ __forceinline__ u64 ffma2(u64 a, u64 b, u64 c) {
    u64 d; asm("fma.rn.f32x2 %0,%1,%2,%3;" : "=l"(d) : "l"(a), "l"(b), "l"(c)); return d;
}

// ---- tensor-core helpers -------------------------------------------------
__device__ __forceinline__ void mma_bf16(float* c, const u32* a, const u32* b) {
    asm("mma.sync.aligned.m16n8k16.row.col.f32.bf16.bf16.f32 "
        "{%0,%1,%2,%3},{%4,%5,%6,%7},{%8,%9},{%0,%1,%2,%3};"
        : "+f"(c[0]), "+f"(c[1]), "+f"(c[2]), "+f"(c[3])
        : "r"(a[0]), "r"(a[1]), "r"(a[2]), "r"(a[3]), "r"(b[0]), "r"(b[1]));
}
__device__ __forceinline__ void ldmA(u32* a, u32 addr) {
    asm volatile("ldmatrix.sync.aligned.m8n8.x4.shared.b16 {%0,%1,%2,%3},[%4];"
        : "=r"(a[0]), "=r"(a[1]), "=r"(a[2]), "=r"(a[3]) : "r"(addr));
}
__device__ __forceinline__ void ldmAT(u32* a, u32 addr) {
    asm volatile("ldmatrix.sync.aligned.m8n8.x4.trans.shared.b16 {%0,%1,%2,%3},[%4];"
        : "=r"(a[0]), "=r"(a[1]), "=r"(a[2]), "=r"(a[3]) : "r"(addr));
}
__device__ __forceinline__ void ldmB(u32* b, u32 addr) {
    asm volatile("ldmatrix.sync.aligned.m8n8.x2.shared.b16 {%0,%1},[%2];"
        : "=r"(b[0]), "=r"(b[1]) : "r"(addr));
}
__device__ __forceinline__ void ldmBT(u32* b, u32 addr) {
    asm volatile("ldmatrix.sync.aligned.m8n8.x2.trans.shared.b16 {%0,%1},[%2];"
        : "=r"(b[0]), "=r"(b[1]) : "r"(addr));
}
__device__ __forceinline__ u32 smaddr(const void* p) {
    return (u32)__cvta_generic_to_shared(p);
}
__device__ __forceinline__ void bsplit2(float a, float b, u32& hi, u32& lo) {
    __nv_bfloat16 ha = __float2bfloat16(a), hb = __float2bfloat16(b);
    hi = (u32)__bfloat16_as_ushort(ha) | ((u32)__bfloat16_as_ushort(hb) << 16);
    float ra = a - __bfloat162float(ha), rb = b - __bfloat162float(hb);
    __nv_bfloat16 la = __float2bfloat16(ra), lb = __float2bfloat16(rb);
    lo = (u32)__bfloat16_as_ushort(la) | ((u32)__bfloat16_as_ushort(lb) << 16);
}

// ---------------- scratch ----------------
__device__ float  d_yg [(size_t)BCD * HWD];
__device__ float  d_yx [(size_t)BCD * HWD];
__device__ float2 d_Fg [(size_t)BCD * Hh * WFD];
__device__ float2 d_Fx [(size_t)BCD * Hh * WFD];
__device__ float2 d_Gg [(size_t)BCD * Hh * WFD];
__device__ float2 d_Gx [(size_t)BCD * Hh * WFD];
__device__ float2 d_Sb [(size_t)BCD * WFD * WFD];
__device__ float2 d_Tb [(size_t)BCD * Hh * WFD];
__device__ float  d_rb [(size_t)BCD * HWD];
__device__ float  d_rsq[BCD * Hh];
__device__ float2 d_W256[256];
__device__ __nv_bfloat16 d_DwTreh[256 * 512];
__device__ __nv_bfloat16 d_DwTrel[256 * 512];
__device__ __nv_bfloat16 d_DwTimh[256 * 512];
__device__ __nv_bfloat16 d_DwTiml[256 * 512];
__device__ __nv_bfloat16 d_CwT1h [512 * 256];
__device__ __nv_bfloat16 d_CwT1l [512 * 256];
__device__ __nv_bfloat16 d_CwT2h [512 * 256];
__device__ __nv_bfloat16 d_CwT2l [512 * 256];

// ---------------- table builder ----------------
__global__ void build_tables_kernel() {
    int idx = blockIdx.x * blockDim.x + threadIdx.x;
    int stride = gridDim.x * blockDim.x;
    float rsW = rsqrtf(510.0f);

    for (int i = idx; i < 256 * 512; i += stride) {
        int v = i >> 9, w = i & 511;
        float re = 0.f, im = 0.f;
        if (w < Ww) {
            int m = (int)(((long long)w * v) % Ww);
            float s, c; sincospif(2.0f * (float)m / (float)Ww, &s, &c);
            re = c * rsW; im = -s * rsW;
        }
        __nv_bfloat16 h = __float2bfloat16(re);
        d_DwTreh[i] = h;
        d_DwTrel[i] = __float2bfloat16(re - __bfloat162float(h));
        h = __float2bfloat16(im);
        d_DwTimh[i] = h;
        d_DwTiml[i] = __float2bfloat16(im - __bfloat162float(h));
    }
    for (int i = idx; i < 512 * 256; i += stride) {
        int w = i >> 8, v = i & 255;
        float b1 = 0.f, b2 = 0.f;
        if (w < Ww) {
            int m = (int)(((long long)v * w) % Ww);
            float s, c; sincospif(2.0f * (float)m / (float)Ww, &s, &c);
            float sv = (v == 0 || v == 255) ? 1.0f : 2.0f;
            b1 = sv * c * rsW; b2 = -sv * s * rsW;
        }
        __nv_bfloat16 h = __float2bfloat16(b1);
        d_CwT1h[i] = h;
        d_CwT1l[i] = __float2bfloat16(b1 - __bfloat162float(h));
        h = __float2bfloat16(b2);
        d_CwT2h[i] = h;
        d_CwT2l[i] = __float2bfloat16(b2 - __bfloat162float(h));
    }
    for (int j = idx; j < 256; j += stride) {
        float s, c; sincospif(2.0f * (float)j / 256.0f, &s, &c);
        d_W256[j] = make_float2(c, -s);
    }
}

__device__ __forceinline__ float sigm(float v) { return 1.f / (1.f + expf(-v)); }

#define PIT  40   // pitch for [row][k32] tiles
#define PITS 72   // pitch for [k32][col64] tiles (trans loads)
#define ASZ  (64 * PIT)
#define SSZ  (32 * PITS)

// ---------------- 1x1 conv — TENSOR CORE, double-buffered ----------------
__global__ void __launch_bounds__(256, 2) conv_tc(
    const float* __restrict__ X, const float* __restrict__ Wm,
    const float* __restrict__ bias, float* __restrict__ Y)
{
    __shared__ __nv_bfloat16 sWh[2][ASZ], sWl[2][ASZ];
    __shared__ __nv_bfloat16 sXh[2][SSZ], sXl[2][SSZ];
    int b = blockIdx.z;
    const float* Xb = X + (size_t)b * Cc * HWD;
    float* Yb = Y + (size_t)b * Cc * HWD;
    int n0 = blockIdx.x * 64, m0 = blockIdx.y * 64;
    int t = threadIdx.x, lane = t & 31, wid = t >> 5;
    int wm = (wid >> 2) * 32, wn = (wid & 3) * 16;
    int g = lane >> 2, tc4 = lane & 3;

    float acc[2][2][4];
#pragma unroll
    for (int i = 0; i < 2; i++)
#pragma unroll
        for (int j = 0; j < 2; j++)
#pragma unroll
            for (int q = 0; q < 4; q++) acc[i][j][q] = 0.f;

    int lrA = lane & 15, lkA = (lane >> 4) * 8;
    int kB = (lane & 7) + ((lane >> 3) & 1) * 8;
    int scA = t & 15, srA = t >> 4;
    int scB = t & 31, srB = t >> 5;

    float2 wv[4], xv[4];
#define CONV_LOAD(K0) { \
    _Pragma("unroll") \
    for (int i = 0; i < 4; i++) { \
        wv[i] = *(const float2*)&Wm[(m0 + srA + i * 16) * Cc + (K0) + 2 * scA]; \
        xv[i] = *(const float2*)&Xb[(size_t)((K0) + srB + i * 8) * HWD + n0 + 2 * scB]; \
    } }
#define CONV_STORE(BF) { \
    _Pragma("unroll") \
    for (int i = 0; i < 4; i++) { \
        u32 hi, lo; bsplit2(wv[i].x, wv[i].y, hi, lo); \
        int so = (srA + i * 16) * PIT + 2 * scA; \
        *(u32*)&sWh[BF][so] = hi; *(u32*)&sWl[BF][so] = lo; \
        bsplit2(xv[i].x, xv[i].y, hi, lo); \
        so = (srB + i * 8) * PITS + 2 * scB; \
        *(u32*)&sXh[BF][so] = hi; *(u32*)&sXl[BF][so] = lo; \
    } }

    CONV_LOAD(0)
    CONV_STORE(0)
    __syncthreads();
    for (int it = 0; it < 4; it++) {
        int buf = it & 1;
        if (it < 3) CONV_LOAD((it + 1) * 32)
        u32 aWh = smaddr(sWh[buf]), aWl = smaddr(sWl[buf]);
        u32 aXh = smaddr(sXh[buf]), aXl = smaddr(sXl[buf]);
#pragma unroll
        for (int ks = 0; ks < 2; ks++) {
            int kb = ks * 16;
            u32 ah[2][4], al[2][4];
#pragma unroll
            for (int tm = 0; tm < 2; tm++) {
                u32 off = ((wm + 16 * tm + lrA) * PIT + kb + lkA) * 2;
                ldmA(ah[tm], aWh + off);
                ldmA(al[tm], aWl + off);
            }
            u32 bh[2][2], bl[2][2];
#pragma unroll
            for (int tn = 0; tn < 2; tn++) {
                u32 off = ((kb + kB) * PITS + wn + 8 * tn) * 2;
                ldmBT(bh[tn], aXh + off);
                ldmBT(bl[tn], aXl + off);
            }
#pragma unroll
            for (int tm = 0; tm < 2; tm++)
#pragma unroll
                for (int tn = 0; tn < 2; tn++) {
                    mma_bf16(acc[tm][tn], ah[tm], bh[tn]);
                    mma_bf16(acc[tm][tn], ah[tm], bl[tn]);
                    mma_bf16(acc[tm][tn], al[tm], bh[tn]);
                }
        }
        if (it < 3) CONV_STORE(buf ^ 1)
        __syncthreads();
    }
#undef CONV_LOAD
#undef CONV_STORE
#pragma unroll
    for (int tm = 0; tm < 2; tm++)
#pragma unroll
        for (int tn = 0; tn < 2; tn++) {
            int r0 = m0 + wm + 16 * tm + g;
            int col = n0 + wn + 8 * tn + 2 * tc4;
            float bv0 = bias[r0], bv1 = bias[r0 + 8];
            *(float2*)&Yb[(size_t)r0 * HWD + col] =
                make_float2(acc[tm][tn][0] + bv0, acc[tm][tn][1] + bv0);
            *(float2*)&Yb[(size_t)(r0 + 8) * HWD + col] =
                make_float2(acc[tm][tn][2] + bv1, acc[tm][tn][3] + bv1);
        }
}

// ---------------- rfft along W — TC, double-buffered (dynamic smem) -------
__global__ void __launch_bounds__(256, 2) rfftw_tc(
    const float* __restrict__ Y, float2* __restrict__ F)
{
    extern __shared__ __nv_bfloat16 dynR[];
    __nv_bfloat16* sAh  = dynR;
    __nv_bfloat16* sAl  = sAh  + 2 * ASZ;
    __nv_bfloat16* sBrh = sAl  + 2 * ASZ;
    __nv_bfloat16* sBrl = sBrh + 2 * ASZ;
    __nv_bfloat16* sBih = sBrl + 2 * ASZ;
    __nv_bfloat16* sBil = sBih + 2 * ASZ;
    int bc = blockIdx.z;
    const float* A = Y + (size_t)bc * HWD;
    float2* Cp = F + (size_t)bc * Hh * WFD;
    int n0 = blockIdx.x * 64, m0 = blockIdx.y * 64;
    int t = threadIdx.x, lane = t & 31, wid = t >> 5;
    int wm = (wid >> 2) * 32, wn = (wid & 3) * 16;
    int g = lane >> 2, tc = lane & 3;

    float cre[2][2][4], cim[2][2][4];
#pragma unroll
    for (int i = 0; i < 2; i++)
#pragma unroll
        for (int j = 0; j < 2; j++)
#pragma unroll
            for (int q = 0; q < 4; q++) { cre[i][j][q] = 0.f; cim[i][j][q] = 0.f; }

    int lrA = lane & 15, lkA = (lane >> 4) * 8;
    int lrB = lane & 7,  lkB = ((lane >> 3) & 1) * 8;
    int sc = t & 15, sr = t >> 4;

    float a0[4], a1[4];
    u32 rbrh[4], rbrl[4], rbih[4], rbil[4];
#define RFW_LOAD(K0) { \
    _Pragma("unroll") \
    for (int i = 0; i < 4; i++) { \
        int r = sr + i * 16; int w = (K0) + 2 * sc; \
        if (w < Ww) { float2 t2 = *(const float2*)&A[(size_t)(m0 + r) * Ww + w]; \
                      a0[i] = t2.x; a1[i] = t2.y; } \
        else { a0[i] = 0.f; a1[i] = 0.f; } \
        size_t gi = (size_t)(n0 + r) * 512 + w; \
        rbrh[i] = *(const u32*)&d_DwTreh[gi]; \
        rbrl[i] = *(const u32*)&d_DwTrel[gi]; \
        rbih[i] = *(const u32*)&d_DwTimh[gi]; \
        rbil[i] = *(const u32*)&d_DwTiml[gi]; \
    } }
#define RFW_STORE(BF) { \
    _Pragma("unroll") \
    for (int i = 0; i < 4; i++) { \
        int so = (BF) * ASZ + (sr + i * 16) * PIT + 2 * sc; \
        u32 hi, lo; bsplit2(a0[i], a1[i], hi, lo); \
        *(u32*)&sAh[so] = hi; *(u32*)&sAl[so] = lo; \
        *(u32*)&sBrh[so] = rbrh[i]; *(u32*)&sBrl[so] = rbrl[i]; \
        *(u32*)&sBih[so] = rbih[i]; *(u32*)&sBil[so] = rbil[i]; \
    } }

    RFW_LOAD(0)
    RFW_STORE(0)
    __syncthreads();
    for (int it = 0; it < 16; it++) {
        int buf = it & 1;
        if (it < 15) RFW_LOAD((it + 1) * 32)
        u32 aAh = smaddr(sAh + buf * ASZ), aAl = smaddr(sAl + buf * ASZ);
        u32 aBrh = smaddr(sBrh + buf * ASZ), aBrl = smaddr(sBrl + buf * ASZ);
        u32 aBih = smaddr(sBih + buf * ASZ), aBil = smaddr(sBil + buf * ASZ);
#pragma unroll
        for (int ks = 0; ks < 2; ks++) {
            int kb = ks * 16;
            u32 ah[2][4], al[2][4];
#pragma unroll
            for (int tm = 0; tm < 2; tm++) {
                u32 off = ((wm + 16 * tm + lrA) * PIT + kb + lkA) * 2;
                ldmA(ah[tm], aAh + off);
                ldmA(al[tm], aAl + off);
            }
            u32 brh[2][2], brl[2][2], bih[2][2], bil[2][2];
#pragma unroll
            for (int tn = 0; tn < 2; tn++) {
                u32 off = ((wn + 8 * tn + lrB) * PIT + kb + lkB) * 2;
                ldmB(brh[tn], aBrh + off);
                ldmB(brl[tn], aBrl + off);
                ldmB(bih[tn], aBih + off);
                ldmB(bil[tn], aBil + off);
            }
#pragma unroll
            for (int tm = 0; tm < 2; tm++)
#pragma unroll
                for (int tn = 0; tn < 2; tn++) {
                    mma_bf16(cre[tm][tn], ah[tm], brh[tn]);
                    mma_bf16(cre[tm][tn], ah[tm], brl[tn]);
                    mma_bf16(cre[tm][tn], al[tm], brh[tn]);
                    mma_bf16(cim[tm][tn], ah[tm], bih[tn]);
                    mma_bf16(cim[tm][tn], ah[tm], bil[tn]);
                    mma_bf16(cim[tm][tn], al[tm], bih[tn]);
                }
        }
        if (it < 15) RFW_STORE(buf ^ 1)
        __syncthreads();
    }
#undef RFW_LOAD
#undef RFW_STORE
#pragma unroll
    for (int tm = 0; tm < 2; tm++)
#pragma unroll
        for (int tn = 0; tn < 2; tn++) {
            int r0 = m0 + wm + 16 * tm + g;
            int col = n0 + wn + 8 * tn + 2 * tc;
            float4 v0 = make_float4(cre[tm][tn][0], cim[tm][tn][0], cre[tm][tn][1], cim[tm][tn][1]);
            *(float4*)&Cp[(size_t)r0 * WFD + col] = v0;
            float4 v1 = make_float4(cre[tm][tn][2], cim[tm][tn][2], cre[tm][tn][3], cim[tm][tn][3]);
            *(float4*)&Cp[(size_t)(r0 + 8) * WFD + col] = v1;
        }
}

// ------- irfft along W + residual — TC, double-buffered (dynamic smem) ----
__global__ void __launch_bounds__(256, 2) irfft_add_tc(
    const float2* __restrict__ T, const float* __restrict__ x, float* __restrict__ r)
{
    extern __shared__ __nv_bfloat16 dynI[];
    __nv_bfloat16* sArh = dynI;
    __nv_bfloat16* sArl = sArh + 2 * ASZ;
    __nv_bfloat16* sAih = sArl + 2 * ASZ;
    __nv_bfloat16* sAil = sAih + 2 * ASZ;
    __nv_bfloat16* sB1h = sAil + 2 * ASZ;
    __nv_bfloat16* sB1l = sB1h + 2 * ASZ;
    __nv_bfloat16* sB2h = sB1l + 2 * ASZ;
    __nv_bfloat16* sB2l = sB2h + 2 * ASZ;
    int bc = blockIdx.z;
    const float2* Ap = T + (size_t)bc * 65536;
    int n0 = blockIdx.x * 64, m0 = blockIdx.y * 64;
    int t = threadIdx.x, lane = t & 31, wid = t >> 5;
    int wm = (wid >> 2) * 32, wn = (wid & 3) * 16;
    int g = lane >> 2, tc = lane & 3;

    float acc[2][2][4];
#pragma unroll
    for (int i = 0; i < 2; i++)
#pragma unroll
        for (int j = 0; j < 2; j++)
#pragma unroll
            for (int q = 0; q < 4; q++) acc[i][j][q] = 0.f;

    int lrA = lane & 15, lkA = (lane >> 4) * 8;
    int lrB = lane & 7,  lkB = ((lane >> 3) & 1) * 8;
    int sc = t & 15, sr = t >> 4;

    float4 va[4];
    u32 rb1h[4], rb1l[4], rb2h[4], rb2l[4];
#define IRF_LOAD(K0) { \
    _Pragma("unroll") \
    for (int i = 0; i < 4; i++) { \
        int rr = sr + i * 16; \
        va[i] = *(const float4*)&Ap[(size_t)(m0 + rr) * 256 + (K0) + 2 * sc]; \
        size_t gi = (size_t)(n0 + rr) * 256 + (K0) + 2 * sc; \
        rb1h[i] = *(const u32*)&d_CwT1h[gi]; \
        rb1l[i] = *(const u32*)&d_CwT1l[gi]; \
        rb2h[i] = *(const u32*)&d_CwT2h[gi]; \
        rb2l[i] = *(const u32*)&d_CwT2l[gi]; \
    } }
#define IRF_STORE(BF) { \
    _Pragma("unroll") \
    for (int i = 0; i < 4; i++) { \
        int so = (BF) * ASZ + (sr + i * 16) * PIT + 2 * sc; \
        u32 hi, lo; \
        bsplit2(va[i].x, va[i].z, hi, lo); \
        *(u32*)&sArh[so] = hi; *(u32*)&sArl[so] = lo; \
        bsplit2(va[i].y, va[i].w, hi, lo); \
        *(u32*)&sAih[so] = hi; *(u32*)&sAil[so] = lo; \
        *(u32*)&sB1h[so] = rb1h[i]; *(u32*)&sB1l[so] = rb1l[i]; \
        *(u32*)&sB2h[so] = rb2h[i]; *(u32*)&sB2l[so] = rb2l[i]; \
    } }

    IRF_LOAD(0)
    IRF_STORE(0)
    __syncthreads();
    for (int it = 0; it < 8; it++) {
        int buf = it & 1;
        if (it < 7) IRF_LOAD((it + 1) * 32)
        u32 aArh = smaddr(sArh + buf * ASZ), aArl = smaddr(sArl + buf * ASZ);
        u32 aAih = smaddr(sAih + buf * ASZ), aAil = smaddr(sAil + buf * ASZ);
        u32 aB1h = smaddr(sB1h + buf * ASZ), aB1l = smaddr(sB1l + buf * ASZ);
        u32 aB2h = smaddr(sB2h + buf * ASZ), aB2l = smaddr(sB2l + buf * ASZ);
#pragma unroll
        for (int ks = 0; ks < 2; ks++) {
            int kb = ks * 16;
            u32 arh[2][4], arl[2][4], aih[2][4], ail[2][4];
#pragma unroll
            for (int tm = 0; tm < 2; tm++) {
                u32 off = ((wm + 16 * tm + lrA) * PIT + kb + lkA) * 2;
                ldmA(arh[tm], aArh + off);
                ldmA(arl[tm], aArl + off);
                ldmA(aih[tm], aAih + off);
                ldmA(ail[tm], aAil + off);
            }
            u32 b1h[2][2], b1l[2][2], b2h[2][2], b2l[2][2];
#pragma unroll
            for (int tn = 0; tn < 2; tn++) {
                u32 off = ((wn + 8 * tn + lrB) * PIT + kb + lkB) * 2;
                ldmB(b1h[tn], aB1h + off);
                ldmB(b1l[tn], aB1l + off);
                ldmB(b2h[tn], aB2h + off);
                ldmB(b2l[tn], aB2l + off);
            }
#pragma unroll
            for (int tm = 0; tm < 2; tm++)
#pragma unroll
                for (int tn = 0; tn < 2; tn++) {
                    mma_bf16(acc[tm][tn], arh[tm], b1h[tn]);
                    mma_bf16(acc[tm][tn], arh[tm], b1l[tn]);
                    mma_bf16(acc[tm][tn], arl[tm], b1h[tn]);
                    mma_bf16(acc[tm][tn], aih[tm], b2h[tn]);
                    mma_bf16(acc[tm][tn], aih[tm], b2l[tn]);
                    mma_bf16(acc[tm][tn], ail[tm], b2h[tn]);
                }
        }
        if (it < 7) IRF_STORE(buf ^ 1)
        __syncthreads();
    }
#undef IRF_LOAD
#undef IRF_STORE
#pragma unroll
    for (int tm = 0; tm < 2; tm++)
#pragma unroll
        for (int tn = 0; tn < 2; tn++) {
            int col = n0 + wn + 8 * tn + 2 * tc;
            if (col < Ww) {
                int r0 = m0 + wm + 16 * tm + g;
                size_t i0 = (size_t)bc * HWD + (size_t)r0 * Ww + col;
                size_t i1 = i0 + (size_t)8 * Ww;
                float2 xv = *(const float2*)&x[i0];
                *(float2*)&r[i0] = make_float2(acc[tm][tn][0] + xv.x, acc[tm][tn][1] + xv.y);
                xv = *(const float2*)&x[i1];
                *(float2*)&r[i1] = make_float2(acc[tm][tn][2] + xv.x, acc[tm][tn][3] + xv.y);
            }
        }
}

// ---------------- 256-pt FFT along slow axis (4-step 16x16) ----------------
template<int INV, int FILT>
__global__ void __launch_bounds__(256) ffth_kernel(
    const float2* __restrict__ in, float2* __restrict__ out,
    const float2* __restrict__ filt)
{
    __shared__ float2 Xs[256][17];
    __shared__ float2 Ws[256];
    int bc = blockIdx.y;
    int v0 = blockIdx.x * 16;
    int tx = threadIdx.x;
    int ty = threadIdx.y;
    int t = ty * 16 + tx;
    const float2* inp = in + (size_t)bc * 65536 + v0;
    float2* outp = out + (size_t)bc * 65536 + v0;

    {
        float2 w = d_W256[t];
        if (INV) w.y = -w.y;
        Ws[t] = w;
    }
#pragma unroll
    for (int i = 0; i < 16; i++) {
        int h = i * 16 + ty;
        Xs[h][tx] = inp[(size_t)h * 256 + tx];
    }
    __syncthreads();

    float2 rr[16];
    {
        u64 tw[16];
#pragma unroll
        for (int n1 = 0; n1 < 16; n1++) {
            float2 w = Ws[(n1 * ty * 16) & 255];
            tw[n1] = pk2(w.x, w.y);
        }
#pragma unroll
        for (int n2 = 0; n2 < 16; n2++) {
            u64 accA = 0ull, accB = 0ull;
#pragma unroll
            for (int n1 = 0; n1 < 16; n1++) {
                float2 xv = Xs[16 * n1 + n2][tx];
                u64 xp = pk2(xv.x, xv.y);
                u64 xq = pk2(xv.y, xv.x);
                accA = ffma2(xp, tw[n1], accA);
                accB = ffma2(xq, tw[n1], accB);
            }
            float2 a = up2(accA), b = up2(accB);
            float ar = a.x - a.y, ai = b.x + b.y;
            float2 tm = Ws[(n2 * ty) & 255];
            rr[n2] = make_float2(ar * tm.x - ai * tm.y, ar * tm.y + ai * tm.x);
        }
    }
    __syncthreads();
#pragma unroll
    for (int n2 = 0; n2 < 16; n2++)
        Xs[ty * 16 + n2][tx] = rr[n2];
    __syncthreads();

    {
        u64 tw[16];
#pragma unroll
        for (int n2 = 0; n2 < 16; n2++) {
            float2 w = Ws[(n2 * ty * 16) & 255];
            tw[n2] = pk2(w.x, w.y);
        }
        int c = bc & (Cc - 1);
#pragma unroll
        for (int k1 = 0; k1 < 16; k1++) {
            u64 accA = 0ull, accB = 0ull;
#pragma unroll
            for (int n2 = 0; n2 < 16; n2++) {
                float2 xv = Xs[k1 * 16 + n2][tx];
                u64 xp = pk2(xv.x, xv.y);
                u64 xq = pk2(xv.y, xv.x);
                accA = ffma2(xp, tw[n2], accA);
                accB = ffma2(xq, tw[n2], accB);
            }
            float2 a = up2(accA), b = up2(accB);
            int u = k1 + 16 * ty;
            float2 v = make_float2((a.x - a.y) * 0.0625f, (b.x + b.y) * 0.0625f);
            if (FILT) {
                float2 wc = filt[((size_t)c * Hh + u) * WFD + v0 + tx];
                v = make_float2(v.x * wc.x - v.y * wc.y, v.x * wc.y + v.y * wc.x);
            }
            outp[(size_t)u * 256 + tx] = v;
        }
    }
}

// ------- variance over v per (bc,u) row -------
__global__ void var_kernel(const float2* __restrict__ G, float* __restrict__ rsq)
{
    __shared__ float s0[256], s1[256], s2[256];
    int row = blockIdx.x;
    int tid = threadIdx.x;
    float2 z = G[(size_t)row * WFD + tid];
    s0[tid] = z.x; s1[tid] = z.y; s2[tid] = z.x * z.x + z.y * z.y;
    __syncthreads();
    for (int s = 128; s > 0; s >>= 1) {
        if (tid < s) { s0[tid] += s0[tid + s]; s1[tid] += s1[tid + s]; s2[tid] += s2[tid + s]; }
        __syncthreads();
    }
    if (tid == 0) {
        float mr = s0[0] * (1.f / WFD), mi = s1[0] * (1.f / WFD);
        float var = s2[0] * (1.f / WFD) - (mr * mr + mi * mi);
        rsq[row] = 1.f / sqrtf(6.283185307179586f * var);
    }
}

// ------- scores — TC complex, double-buffered (dynamic smem) -------
__global__ void __launch_bounds__(256) scores_tc(
    const float2* __restrict__ Gb, const float2* __restrict__ Xb,
    const float* __restrict__ rsq, float2* __restrict__ Sb)
{
    extern __shared__ __nv_bfloat16 dynS[];
    __nv_bfloat16* sGrh = dynS;
    __nv_bfloat16* sGrl = sGrh + 2 * SSZ;
    __nv_bfloat16* sGih = sGrl + 2 * SSZ;
    __nv_bfloat16* sGil = sGih + 2 * SSZ;
    __nv_bfloat16* sXrh = sGil + 2 * SSZ;
    __nv_bfloat16* sXrl = sXrh + 2 * SSZ;
    __nv_bfloat16* sXih = sXrl + 2 * SSZ;
    __nv_bfloat16* sXil = sXih + 2 * SSZ;
    int bc = blockIdx.z;
    const float2* Ap = Gb + (size_t)bc * 65536;
    const float2* Bp = Xb + (size_t)bc * 65536;
    float2* Cp = Sb + (size_t)bc * 65536;
    int n0 = blockIdx.x * 64, m0 = blockIdx.y * 64;
    int t = threadIdx.x, lane = t & 31, wid = t >> 5;
    int wm = (wid >> 2) * 32, wn = (wid & 3) * 16;
    int g = lane >> 2, tc4 = lane & 3;

    float are[2][2][4], aim[2][2][4];
#pragma unroll
    for (int i = 0; i < 2; i++)
#pragma unroll
        for (int j = 0; j < 2; j++)
#pragma unroll
            for (int q = 0; q < 4; q++) { are[i][j][q] = 0.f; aim[i][j][q] = 0.f; }

    int kA = (lane & 7) + ((lane >> 4) & 1) * 8;
    int mA = ((lane >> 3) & 1) * 8;
    int kB = (lane & 7) + ((lane >> 3) & 1) * 8;
    int sc = t & 31, sr = t >> 5;

    float4 vA[4], vB[4];
#define SCR_LOAD(K0) { \
    _Pragma("unroll") \
    for (int i = 0; i < 4; i++) { \
        int k = sr + i * 8; \
        vA[i] = *(const float4*)&Ap[(size_t)((K0) + k) * 256 + m0 + 2 * sc]; \
        vB[i] = *(const float4*)&Bp[(size_t)((K0) + k) * 256 + n0 + 2 * sc]; \
    } }
#define SCR_STORE(BF) { \
    _Pragma("unroll") \
    for (int i = 0; i < 4; i++) { \
        int so = (BF) * SSZ + (sr + i * 8) * PITS + 2 * sc; \
        u32 hi, lo; \
        bsplit2(vA[i].x, vA[i].z, hi, lo); *(u32*)&sGrh[so] = hi; *(u32*)&sGrl[so] = lo; \
        bsplit2(vA[i].y, vA[i].w, hi, lo); *(u32*)&sGih[so] = hi; *(u32*)&sGil[so] = lo; \
        bsplit2(vB[i].x, vB[i].z, hi, lo); *(u32*)&sXrh[so] = hi; *(u32*)&sXrl[so] = lo; \
        bsplit2(vB[i].y, vB[i].w, hi, lo); *(u32*)&sXih[so] = hi; *(u32*)&sXil[so] = lo; \
    } }

    SCR_LOAD(0)
    SCR_STORE(0)
    __syncthreads();
    for (int it = 0; it < 8; it++) {
        int buf = it & 1;
        if (it < 7) SCR_LOAD((it + 1) * 32)
        u32 aGrh = smaddr(sGrh + buf * SSZ), aGrl = smaddr(sGrl + buf * SSZ);
        u32 aGih = smaddr(sGih + buf * SSZ), aGil = smaddr(sGil + buf * SSZ);
        u32 aXrh = smaddr(sXrh + buf * SSZ), aXrl = smaddr(sXrl + buf * SSZ);
        u32 aXih = smaddr(sXih + buf * SSZ), aXil = smaddr(sXil + buf * SSZ);
#pragma unroll
        for (int ks = 0; ks < 2; ks++) {
            int kb = ks * 16;
            u32 grh[2][4], grl[2][4], gih[2][4], gil[2][4];
#pragma unroll
            for (int tm = 0; tm < 2; tm++) {
                u32 off = ((kb + kA) * PITS + wm + 16 * tm + mA) * 2;
                ldmAT(grh[tm], aGrh + off);
                ldmAT(grl[tm], aGrl + off);
                ldmAT(gih[tm], aGih + off);
                ldmAT(gil[tm], aGil + off);
            }
            u32 xrh[2][2], xrl[2][2], xih[2][2], xil[2][2];
#pragma unroll
            for (int tn = 0; tn < 2; tn++) {
                u32 off = ((kb + kB) * PITS + wn + 8 * tn) * 2;
                ldmBT(xrh[tn], aXrh + off);
                ldmBT(xrl[tn], aXrl + off);
                ldmBT(xih[tn], aXih + off);
                ldmBT(xil[tn], aXil + off);
            }
#pragma unroll
            for (int tm = 0; tm < 2; tm++) {
                u32 nih[4], nil_[4];
#pragma unroll
                for (int q = 0; q < 4; q++) {
                    nih[q]  = gih[tm][q] ^ 0x80008000u;
                    nil_[q] = gil[tm][q] ^ 0x80008000u;
                }
#pragma unroll
                for (int tn = 0; tn < 2; tn++) {
                    mma_bf16(are[tm][tn], grh[tm], xrh[tn]);
                    mma_bf16(are[tm][tn], grh[tm], xrl[tn]);
                    mma_bf16(are[tm][tn], grl[tm], xrh[tn]);
                    mma_bf16(are[tm][tn], nih,     xih[tn]);
                    mma_bf16(are[tm][tn], nih,     xil[tn]);
                    mma_bf16(are[tm][tn], nil_,    xih[tn]);
                    mma_bf16(aim[tm][tn], grh[tm], xih[tn]);
                    mma_bf16(aim[tm][tn], grh[tm], xil[tn]);
                    mma_bf16(aim[tm][tn], grl[tm], xih[tn]);
                    mma_bf16(aim[tm][tn], gih[tm], xrh[tn]);
                    mma_bf16(aim[tm][tn], gih[tm], xrl[tn]);
                    mma_bf16(aim[tm][tn], gil[tm], xrh[tn]);
                }
            }
        }
        if (it < 7) SCR_STORE(buf ^ 1)
        __syncthreads();
    }
#undef SCR_LOAD
#undef SCR_STORE
#pragma unroll
    for (int tm = 0; tm < 2; tm++)
#pragma unroll
        for (int tn = 0; tn < 2; tn++) {
            int r0 = m0 + wm + 16 * tm + g;
            int col = n0 + wn + 8 * tn + 2 * tc4;
            float s0 = rsq[bc * Hh + r0], s1 = rsq[bc * Hh + r0 + 8];
            float4 o0 = make_float4(
                sigm(are[tm][tn][0] * s0), sigm(aim[tm][tn][0] * s0),
                sigm(are[tm][tn][1] * s0), sigm(aim[tm][tn][1] * s0));
            *(float4*)&Cp[(size_t)r0 * 256 + col] = o0;
            float4 o1 = make_float4(
                sigm(are[tm][tn][2] * s1), sigm(aim[tm][tn][2] * s1),
                sigm(are[tm][tn][3] * s1), sigm(aim[tm][tn][3] * s1));
            *(float4*)&Cp[(size_t)(r0 + 8) * 256 + col] = o1;
        }
}

// ------- channel LayerNorm — single-read smem-tiled -------
__global__ void __launch_bounds__(256) ln_kernel(
    const float* __restrict__ r, const float* __restrict__ gamma,
    const float* __restrict__ beta, float* __restrict__ out)
{
    __shared__ float tile[128][64];
    __shared__ float ps[4][64], qs[4][64];
    __shared__ float mu[64], inv[64];
    int blk = blockIdx.x;
    int b = blk / 2040;
    int w0 = (blk - b * 2040) * 64;
    int t = threadIdx.x;
    int wl = t & 63, cq = t >> 6;

#pragma unroll 8
    for (int c0 = 0; c0 < 128; c0 += 4) {
        int c = c0 + cq;
        tile[c][wl] = r[(size_t)(b * Cc + c) * HWD + w0 + wl];
    }
    __syncthreads();
    {
        float s = 0.f, q = 0.f;
#pragma unroll
        for (int c = 0; c < 32; c++) {
            float v = tile[cq * 32 + c][wl];
            s += v; q += v * v;
        }
        ps[cq][wl] = s; qs[cq][wl] = q;
    }
    __syncthreads();
    if (t < 64) {
        float s = ps[0][t] + ps[1][t] + ps[2][t] + ps[3][t];
        float q = qs[0][t] + qs[1][t] + qs[2][t] + qs[3][t];
        float m = s * (1.f / 128.f);
        mu[t] = m;
        inv[t] = rsqrtf(q * (1.f / 128.f) - m * m + 1e-6f);
    }
    __syncthreads();
#pragma unroll 8
    for (int c0 = 0; c0 < 128; c0 += 4) {
        int c = c0 + cq;
        out[(size_t)(b * Cc + c) * HWD + w0 + wl] =
            gamma[c] * (tile[c][wl] - mu[wl]) * inv[wl] + beta[c];
    }
}

// ---------------- launch ----------------
extern "C" void kernel_launch(void* const* d_in, const int* in_sizes, int n_in,
                              void* d_out, int out_size)
{
    (void)in_sizes; (void)n_in; (void)out_size;
    const float*  g     = (const float*)d_in[0];
    const float*  x     = (const float*)d_in[1];
    const float*  wg    = (const float*)d_in[2];
    const float*  bg    = (const float*)d_in[3];
    const float*  wx    = (const float*)d_in[4];
    const float*  bx    = (const float*)d_in[5];
    const float2* fg    = (const float2*)d_in[6];
    const float2* fx    = (const float2*)d_in[7];
    const float*  gamma = (const float*)d_in[8];
    const float*  beta  = (const float*)d_in[9];
    float* out = (float*)d_out;

    float *yg, *yx, *rb, *rsq;
    float2 *Fg, *Fx, *Gg, *Gx, *S, *T;
    cudaGetSymbolAddress((void**)&yg,  d_yg);
    cudaGetSymbolAddress((void**)&yx,  d_yx);
    cudaGetSymbolAddress((void**)&Fg,  d_Fg);
    cudaGetSymbolAddress((void**)&Fx,  d_Fx);
    cudaGetSymbolAddress((void**)&Gg,  d_Gg);
    cudaGetSymbolAddress((void**)&Gx,  d_Gx);
    cudaGetSymbolAddress((void**)&S,   d_Sb);
    cudaGetSymbolAddress((void**)&T,   d_Tb);
    cudaGetSymbolAddress((void**)&rb,  d_rb);
    cudaGetSymbolAddress((void**)&rsq, d_rsq);

    static int attr_done = 0;
    if (!attr_done) {
        cudaFuncSetAttribute(rfftw_tc, cudaFuncAttributeMaxDynamicSharedMemorySize,
                             12 * ASZ * 2);
        cudaFuncSetAttribute(scores_tc, cudaFuncAttributeMaxDynamicSharedMemorySize,
                             16 * SSZ * 2);
        cudaFuncSetAttribute(irfft_add_tc, cudaFuncAttributeMaxDynamicSharedMemorySize,
                             16 * ASZ * 2);
        attr_done = 1;
    }

    dim3 blk(16, 16);

    build_tables_kernel<<<256, 256>>>();

    conv_tc<<<dim3(HWD / 64, 2, Bb), 256>>>(g, wg, bg, yg);
    conv_tc<<<dim3(HWD / 64, 2, Bb), 256>>>(x, wx, bx, yx);

    rfftw_tc<<<dim3(4, 4, BCD), 256, 12 * ASZ * 2>>>(yg, Fg);
    rfftw_tc<<<dim3(4, 4, BCD), 256, 12 * ASZ * 2>>>(yx, Fx);

    ffth_kernel<0, 1><<<dim3(16, BCD), blk>>>(Fg, Gg, fg);
    ffth_kernel<0, 1><<<dim3(16, BCD), blk>>>(Fx, Gx, fx);

    var_kernel<<<BCD * Hh, 256>>>(Gg, rsq);

    scores_tc<<<dim3(4, 4, BCD), 256, 16 * SSZ * 2>>>(Gg, Gx, rsq, S);

    ffth_kernel<1, 0><<<dim3(16, BCD), blk>>>(S, T, nullptr);

    irfft_add_tc<<<dim3(8, 4, BCD), 256, 16 * ASZ * 2>>>(T, x, rb);

    ln_kernel<<<Bb * 2040, 256>>>(rb, gamma, beta, out);
}

// round 9
// speedup vs baseline: 2.6824x; 1.0593x over previous
#include <cuda_runtime.h>
#include <cuda_bf16.h>
#include <math.h>

#define Bb  2
#define Cc  128
#define Hh  256
#define Ww  510
#define WFD 256
#define HWD 130560   /* 256*510 */
#define BCD 256      /* Bb*Cc */

typedef unsigned int u32;
typedef unsigned long long u64;

__device__ __forceinline__ u64 pk2(float lo, float hi) {
    u64 r; asm("mov.b64 %0,{%1,%2};" : "=l"(r) : "f"(lo), "f"(hi)); return r;
}
__device__ __forceinline__ float2 up2(u64 v) {
    float2 r; asm("mov.b64 {%0,%1},%2;" : "=f"(r.x), "=f"(r.y) : "l"(v)); return r;
}
__device__ __forceinline__ u64 ffma2(u64 a, u64 b, u64 c) {
    u64 d; asm("fma.rn.f32x2 %0,%1,%2,%3;" : "=l"(d) : "l"(a), "l"(b), "l"(c)); return d;
}

// ---- tensor-core helpers -------------------------------------------------
__device__ __forceinline__ void mma_bf16(float* c, const u32* a, const u32* b) {
    asm("mma.sync.aligned.m16n8k16.row.col.f32.bf16.bf16.f32 "
        "{%0,%1,%2,%3},{%4,%5,%6,%7},{%8,%9},{%0,%1,%2,%3};"
        : "+f"(c[0]), "+f"(c[1]), "+f"(c[2]), "+f"(c[3])
        : "r"(a[0]), "r"(a[1]), "r"(a[2]), "r"(a[3]), "r"(b[0]), "r"(b[1]));
}
__device__ __forceinline__ void ldmA(u32* a, u32 addr) {
    asm volatile("ldmatrix.sync.aligned.m8n8.x4.shared.b16 {%0,%1,%2,%3},[%4];"
        : "=r"(a[0]), "=r"(a[1]), "=r"(a[2]), "=r"(a[3]) : "r"(addr));
}
__device__ __forceinline__ void ldmAT(u32* a, u32 addr) {
    asm volatile("ldmatrix.sync.aligned.m8n8.x4.trans.shared.b16 {%0,%1,%2,%3},[%4];"
        : "=r"(a[0]), "=r"(a[1]), "=r"(a[2]), "=r"(a[3]) : "r"(addr));
}
__device__ __forceinline__ void ldmB(u32* b, u32 addr) {
    asm volatile("ldmatrix.sync.aligned.m8n8.x2.shared.b16 {%0,%1},[%2];"
        : "=r"(b[0]), "=r"(b[1]) : "r"(addr));
}
__device__ __forceinline__ void ldmBT(u32* b, u32 addr) {
    asm volatile("ldmatrix.sync.aligned.m8n8.x2.trans.shared.b16 {%0,%1},[%2];"
        : "=r"(b[0]), "=r"(b[1]) : "r"(addr));
}
__device__ __forceinline__ u32 smaddr(const void* p) {
    return (u32)__cvta_generic_to_shared(p);
}
__device__ __forceinline__ void bsplit2(float a, float b, u32& hi, u32& lo) {
    __nv_bfloat16 ha = __float2bfloat16(a), hb = __float2bfloat16(b);
    hi = (u32)__bfloat16_as_ushort(ha) | ((u32)__bfloat16_as_ushort(hb) << 16);
    float ra = a - __bfloat162float(ha), rb = b - __bfloat162float(hb);
    __nv_bfloat16 la = __float2bfloat16(ra), lb = __float2bfloat16(rb);
    lo = (u32)__bfloat16_as_ushort(la) | ((u32)__bfloat16_as_ushort(lb) << 16);
}

// ---------------- scratch ----------------
__device__ float  d_yg [(size_t)BCD * HWD];
__device__ float  d_yx [(size_t)BCD * HWD];
__device__ float2 d_Fg [(size_t)BCD * Hh * WFD];
__device__ float2 d_Fx [(size_t)BCD * Hh * WFD];
__device__ float2 d_Gg [(size_t)BCD * Hh * WFD];
__device__ float2 d_Gx [(size_t)BCD * Hh * WFD];
__device__ float2 d_Sb [(size_t)BCD * WFD * WFD];
__device__ float2 d_Tb [(size_t)BCD * Hh * WFD];
__device__ float  d_rb [(size_t)BCD * HWD];
__device__ float  d_rsq[BCD * Hh];
__device__ float2 d_W256[256];
// mma-fragment-order DFT tables: u64 = {reg0(lo u32), reg1(hi u32)}, each u32 = bf16x2
// rfftw B (Dw): index ((nblk*32 + kblk)*32 + lane), nblk<32 (v/8), kblk<32 (w/16)
__device__ u64 d_DwFrh[32768], d_DwFrl[32768], d_DwFih[32768], d_DwFil[32768];
// irfft B (Cw): index ((nblk*16 + kblk)*32 + lane), nblk<64 (w/8), kblk<16 (v/16)
__device__ u64 d_CwF1h[32768], d_CwF1l[32768], d_CwF2h[32768], d_CwF2l[32768];

__device__ __forceinline__ void sp_bits(float x, u32& hb, u32& lb) {
    __nv_bfloat16 h = __float2bfloat16(x);
    hb = (u32)__bfloat16_as_ushort(h);
    lb = (u32)__bfloat16_as_ushort(__float2bfloat16(x - __bfloat162float(h)));
}

// ---------------- table builder ----------------
__global__ void build_tables_kernel() {
    int idx = blockIdx.x * blockDim.x + threadIdx.x;
    int stride = gridDim.x * blockDim.x;
    float rsW = rsqrtf(510.0f);

    // Dw fragment tables: B[k=w][n=v], value = e^{-2pi i w v/510}/sqrt(510)
    for (int i = idx; i < 32768; i += stride) {
        int lane = i & 31, kblk = (i >> 5) & 31, nblk = i >> 10;
        int v = nblk * 8 + (lane >> 2);
        u32 prh[2], prl[2], pih[2], pil[2];
#pragma unroll
        for (int reg = 0; reg < 2; reg++) {
            prh[reg] = prl[reg] = pih[reg] = pil[reg] = 0;
#pragma unroll
            for (int e = 0; e < 2; e++) {
                int w = kblk * 16 + (lane & 3) * 2 + e + reg * 8;
                float re = 0.f, im = 0.f;
                if (w < Ww) {
                    int m = (w * v) % Ww;
                    float s, c; sincospif(2.0f * (float)m / (float)Ww, &s, &c);
                    re = c * rsW; im = -s * rsW;
                }
                u32 hb, lb;
                sp_bits(re, hb, lb);
                prh[reg] |= hb << (16 * e); prl[reg] |= lb << (16 * e);
                sp_bits(im, hb, lb);
                pih[reg] |= hb << (16 * e); pil[reg] |= lb << (16 * e);
            }
        }
        d_DwFrh[i] = (u64)prh[0] | ((u64)prh[1] << 32);
        d_DwFrl[i] = (u64)prl[0] | ((u64)prl[1] << 32);
        d_DwFih[i] = (u64)pih[0] | ((u64)pih[1] << 32);
        d_DwFil[i] = (u64)pil[0] | ((u64)pil[1] << 32);
    }
    // Cw fragment tables: B[k=v][n=w], b1 = sv*cos/sqrt, b2 = -sv*sin/sqrt
    for (int i = idx; i < 32768; i += stride) {
        int lane = i & 31, kblk = (i >> 5) & 15, nblk = i >> 9;
        int w = nblk * 8 + (lane >> 2);
        u32 p1h[2], p1l[2], p2h[2], p2l[2];
#pragma unroll
        for (int reg = 0; reg < 2; reg++) {
            p1h[reg] = p1l[reg] = p2h[reg] = p2l[reg] = 0;
#pragma unroll
            for (int e = 0; e < 2; e++) {
                int v = kblk * 16 + (lane & 3) * 2 + e + reg * 8;
                float b1 = 0.f, b2 = 0.f;
                if (w < Ww) {
                    int m = (v * w) % Ww;
                    float s, c; sincospif(2.0f * (float)m / (float)Ww, &s, &c);
                    float sv = (v == 0 || v == 255) ? 1.0f : 2.0f;
                    b1 = sv * c * rsW; b2 = -sv * s * rsW;
                }
                u32 hb, lb;
                sp_bits(b1, hb, lb);
                p1h[reg] |= hb << (16 * e); p1l[reg] |= lb << (16 * e);
                sp_bits(b2, hb, lb);
                p2h[reg] |= hb << (16 * e); p2l[reg] |= lb << (16 * e);
            }
        }
        d_CwF1h[i] = (u64)p1h[0] | ((u64)p1h[1] << 32);
        d_CwF1l[i] = (u64)p1l[0] | ((u64)p1l[1] << 32);
        d_CwF2h[i] = (u64)p2h[0] | ((u64)p2h[1] << 32);
        d_CwF2l[i] = (u64)p2l[0] | ((u64)p2l[1] << 32);
    }
    for (int j = idx; j < 256; j += stride) {
        float s, c; sincospif(2.0f * (float)j / 256.0f, &s, &c);
        d_W256[j] = make_float2(c, -s);
    }
}

__device__ __forceinline__ float sigm(float v) { return 1.f / (1.f + expf(-v)); }

#define PIT  40
#define PITS 72
#define ASZ  (64 * PIT)
#define SSZ  (32 * PITS)

// ---------------- 1x1 conv — HMMA, double-buffered ----------------
__global__ void __launch_bounds__(256, 2) conv_tc(
    const float* __restrict__ X, const float* __restrict__ Wm,
    const float* __restrict__ bias, float* __restrict__ Y)
{
    __shared__ __nv_bfloat16 sWh[2][ASZ], sWl[2][ASZ];
    __shared__ __nv_bfloat16 sXh[2][SSZ], sXl[2][SSZ];
    int b = blockIdx.z;
    const float* Xb = X + (size_t)b * Cc * HWD;
    float* Yb = Y + (size_t)b * Cc * HWD;
    int n0 = blockIdx.x * 64, m0 = blockIdx.y * 64;
    int t = threadIdx.x, lane = t & 31, wid = t >> 5;
    int wm = (wid >> 2) * 32, wn = (wid & 3) * 16;
    int g = lane >> 2, tc4 = lane & 3;

    float acc[2][2][4];
#pragma unroll
    for (int i = 0; i < 2; i++)
#pragma unroll
        for (int j = 0; j < 2; j++)
#pragma unroll
            for (int q = 0; q < 4; q++) acc[i][j][q] = 0.f;

    int lrA = lane & 15, lkA = (lane >> 4) * 8;
    int kB = (lane & 7) + ((lane >> 3) & 1) * 8;
    int scA = t & 15, srA = t >> 4;
    int scB = t & 31, srB = t >> 5;

    float2 wv[4], xv[4];
#define CONV_LOAD(K0) { \
    _Pragma("unroll") \
    for (int i = 0; i < 4; i++) { \
        wv[i] = *(const float2*)&Wm[(m0 + srA + i * 16) * Cc + (K0) + 2 * scA]; \
        xv[i] = *(const float2*)&Xb[(size_t)((K0) + srB + i * 8) * HWD + n0 + 2 * scB]; \
    } }
#define CONV_STORE(BF) { \
    _Pragma("unroll") \
    for (int i = 0; i < 4; i++) { \
        u32 hi, lo; bsplit2(wv[i].x, wv[i].y, hi, lo); \
        int so = (srA + i * 16) * PIT + 2 * scA; \
        *(u32*)&sWh[BF][so] = hi; *(u32*)&sWl[BF][so] = lo; \
        bsplit2(xv[i].x, xv[i].y, hi, lo); \
        so = (srB + i * 8) * PITS + 2 * scB; \
        *(u32*)&sXh[BF][so] = hi; *(u32*)&sXl[BF][so] = lo; \
    } }

    CONV_LOAD(0)
    CONV_STORE(0)
    __syncthreads();
    for (int it = 0; it < 4; it++) {
        int buf = it & 1;
        if (it < 3) CONV_LOAD((it + 1) * 32)
        u32 aWh = smaddr(sWh[buf]), aWl = smaddr(sWl[buf]);
        u32 aXh = smaddr(sXh[buf]), aXl = smaddr(sXl[buf]);
#pragma unroll
        for (int ks = 0; ks < 2; ks++) {
            int kb = ks * 16;
            u32 ah[2][4], al[2][4];
#pragma unroll
            for (int tm = 0; tm < 2; tm++) {
                u32 off = ((wm + 16 * tm + lrA) * PIT + kb + lkA) * 2;
                ldmA(ah[tm], aWh + off);
                ldmA(al[tm], aWl + off);
            }
            u32 bh[2][2], bl[2][2];
#pragma unroll
            for (int tn = 0; tn < 2; tn++) {
                u32 off = ((kb + kB) * PITS + wn + 8 * tn) * 2;
                ldmBT(bh[tn], aXh + off);
                ldmBT(bl[tn], aXl + off);
            }
#pragma unroll
            for (int tm = 0; tm < 2; tm++)
#pragma unroll
                for (int tn = 0; tn < 2; tn++) {
                    mma_bf16(acc[tm][tn], ah[tm], bh[tn]);
                    mma_bf16(acc[tm][tn], ah[tm], bl[tn]);
                    mma_bf16(acc[tm][tn], al[tm], bh[tn]);
                }
        }
        if (it < 3) CONV_STORE(buf ^ 1)
        __syncthreads();
    }
#undef CONV_LOAD
#undef CONV_STORE
#pragma unroll
    for (int tm = 0; tm < 2; tm++)
#pragma unroll
        for (int tn = 0; tn < 2; tn++) {
            int r0 = m0 + wm + 16 * tm + g;
            int col = n0 + wn + 8 * tn + 2 * tc4;
            float bv0 = bias[r0], bv1 = bias[r0 + 8];
            *(float2*)&Yb[(size_t)r0 * HWD + col] =
                make_float2(acc[tm][tn][0] + bv0, acc[tm][tn][1] + bv0);
            *(float2*)&Yb[(size_t)(r0 + 8) * HWD + col] =
                make_float2(acc[tm][tn][2] + bv1, acc[tm][tn][3] + bv1);
        }
}

// ------- rfft along W — HMMA, A via smem, B direct fragment LDG -------
__global__ void __launch_bounds__(256, 2) rfftw_tc(
    const float* __restrict__ Y, float2* __restrict__ F)
{
    __shared__ __nv_bfloat16 sAh[2][ASZ], sAl[2][ASZ];
    int bc = blockIdx.z;
    const float* A = Y + (size_t)bc * HWD;
    float2* Cp = F + (size_t)bc * Hh * WFD;
    int n0 = blockIdx.x * 64, m0 = blockIdx.y * 64;
    int t = threadIdx.x, lane = t & 31, wid = t >> 5;
    int wm = (wid >> 2) * 32, wn = (wid & 3) * 16;
    int g = lane >> 2, tc = lane & 3;

    float cre[2][2][4], cim[2][2][4];
#pragma unroll
    for (int i = 0; i < 2; i++)
#pragma unroll
        for (int j = 0; j < 2; j++)
#pragma unroll
            for (int q = 0; q < 4; q++) { cre[i][j][q] = 0.f; cim[i][j][q] = 0.f; }

    int lrA = lane & 15, lkA = (lane >> 4) * 8;
    int sc = t & 15, sr = t >> 4;
    int nblk0 = (n0 + wn) >> 3;   // fragment n-blocks are nblk0, nblk0+1

    float a0[4], a1[4];
#define RFW_LOAD(K0) { \
    _Pragma("unroll") \
    for (int i = 0; i < 4; i++) { \
        int r = sr + i * 16; int w = (K0) + 2 * sc; \
        if (w < Ww) { float2 t2 = *(const float2*)&A[(size_t)(m0 + r) * Ww + w]; \
                      a0[i] = t2.x; a1[i] = t2.y; } \
        else { a0[i] = 0.f; a1[i] = 0.f; } \
    } }
#define RFW_STORE(BF) { \
    _Pragma("unroll") \
    for (int i = 0; i < 4; i++) { \
        int so = (sr + i * 16) * PIT + 2 * sc; \
        u32 hi, lo; bsplit2(a0[i], a1[i], hi, lo); \
        *(u32*)&sAh[BF][so] = hi; *(u32*)&sAl[BF][so] = lo; \
    } }

    RFW_LOAD(0)
    RFW_STORE(0)
    __syncthreads();
    for (int it = 0; it < 16; it++) {
        int buf = it & 1;
        if (it < 15) RFW_LOAD((it + 1) * 32)
        u32 aAh = smaddr(sAh[buf]), aAl = smaddr(sAl[buf]);
#pragma unroll
        for (int ks = 0; ks < 2; ks++) {
            int kb = ks * 16;
            int kblk = it * 2 + ks;
            u32 ah[2][4], al[2][4];
#pragma unroll
            for (int tm = 0; tm < 2; tm++) {
                u32 off = ((wm + 16 * tm + lrA) * PIT + kb + lkA) * 2;
                ldmA(ah[tm], aAh + off);
                ldmA(al[tm], aAl + off);
            }
            u32 brh[2][2], brl[2][2], bih[2][2], bil[2][2];
#pragma unroll
            for (int tn = 0; tn < 2; tn++) {
                size_t bi = ((size_t)((nblk0 + tn) * 32 + kblk) << 5) + lane;
                u64 v;
                v = d_DwFrh[bi]; brh[tn][0] = (u32)v; brh[tn][1] = (u32)(v >> 32);
                v = d_DwFrl[bi]; brl[tn][0] = (u32)v; brl[tn][1] = (u32)(v >> 32);
                v = d_DwFih[bi]; bih[tn][0] = (u32)v; bih[tn][1] = (u32)(v >> 32);
                v = d_DwFil[bi]; bil[tn][0] = (u32)v; bil[tn][1] = (u32)(v >> 32);
            }
#pragma unroll
            for (int tm = 0; tm < 2; tm++)
#pragma unroll
                for (int tn = 0; tn < 2; tn++) {
                    mma_bf16(cre[tm][tn], ah[tm], brh[tn]);
                    mma_bf16(cre[tm][tn], ah[tm], brl[tn]);
                    mma_bf16(cre[tm][tn], al[tm], brh[tn]);
                    mma_bf16(cim[tm][tn], ah[tm], bih[tn]);
                    mma_bf16(cim[tm][tn], ah[tm], bil[tn]);
                    mma_bf16(cim[tm][tn], al[tm], bih[tn]);
                }
        }
        if (it < 15) RFW_STORE(buf ^ 1)
        __syncthreads();
    }
#undef RFW_LOAD
#undef RFW_STORE
#pragma unroll
    for (int tm = 0; tm < 2; tm++)
#pragma unroll
        for (int tn = 0; tn < 2; tn++) {
            int r0 = m0 + wm + 16 * tm + g;
            int col = n0 + wn + 8 * tn + 2 * tc;
            float4 v0 = make_float4(cre[tm][tn][0], cim[tm][tn][0], cre[tm][tn][1], cim[tm][tn][1]);
            *(float4*)&Cp[(size_t)r0 * WFD + col] = v0;
            float4 v1 = make_float4(cre[tm][tn][2], cim[tm][tn][2], cre[tm][tn][3], cim[tm][tn][3]);
            *(float4*)&Cp[(size_t)(r0 + 8) * WFD + col] = v1;
        }
}

// ------- irfft along W + residual — HMMA, A via smem, B direct fragment LDG ----
__global__ void __launch_bounds__(256, 2) irfft_add_tc(
    const float2* __restrict__ T, const float* __restrict__ x, float* __restrict__ r)
{
    __shared__ __nv_bfloat16 sArh[2][ASZ], sArl[2][ASZ], sAih[2][ASZ], sAil[2][ASZ];
    int bc = blockIdx.z;
    const float2* Ap = T + (size_t)bc * 65536;
    int n0 = blockIdx.x * 64, m0 = blockIdx.y * 64;
    int t = threadIdx.x, lane = t & 31, wid = t >> 5;
    int wm = (wid >> 2) * 32, wn = (wid & 3) * 16;
    int g = lane >> 2, tc = lane & 3;

    float acc[2][2][4];
#pragma unroll
    for (int i = 0; i < 2; i++)
#pragma unroll
        for (int j = 0; j < 2; j++)
#pragma unroll
            for (int q = 0; q < 4; q++) acc[i][j][q] = 0.f;

    int lrA = lane & 15, lkA = (lane >> 4) * 8;
    int sc = t & 15, sr = t >> 4;
    int nblk0 = (n0 + wn) >> 3;

    float4 va[4];
#define IRF_LOAD(K0) { \
    _Pragma("unroll") \
    for (int i = 0; i < 4; i++) { \
        int rr = sr + i * 16; \
        va[i] = *(const float4*)&Ap[(size_t)(m0 + rr) * 256 + (K0) + 2 * sc]; \
    } }
#define IRF_STORE(BF) { \
    _Pragma("unroll") \
    for (int i = 0; i < 4; i++) { \
        int so = (sr + i * 16) * PIT + 2 * sc; \
        u32 hi, lo; \
        bsplit2(va[i].x, va[i].z, hi, lo); \
        *(u32*)&sArh[BF][so] = hi; *(u32*)&sArl[BF][so] = lo; \
        bsplit2(va[i].y, va[i].w, hi, lo); \
        *(u32*)&sAih[BF][so] = hi; *(u32*)&sAil[BF][so] = lo; \
    } }

    IRF_LOAD(0)
    IRF_STORE(0)
    __syncthreads();
    for (int it = 0; it < 8; it++) {
        int buf = it & 1;
        if (it < 7) IRF_LOAD((it + 1) * 32)
        u32 aArh = smaddr(sArh[buf]), aArl = smaddr(sArl[buf]);
        u32 aAih = smaddr(sAih[buf]), aAil = smaddr(sAil[buf]);
#pragma unroll
        for (int ks = 0; ks < 2; ks++) {
            int kb = ks * 16;
            int kblk = it * 2 + ks;
            u32 arh[2][4], arl[2][4], aih[2][4], ail[2][4];
#pragma unroll
            for (int tm = 0; tm < 2; tm++) {
                u32 off = ((wm + 16 * tm + lrA) * PIT + kb + lkA) * 2;
                ldmA(arh[tm], aArh + off);
                ldmA(arl[tm], aArl + off);
                ldmA(aih[tm], aAih + off);
                ldmA(ail[tm], aAil + off);
            }
            u32 b1h[2][2], b1l[2][2], b2h[2][2], b2l[2][2];
#pragma unroll
            for (int tn = 0; tn < 2; tn++) {
                size_t bi = ((size_t)((nblk0 + tn) * 16 + kblk) << 5) + lane;
                u64 v;
                v = d_CwF1h[bi]; b1h[tn][0] = (u32)v; b1h[tn][1] = (u32)(v >> 32);
                v = d_CwF1l[bi]; b1l[tn][0] = (u32)v; b1l[tn][1] = (u32)(v >> 32);
                v = d_CwF2h[bi]; b2h[tn][0] = (u32)v; b2h[tn][1] = (u32)(v >> 32);
                v = d_CwF2l[bi]; b2l[tn][0] = (u32)v; b2l[tn][1] = (u32)(v >> 32);
            }
#pragma unroll
            for (int tm = 0; tm < 2; tm++)
#pragma unroll
                for (int tn = 0; tn < 2; tn++) {
                    mma_bf16(acc[tm][tn], arh[tm], b1h[tn]);
                    mma_bf16(acc[tm][tn], arh[tm], b1l[tn]);
                    mma_bf16(acc[tm][tn], arl[tm], b1h[tn]);
                    mma_bf16(acc[tm][tn], aih[tm], b2h[tn]);
                    mma_bf16(acc[tm][tn], aih[tm], b2l[tn]);
                    mma_bf16(acc[tm][tn], ail[tm], b2h[tn]);
                }
        }
        if (it < 7) IRF_STORE(buf ^ 1)
        __syncthreads();
    }
#undef IRF_LOAD
#undef IRF_STORE
#pragma unroll
    for (int tm = 0; tm < 2; tm++)
#pragma unroll
        for (int tn = 0; tn < 2; tn++) {
            int col = n0 + wn + 8 * tn + 2 * tc;
            if (col < Ww) {
                int r0 = m0 + wm + 16 * tm + g;
                size_t i0 = (size_t)bc * HWD + (size_t)r0 * Ww + col;
                size_t i1 = i0 + (size_t)8 * Ww;
                float2 xv = *(const float2*)&x[i0];
                *(float2*)&r[i0] = make_float2(acc[tm][tn][0] + xv.x, acc[tm][tn][1] + xv.y);
                xv = *(const float2*)&x[i1];
                *(float2*)&r[i1] = make_float2(acc[tm][tn][2] + xv.x, acc[tm][tn][3] + xv.y);
            }
        }
}

// ---------------- 256-pt FFT along slow axis (4-step 16x16) ----------------
template<int INV, int FILT>
__global__ void __launch_bounds__(256) ffth_kernel(
    const float2* __restrict__ in, float2* __restrict__ out,
    const float2* __restrict__ filt)
{
    __shared__ float2 Xs[256][17];
    __shared__ float2 Ws[256];
    int bc = blockIdx.y;
    int v0 = blockIdx.x * 16;
    int tx = threadIdx.x;
    int ty = threadIdx.y;
    int t = ty * 16 + tx;
    const float2* inp = in + (size_t)bc * 65536 + v0;
    float2* outp = out + (size_t)bc * 65536 + v0;

    {
        float2 w = d_W256[t];
        if (INV) w.y = -w.y;
        Ws[t] = w;
    }
#pragma unroll
    for (int i = 0; i < 16; i++) {
        int h = i * 16 + ty;
        Xs[h][tx] = inp[(size_t)h * 256 + tx];
    }
    __syncthreads();

    float2 rr[16];
    {
        u64 tw[16];
#pragma unroll
        for (int n1 = 0; n1 < 16; n1++) {
            float2 w = Ws[(n1 * ty * 16) & 255];
            tw[n1] = pk2(w.x, w.y);
        }
#pragma unroll
        for (int n2 = 0; n2 < 16; n2++) {
            u64 accA = 0ull, accB = 0ull;
#pragma unroll
            for (int n1 = 0; n1 < 16; n1++) {
                float2 xv = Xs[16 * n1 + n2][tx];
                u64 xp = pk2(xv.x, xv.y);
                u64 xq = pk2(xv.y, xv.x);
                accA = ffma2(xp, tw[n1], accA);
                accB = ffma2(xq, tw[n1], accB);
            }
            float2 a = up2(accA), b = up2(accB);
            float ar = a.x - a.y, ai = b.x + b.y;
            float2 tm = Ws[(n2 * ty) & 255];
            rr[n2] = make_float2(ar * tm.x - ai * tm.y, ar * tm.y + ai * tm.x);
        }
    }
    __syncthreads();
#pragma unroll
    for (int n2 = 0; n2 < 16; n2++)
        Xs[ty * 16 + n2][tx] = rr[n2];
    __syncthreads();

    {
        u64 tw[16];
#pragma unroll
        for (int n2 = 0; n2 < 16; n2++) {
            float2 w = Ws[(n2 * ty * 16) & 255];
            tw[n2] = pk2(w.x, w.y);
        }
        int c = bc & (Cc - 1);
#pragma unroll
        for (int k1 = 0; k1 < 16; k1++) {
            u64 accA = 0ull, accB = 0ull;
#pragma unroll
            for (int n2 = 0; n2 < 16; n2++) {
                float2 xv = Xs[k1 * 16 + n2][tx];
                u64 xp = pk2(xv.x, xv.y);
                u64 xq = pk2(xv.y, xv.x);
                accA = ffma2(xp, tw[n2], accA);
                accB = ffma2(xq, tw[n2], accB);
            }
            float2 a = up2(accA), b = up2(accB);
            int u = k1 + 16 * ty;
            float2 v = make_float2((a.x - a.y) * 0.0625f, (b.x + b.y) * 0.0625f);
            if (FILT) {
                float2 wc = filt[((size_t)c * Hh + u) * WFD + v0 + tx];
                v = make_float2(v.x * wc.x - v.y * wc.y, v.x * wc.y + v.y * wc.x);
            }
            outp[(size_t)u * 256 + tx] = v;
        }
    }
}

// ------- variance over v per (bc,u) row -------
__global__ void var_kernel(const float2* __restrict__ G, float* __restrict__ rsq)
{
    __shared__ float s0[256], s1[256], s2[256];
    int row = blockIdx.x;
    int tid = threadIdx.x;
    float2 z = G[(size_t)row * WFD + tid];
    s0[tid] = z.x; s1[tid] = z.y; s2[tid] = z.x * z.x + z.y * z.y;
    __syncthreads();
    for (int s = 128; s > 0; s >>= 1) {
        if (tid < s) { s0[tid] += s0[tid + s]; s1[tid] += s1[tid + s]; s2[tid] += s2[tid + s]; }
        __syncthreads();
    }
    if (tid == 0) {
        float mr = s0[0] * (1.f / WFD), mi = s1[0] * (1.f / WFD);
        float var = s2[0] * (1.f / WFD) - (mr * mr + mi * mi);
        rsq[row] = 1.f / sqrtf(6.283185307179586f * var);
    }
}

// ------- scores — HMMA complex, double-buffered (dynamic smem) -------
__global__ void __launch_bounds__(256) scores_tc(
    const float2* __restrict__ Gb, const float2* __restrict__ Xb,
    const float* __restrict__ rsq, float2* __restrict__ Sb)
{
    extern __shared__ __nv_bfloat16 dynS[];
    __nv_bfloat16* sGrh = dynS;
    __nv_bfloat16* sGrl = sGrh + 2 * SSZ;
    __nv_bfloat16* sGih = sGrl + 2 * SSZ;
    __nv_bfloat16* sGil = sGih + 2 * SSZ;
    __nv_bfloat16* sXrh = sGil + 2 * SSZ;
    __nv_bfloat16* sXrl = sXrh + 2 * SSZ;
    __nv_bfloat16* sXih = sXrl + 2 * SSZ;
    __nv_bfloat16* sXil = sXih + 2 * SSZ;
    int bc = blockIdx.z;
    const float2* Ap = Gb + (size_t)bc * 65536;
    const float2* Bp = Xb + (size_t)bc * 65536;
    float2* Cp = Sb + (size_t)bc * 65536;
    int n0 = blockIdx.x * 64, m0 = blockIdx.y * 64;
    int t = threadIdx.x, lane = t & 31, wid = t >> 5;
    int wm = (wid >> 2) * 32, wn = (wid & 3) * 16;
    int g = lane >> 2, tc4 = lane & 3;

    float are[2][2][4], aim[2][2][4];
#pragma unroll
    for (int i = 0; i < 2; i++)
#pragma unroll
        for (int j = 0; j < 2; j++)
#pragma unroll
            for (int q = 0; q < 4; q++) { are[i][j][q] = 0.f; aim[i][j][q] = 0.f; }

    int kA = (lane & 7) + ((lane >> 4) & 1) * 8;
    int mA = ((lane >> 3) & 1) * 8;
    int kB = (lane & 7) + ((lane >> 3) & 1) * 8;
    int sc = t & 31, sr = t >> 5;

    float4 vA[4], vB[4];
#define SCR_LOAD(K0) { \
    _Pragma("unroll") \
    for (int i = 0; i < 4; i++) { \
        int k = sr + i * 8; \
        vA[i] = *(const float4*)&Ap[(size_t)((K0) + k) * 256 + m0 + 2 * sc]; \
        vB[i] = *(const float4*)&Bp[(size_t)((K0) + k) * 256 + n0 + 2 * sc]; \
    } }
#define SCR_STORE(BF) { \
    _Pragma("unroll") \
    for (int i = 0; i < 4; i++) { \
        int so = (BF) * SSZ + (sr + i * 8) * PITS + 2 * sc; \
        u32 hi, lo; \
        bsplit2(vA[i].x, vA[i].z, hi, lo); *(u32*)&sGrh[so] = hi; *(u32*)&sGrl[so] = lo; \
        bsplit2(vA[i].y, vA[i].w, hi, lo); *(u32*)&sGih[so] = hi; *(u32*)&sGil[so] = lo; \
        bsplit2(vB[i].x, vB[i].z, hi, lo); *(u32*)&sXrh[so] = hi; *(u32*)&sXrl[so] = lo; \
        bsplit2(vB[i].y, vB[i].w, hi, lo); *(u32*)&sXih[so] = hi; *(u32*)&sXil[so] = lo; \
    } }

    SCR_LOAD(0)
    SCR_STORE(0)
    __syncthreads();
    for (int it = 0; it < 8; it++) {
        int buf = it & 1;
        if (it < 7) SCR_LOAD((it + 1) * 32)
        u32 aGrh = smaddr(sGrh + buf * SSZ), aGrl = smaddr(sGrl + buf * SSZ);
        u32 aGih = smaddr(sGih + buf * SSZ), aGil = smaddr(sGil + buf * SSZ);
        u32 aXrh = smaddr(sXrh + buf * SSZ), aXrl = smaddr(sXrl + buf * SSZ);
        u32 aXih = smaddr(sXih + buf * SSZ), aXil = smaddr(sXil + buf * SSZ);
#pragma unroll
        for (int ks = 0; ks < 2; ks++) {
            int kb = ks * 16;
            u32 grh[2][4], grl[2][4], gih[2][4], gil[2][4];
#pragma unroll
            for (int tm = 0; tm < 2; tm++) {
                u32 off = ((kb + kA) * PITS + wm + 16 * tm + mA) * 2;
                ldmAT(grh[tm], aGrh + off);
                ldmAT(grl[tm], aGrl + off);
                ldmAT(gih[tm], aGih + off);
                ldmAT(gil[tm], aGil + off);
            }
            u32 xrh[2][2], xrl[2][2], xih[2][2], xil[2][2];
#pragma unroll
            for (int tn = 0; tn < 2; tn++) {
                u32 off = ((kb + kB) * PITS + wn + 8 * tn) * 2;
                ldmBT(xrh[tn], aXrh + off);
                ldmBT(xrl[tn], aXrl + off);
                ldmBT(xih[tn], aXih + off);
                ldmBT(xil[tn], aXil + off);
            }
#pragma unroll
            for (int tm = 0; tm < 2; tm++) {
                u32 nih[4], nil_[4];
#pragma unroll
                for (int q = 0; q < 4; q++) {
                    nih[q]  = gih[tm][q] ^ 0x80008000u;
                    nil_[q] = gil[tm][q] ^ 0x80008000u;
                }
#pragma unroll
                for (int tn = 0; tn < 2; tn++) {
                    mma_bf16(are[tm][tn], grh[tm], xrh[tn]);
                    mma_bf16(are[tm][tn], grh[tm], xrl[tn]);
                    mma_bf16(are[tm][tn], grl[tm], xrh[tn]);
                    mma_bf16(are[tm][tn], nih,     xih[tn]);
                    mma_bf16(are[tm][tn], nih,     xil[tn]);
                    mma_bf16(are[tm][tn], nil_,    xih[tn]);
                    mma_bf16(aim[tm][tn], grh[tm], xih[tn]);
                    mma_bf16(aim[tm][tn], grh[tm], xil[tn]);
                    mma_bf16(aim[tm][tn], grl[tm], xih[tn]);
                    mma_bf16(aim[tm][tn], gih[tm], xrh[tn]);
                    mma_bf16(aim[tm][tn], gih[tm], xrl[tn]);
                    mma_bf16(aim[tm][tn], gil[tm], xrh[tn]);
                }
            }
        }
        if (it < 7) SCR_STORE(buf ^ 1)
        __syncthreads();
    }
#undef SCR_LOAD
#undef SCR_STORE
#pragma unroll
    for (int tm = 0; tm < 2; tm++)
#pragma unroll
        for (int tn = 0; tn < 2; tn++) {
            int r0 = m0 + wm + 16 * tm + g;
            int col = n0 + wn + 8 * tn + 2 * tc4;
            float s0 = rsq[bc * Hh + r0], s1 = rsq[bc * Hh + r0 + 8];
            float4 o0 = make_float4(
                sigm(are[tm][tn][0] * s0), sigm(aim[tm][tn][0] * s0),
                sigm(are[tm][tn][1] * s0), sigm(aim[tm][tn][1] * s0));
            *(float4*)&Cp[(size_t)r0 * 256 + col] = o0;
            float4 o1 = make_float4(
                sigm(are[tm][tn][2] * s1), sigm(aim[tm][tn][2] * s1),
                sigm(are[tm][tn][3] * s1), sigm(aim[tm][tn][3] * s1));
            *(float4*)&Cp[(size_t)(r0 + 8) * 256 + col] = o1;
        }
}

// ------- channel LayerNorm — single-read smem-tiled -------
__global__ void __launch_bounds__(256) ln_kernel(
    const float* __restrict__ r, const float* __restrict__ gamma,
    const float* __restrict__ beta, float* __restrict__ out)
{
    __shared__ float tile[128][64];
    __shared__ float ps[4][64], qs[4][64];
    __shared__ float mu[64], inv[64];
    int blk = blockIdx.x;
    int b = blk / 2040;
    int w0 = (blk - b * 2040) * 64;
    int t = threadIdx.x;
    int wl = t & 63, cq = t >> 6;

#pragma unroll 8
    for (int c0 = 0; c0 < 128; c0 += 4) {
        int c = c0 + cq;
        tile[c][wl] = r[(size_t)(b * Cc + c) * HWD + w0 + wl];
    }
    __syncthreads();
    {
        float s = 0.f, q = 0.f;
#pragma unroll
        for (int c = 0; c < 32; c++) {
            float v = tile[cq * 32 + c][wl];
            s += v; q += v * v;
        }
        ps[cq][wl] = s; qs[cq][wl] = q;
    }
    __syncthreads();
    if (t < 64) {
        float s = ps[0][t] + ps[1][t] + ps[2][t] + ps[3][t];
        float q = qs[0][t] + qs[1][t] + qs[2][t] + qs[3][t];
        float m = s * (1.f / 128.f);
        mu[t] = m;
        inv[t] = rsqrtf(q * (1.f / 128.f) - m * m + 1e-6f);
    }
    __syncthreads();
#pragma unroll 8
    for (int c0 = 0; c0 < 128; c0 += 4) {
        int c = c0 + cq;
        out[(size_t)(b * Cc + c) * HWD + w0 + wl] =
            gamma[c] * (tile[c][wl] - mu[wl]) * inv[wl] + beta[c];
    }
}

// ---------------- launch ----------------
extern "C" void kernel_launch(void* const* d_in, const int* in_sizes, int n_in,
                              void* d_out, int out_size)
{
    (void)in_sizes; (void)n_in; (void)out_size;
    const float*  g     = (const float*)d_in[0];
    const float*  x     = (const float*)d_in[1];
    const float*  wg    = (const float*)d_in[2];
    const float*  bg    = (const float*)d_in[3];
    const float*  wx    = (const float*)d_in[4];
    const float*  bx    = (const float*)d_in[5];
    const float2* fg    = (const float2*)d_in[6];
    const float2* fx    = (const float2*)d_in[7];
    const float*  gamma = (const float*)d_in[8];
    const float*  beta  = (const float*)d_in[9];
    float* out = (float*)d_out;

    float *yg, *yx, *rb, *rsq;
    float2 *Fg, *Fx, *Gg, *Gx, *S, *T;
    cudaGetSymbolAddress((void**)&yg,  d_yg);
    cudaGetSymbolAddress((void**)&yx,  d_yx);
    cudaGetSymbolAddress((void**)&Fg,  d_Fg);
    cudaGetSymbolAddress((void**)&Fx,  d_Fx);
    cudaGetSymbolAddress((void**)&Gg,  d_Gg);
    cudaGetSymbolAddress((void**)&Gx,  d_Gx);
    cudaGetSymbolAddress((void**)&S,   d_Sb);
    cudaGetSymbolAddress((void**)&T,   d_Tb);
    cudaGetSymbolAddress((void**)&rb,  d_rb);
    cudaGetSymbolAddress((void**)&rsq, d_rsq);

    static int attr_done = 0;
    if (!attr_done) {
        cudaFuncSetAttribute(scores_tc, cudaFuncAttributeMaxDynamicSharedMemorySize,
                             16 * SSZ * 2);
        attr_done = 1;
    }

    dim3 blk(16, 16);

    build_tables_kernel<<<256, 256>>>();

    conv_tc<<<dim3(HWD / 64, 2, Bb), 256>>>(g, wg, bg, yg);
    conv_tc<<<dim3(HWD / 64, 2, Bb), 256>>>(x, wx, bx, yx);

    rfftw_tc<<<dim3(4, 4, BCD), 256>>>(yg, Fg);
    rfftw_tc<<<dim3(4, 4, BCD), 256>>>(yx, Fx);

    ffth_kernel<0, 1><<<dim3(16, BCD), blk>>>(Fg, Gg, fg);
    ffth_kernel<0, 1><<<dim3(16, BCD), blk>>>(Fx, Gx, fx);

    var_kernel<<<BCD * Hh, 256>>>(Gg, rsq);

    scores_tc<<<dim3(4, 4, BCD), 256, 16 * SSZ * 2>>>(Gg, Gx, rsq, S);

    ffth_kernel<1, 0><<<dim3(16, BCD), blk>>>(S, T, nullptr);

    irfft_add_tc<<<dim3(8, 4, BCD), 256>>>(T, x, rb);

    ln_kernel<<<Bb * 2040, 256>>>(rb, gamma, beta, out);
}